// round 2
// baseline (speedup 1.0000x reference)
#include <cuda_runtime.h>
#include <cuda_bf16.h>

#define NN   20000
#define EE   320000
#define INF  256
#define HIDF 256
#define OUTF 128

// ---------------- scratch (device globals; no allocation allowed) ------------
__device__ float g_h [NN * HIDF];
__device__ float g_h2[NN * HIDF];
__device__ float g_Ah[NN * HIDF];
__device__ int   g_cnt[NN];
__device__ int   g_off[NN + 1];
__device__ int   g_fill[NN];
__device__ int   g_csr_src[EE];
__device__ float g_csr_w[EE];

// ---------------- CSR build --------------------------------------------------
__global__ void zero_cnt_k() {
    int i = blockIdx.x * blockDim.x + threadIdx.x;
    if (i < NN) g_cnt[i] = 0;
}

__global__ void count_k(const int* __restrict__ dst) {
    int e = blockIdx.x * blockDim.x + threadIdx.x;
    if (e < EE) atomicAdd(&g_cnt[dst[e]], 1);
}

// single-block exclusive scan of g_cnt -> g_off (and g_fill), blockDim = 1024
__global__ void scan_k() {
    __shared__ int s[1024];
    __shared__ int carry;
    int tid = threadIdx.x;
    if (tid == 0) carry = 0;
    __syncthreads();
    for (int base = 0; base < NN; base += 1024) {
        int i = base + tid;
        int v = (i < NN) ? g_cnt[i] : 0;
        s[tid] = v;
        __syncthreads();
        #pragma unroll
        for (int off = 1; off < 1024; off <<= 1) {
            int t = 0;
            if (tid >= off) t = s[tid - off];
            __syncthreads();
            if (tid >= off) s[tid] += t;
            __syncthreads();
        }
        int incl  = s[tid];
        int cbase = carry;
        __syncthreads();
        if (i < NN) {
            int ex = cbase + incl - v;
            g_off[i]  = ex;
            g_fill[i] = ex;
        }
        __syncthreads();
        if (tid == 0) carry = cbase + s[1023];
        __syncthreads();
    }
    if (tid == 0) g_off[NN] = carry;
}

__global__ void scatter_k(const int* __restrict__ src, const int* __restrict__ dst,
                          const float* __restrict__ w) {
    int e = blockIdx.x * blockDim.x + threadIdx.x;
    if (e < EE) {
        int d = dst[e];
        int p = atomicAdd(&g_fill[d], 1);
        g_csr_src[p] = src[e];
        g_csr_w[p]   = w[e];
    }
}

// ---------------- adj_mul gather: Ah[i,:] = sum_e w_e * h[src_e,:] -----------
// blockDim (64,4): 64 lanes x float4 cover 256 feats; 4 nodes per block.
__global__ void gather_k(const float* __restrict__ h, float* __restrict__ ah) {
    int node = blockIdx.x * 4 + threadIdx.y;
    if (node >= NN) return;
    int beg = g_off[node], end = g_off[node + 1];
    const float4* H = (const float4*)h;
    int t = threadIdx.x;  // 0..63
    float4 acc = make_float4(0.f, 0.f, 0.f, 0.f);
    for (int k = beg; k < end; ++k) {
        int s  = g_csr_src[k];
        float w = g_csr_w[k];
        float4 v = H[(size_t)s * 64 + t];
        acc.x += v.x * w; acc.y += v.y * w; acc.z += v.z * w; acc.w += v.w * w;
    }
    ((float4*)ah)[(size_t)node * 64 + t] = acc;
}

// ---------------- fp32 tiled GEMM with fused gconv epilogue ------------------
// C[i,j] = epi( sum_{k<K1} A1[i,k]*W[j,k] + sum_{k<K2} A2[i,k]*W[j,K1+k] )
// epi: optional +bias[j]; if res != null: C = res[i,j] + relu(.)
// BM=BN=128, BK=8, 256 threads, 8x8 per thread. K1,K2 multiples of 8.
// Ncols multiple of 128 (grid.y covers it). Row guard on M.
__global__ __launch_bounds__(256, 2)
void gemm_k(const float* __restrict__ A1, const float* __restrict__ A2,
            int K1, int K2,
            const float* __restrict__ W, const float* __restrict__ bias,
            const float* __restrict__ res, float* __restrict__ C,
            int M, int Ncols) {
    __shared__ float As[8][128];
    __shared__ float Bs[8][128];

    int tid  = threadIdx.x;
    int tx   = tid & 15;          // col group
    int ty   = tid >> 4;          // row group
    int arow = tid >> 1;          // 0..127
    int acol = (tid & 1) * 4;     // 0 or 4

    int ib = blockIdx.x * 128;
    int jb = blockIdx.y * 128;
    int Ktot = K1 + K2;

    float acc[8][8];
    #pragma unroll
    for (int i = 0; i < 8; ++i)
        #pragma unroll
        for (int j = 0; j < 8; ++j) acc[i][j] = 0.f;

    int grow = ib + arow;
    bool rok = grow < M;

    for (int k0 = 0; k0 < Ktot; k0 += 8) {
        // pick source for this K-tile (K1 multiple of 8 so tiles never straddle)
        const float* Asrc; int ld, kk;
        if (k0 < K1) { Asrc = A1; ld = K1; kk = k0; }
        else         { Asrc = A2; ld = K2; kk = k0 - K1; }

        float4 av = make_float4(0.f, 0.f, 0.f, 0.f);
        if (rok) av = *(const float4*)&Asrc[(size_t)grow * ld + kk + acol];
        float4 bv = *(const float4*)&W[(size_t)(jb + arow) * Ktot + k0 + acol];

        As[acol + 0][arow] = av.x;
        As[acol + 1][arow] = av.y;
        As[acol + 2][arow] = av.z;
        As[acol + 3][arow] = av.w;
        Bs[acol + 0][arow] = bv.x;
        Bs[acol + 1][arow] = bv.y;
        Bs[acol + 2][arow] = bv.z;
        Bs[acol + 3][arow] = bv.w;
        __syncthreads();

        #pragma unroll
        for (int p = 0; p < 8; ++p) {
            float4 a0 = *(float4*)&As[p][ty * 8];
            float4 a1 = *(float4*)&As[p][ty * 8 + 4];
            float4 b0 = *(float4*)&Bs[p][tx * 8];
            float4 b1 = *(float4*)&Bs[p][tx * 8 + 4];
            float a[8] = {a0.x, a0.y, a0.z, a0.w, a1.x, a1.y, a1.z, a1.w};
            float b[8] = {b0.x, b0.y, b0.z, b0.w, b1.x, b1.y, b1.z, b1.w};
            #pragma unroll
            for (int i = 0; i < 8; ++i)
                #pragma unroll
                for (int j = 0; j < 8; ++j)
                    acc[i][j] = fmaf(a[i], b[j], acc[i][j]);
        }
        __syncthreads();
    }

    // epilogue
    int jbase = jb + tx * 8;
    float bvreg[8];
    #pragma unroll
    for (int j = 0; j < 8; ++j) bvreg[j] = bias ? bias[jbase + j] : 0.f;

    #pragma unroll
    for (int i = 0; i < 8; ++i) {
        int row = ib + ty * 8 + i;
        if (row >= M) continue;
        float* crow = &C[(size_t)row * Ncols + jbase];
        if (res) {
            const float4* rr = (const float4*)&res[(size_t)row * Ncols + jbase];
            float4 r0 = rr[0], r1 = rr[1];
            float4 o0, o1;
            o0.x = r0.x + fmaxf(acc[i][0] + bvreg[0], 0.f);
            o0.y = r0.y + fmaxf(acc[i][1] + bvreg[1], 0.f);
            o0.z = r0.z + fmaxf(acc[i][2] + bvreg[2], 0.f);
            o0.w = r0.w + fmaxf(acc[i][3] + bvreg[3], 0.f);
            o1.x = r1.x + fmaxf(acc[i][4] + bvreg[4], 0.f);
            o1.y = r1.y + fmaxf(acc[i][5] + bvreg[5], 0.f);
            o1.z = r1.z + fmaxf(acc[i][6] + bvreg[6], 0.f);
            o1.w = r1.w + fmaxf(acc[i][7] + bvreg[7], 0.f);
            ((float4*)crow)[0] = o0;
            ((float4*)crow)[1] = o1;
        } else {
            float4 o0 = make_float4(acc[i][0] + bvreg[0], acc[i][1] + bvreg[1],
                                    acc[i][2] + bvreg[2], acc[i][3] + bvreg[3]);
            float4 o1 = make_float4(acc[i][4] + bvreg[4], acc[i][5] + bvreg[5],
                                    acc[i][6] + bvreg[6], acc[i][7] + bvreg[7]);
            ((float4*)crow)[0] = o0;
            ((float4*)crow)[1] = o1;
        }
    }
}

// ---------------- row L2-normalize (128 cols): one warp per row --------------
__global__ void norm_k(float* __restrict__ out) {
    int row = blockIdx.x * 8 + threadIdx.y;  // blockDim (32,8)
    if (row >= NN) return;
    float4* p = (float4*)out + (size_t)row * 32 + threadIdx.x;
    float4 v = *p;
    float s = v.x * v.x + v.y * v.y + v.z * v.z + v.w * v.w;
    #pragma unroll
    for (int off = 16; off > 0; off >>= 1)
        s += __shfl_xor_sync(0xFFFFFFFFu, s, off);
    float r = rsqrtf(s);
    v.x *= r; v.y *= r; v.z *= r; v.w *= r;
    *p = v;
}

// ---------------- launch -----------------------------------------------------
extern "C" void kernel_launch(void* const* d_in, const int* in_sizes, int n_in,
                              void* d_out, int out_size) {
    const float* x     = (const float*)d_in[0];
    const int*   esrc  = (const int*)  d_in[1];
    const int*   edst  = (const int*)  d_in[2];
    const float* ew    = (const float*)d_in[3];
    const float* W_emb = (const float*)d_in[4];
    const float* W_gc1 = (const float*)d_in[5];
    const float* b_gc1 = (const float*)d_in[6];
    const float* W_gc2 = (const float*)d_in[7];
    const float* b_gc2 = (const float*)d_in[8];
    const float* W_fc  = (const float*)d_in[9];
    float* out = (float*)d_out;

    float *h, *h2, *ah;
    cudaGetSymbolAddress((void**)&h,  g_h);
    cudaGetSymbolAddress((void**)&h2, g_h2);
    cudaGetSymbolAddress((void**)&ah, g_Ah);

    // CSR build (per-launch, deterministic up to fp-neutral slot order)
    zero_cnt_k<<<(NN + 255) / 256, 256>>>();
    count_k  <<<(EE + 255) / 256, 256>>>(edst);
    scan_k   <<<1, 1024>>>();
    scatter_k<<<(EE + 255) / 256, 256>>>(esrc, edst, ew);

    dim3 gridHid((NN + 127) / 128, HIDF / 128);  // 157 x 2
    dim3 gridOut((NN + 127) / 128, OUTF / 128);  // 157 x 1
    dim3 gblk(5000), gthr(64, 4);

    // h = x @ W_emb^T
    gemm_k<<<gridHid, 256>>>(x, nullptr, INF, 0, W_emb, nullptr, nullptr, h, NN, HIDF);
    // Ah = A @ h ; h2 = h + relu([h,Ah] @ W_gc1^T + b1)
    gather_k<<<gblk, gthr>>>(h, ah);
    gemm_k<<<gridHid, 256>>>(h, ah, HIDF, HIDF, W_gc1, b_gc1, h, h2, NN, HIDF);
    // Ah = A @ h2 ; h = h2 + relu([h2,Ah] @ W_gc2^T + b2)
    gather_k<<<gblk, gthr>>>(h2, ah);
    gemm_k<<<gridHid, 256>>>(h2, ah, HIDF, HIDF, W_gc2, b_gc2, h2, h, NN, HIDF);
    // out = h @ W_fc^T ; rows L2-normalized
    gemm_k<<<gridOut, 256>>>(h, nullptr, HIDF, 0, W_fc, nullptr, nullptr, out, NN, OUTF);
    norm_k<<<(NN + 7) / 8, dim3(32, 8)>>>(out);
}

// round 4
// speedup vs baseline: 1.0881x; 1.0881x over previous
#include <cuda_runtime.h>
#include <cuda_bf16.h>
#include <cstdint>

#define NN   20000
#define EE   320000
#define INF  256
#define HIDF 256
#define OUTF 128
#define BKB  144   // padded smem row stride (bytes) -> conflict-free fragments

typedef __nv_bfloat16 bf16;

// ---------------- scratch (device globals; no allocation allowed) ------------
__device__ float g_h [NN * HIDF];
__device__ float g_h2[NN * HIDF];
__device__ bf16  g_xh [NN * HIDF], g_xl [NN * HIDF];
__device__ bf16  g_hh [NN * HIDF], g_hl [NN * HIDF];
__device__ bf16  g_h2h[NN * HIDF], g_h2l[NN * HIDF];
__device__ bf16  g_ahh[NN * HIDF], g_ahl[NN * HIDF];
__device__ bf16  g_weh[HIDF * INF],     g_wel[HIDF * INF];
__device__ bf16  g_w1h[HIDF * 2 * HIDF], g_w1l[HIDF * 2 * HIDF];
__device__ bf16  g_w2h[HIDF * 2 * HIDF], g_w2l[HIDF * 2 * HIDF];
__device__ bf16  g_wfh[OUTF * HIDF],    g_wfl[OUTF * HIDF];
__device__ int   g_cnt[NN];
__device__ int   g_off[NN + 1];
__device__ int   g_fill[NN];
__device__ int   g_csr_src[EE];
__device__ float g_csr_w[EE];

// ---------------- helpers ----------------------------------------------------
__device__ __forceinline__ void split2(float x, float y, uint32_t& hi, uint32_t& lo) {
    bf16 hx = __float2bfloat16_rn(x);
    bf16 hy = __float2bfloat16_rn(y);
    float rx = x - __bfloat162float(hx);
    float ry = y - __bfloat162float(hy);
    __nv_bfloat162 H; H.x = hx; H.y = hy;
    __nv_bfloat162 L = __floats2bfloat162_rn(rx, ry);
    hi = *reinterpret_cast<uint32_t*>(&H);
    lo = *reinterpret_cast<uint32_t*>(&L);
}

__device__ __forceinline__ void mma_bf16(float c[4],
                                         uint32_t a0, uint32_t a1, uint32_t a2, uint32_t a3,
                                         uint32_t b0, uint32_t b1) {
    asm volatile(
        "mma.sync.aligned.m16n8k16.row.col.f32.bf16.bf16.f32 "
        "{%0,%1,%2,%3}, {%4,%5,%6,%7}, {%8,%9}, {%0,%1,%2,%3};"
        : "+f"(c[0]), "+f"(c[1]), "+f"(c[2]), "+f"(c[3])
        : "r"(a0), "r"(a1), "r"(a2), "r"(a3), "r"(b0), "r"(b1));
}

// ---------------- fp32 -> bf16 hi/lo split -----------------------------------
__global__ void split_k(const float* __restrict__ s, bf16* __restrict__ hi,
                        bf16* __restrict__ lo, int n) {
    int i = (blockIdx.x * blockDim.x + threadIdx.x) * 4;
    if (i >= n) return;
    float4 v = *(const float4*)(s + i);
    uint32_t h0, l0, h1, l1;
    split2(v.x, v.y, h0, l0);
    split2(v.z, v.w, h1, l1);
    *(uint2*)(hi + i) = make_uint2(h0, h1);
    *(uint2*)(lo + i) = make_uint2(l0, l1);
}

// ---------------- CSR build --------------------------------------------------
__global__ void zero_cnt_k() {
    int i = blockIdx.x * blockDim.x + threadIdx.x;
    if (i < NN) g_cnt[i] = 0;
}

__global__ void count_k(const int* __restrict__ dst) {
    int e = blockIdx.x * blockDim.x + threadIdx.x;
    if (e < EE) atomicAdd(&g_cnt[dst[e]], 1);
}

__global__ void scan_k() {
    __shared__ int s[1024];
    __shared__ int carry;
    int tid = threadIdx.x;
    if (tid == 0) carry = 0;
    __syncthreads();
    for (int base = 0; base < NN; base += 1024) {
        int i = base + tid;
        int v = (i < NN) ? g_cnt[i] : 0;
        s[tid] = v;
        __syncthreads();
        #pragma unroll
        for (int off = 1; off < 1024; off <<= 1) {
            int t = 0;
            if (tid >= off) t = s[tid - off];
            __syncthreads();
            if (tid >= off) s[tid] += t;
            __syncthreads();
        }
        int incl  = s[tid];
        int cbase = carry;
        __syncthreads();
        if (i < NN) {
            int ex = cbase + incl - v;
            g_off[i]  = ex;
            g_fill[i] = ex;
        }
        __syncthreads();
        if (tid == 0) carry = cbase + s[1023];
        __syncthreads();
    }
    if (tid == 0) g_off[NN] = carry;
}

__global__ void scatter_k(const int* __restrict__ src, const int* __restrict__ dst,
                          const float* __restrict__ w) {
    int e = blockIdx.x * blockDim.x + threadIdx.x;
    if (e < EE) {
        int d = dst[e];
        int p = atomicAdd(&g_fill[d], 1);
        g_csr_src[p] = src[e];
        g_csr_w[p]   = w[e];
    }
}

// ---------------- adj_mul gather -> bf16 hi/lo output ------------------------
__global__ void gather_k(const float* __restrict__ h,
                         bf16* __restrict__ ahh, bf16* __restrict__ ahl) {
    int node = blockIdx.x * 4 + threadIdx.y;
    if (node >= NN) return;
    int beg = g_off[node], end = g_off[node + 1];
    const float4* H = (const float4*)h;
    int t = threadIdx.x;  // 0..63
    float4 acc = make_float4(0.f, 0.f, 0.f, 0.f);
    for (int k = beg; k < end; ++k) {
        int s  = g_csr_src[k];
        float w = g_csr_w[k];
        float4 v = H[(size_t)s * 64 + t];
        acc.x += v.x * w; acc.y += v.y * w; acc.z += v.z * w; acc.w += v.w * w;
    }
    uint32_t h0, l0, h1, l1;
    split2(acc.x, acc.y, h0, l0);
    split2(acc.z, acc.w, h1, l1);
    ((uint2*)ahh)[(size_t)node * 64 + t] = make_uint2(h0, h1);
    ((uint2*)ahl)[(size_t)node * 64 + t] = make_uint2(l0, l1);
}

// ---------------- bf16x3 tensor-core GEMM (mma.sync, base PTX) ---------------
// C[i,j] = epi( sum_k A[i,k]*W[j,k] ), A = [A1|A2] bf16 hi/lo (ld 256 each),
// W bf16 hi/lo row-major [Ncols, Ktot]. 3 products: hh + hl + lh.
// Block 128x128, BK=32, 256 thr, 8 warps (2x4), warp 64x32, m16n8k16 frags.
template<bool FUSE, bool SPLIT>
__global__ __launch_bounds__(256, 2)
void mma_gemm_k(const bf16* __restrict__ a1h, const bf16* __restrict__ a1l,
                const bf16* __restrict__ a2h, const bf16* __restrict__ a2l,
                int K1, int Ktot,
                const bf16* __restrict__ wh, const bf16* __restrict__ wl,
                const float* __restrict__ bias, const float* __restrict__ res,
                float* __restrict__ C, bf16* __restrict__ Chi, bf16* __restrict__ Clo,
                int M, int Ncols)
{
    extern __shared__ __align__(16) char smem[];
    char* sAH = smem;                 // 128 rows * 144B = 18432 each
    char* sAL = smem + 18432;
    char* sBH = smem + 36864;
    char* sBL = smem + 55296;

    const int tid  = threadIdx.x;
    const int lane = tid & 31, wid = tid >> 5;
    const int wm = wid >> 2, wn = wid & 3;       // warp grid 2 x 4
    const int r = lane >> 2, q = lane & 3;
    const int ib = blockIdx.x * 128, jb = blockIdx.y * 128;

    float acc[4][4][4];
    #pragma unroll
    for (int a = 0; a < 4; ++a)
        #pragma unroll
        for (int b = 0; b < 4; ++b)
            #pragma unroll
            for (int c = 0; c < 4; ++c) acc[a][b][c] = 0.f;

    const int S = Ktot / 32;
    for (int sk = 0; sk < S; ++sk) {
        const int k0 = sk * 32;
        const bf16 *ah, *al; int kk;
        if (k0 < K1) { ah = a1h; al = a1l; kk = k0; }
        else         { ah = a2h; al = a2l; kk = k0 - K1; }

        uint4 vh[2], vl[2], uh[2], ul[2];
        int rows[2], chs[2];
        #pragma unroll
        for (int i = 0; i < 2; ++i) {
            int u = tid + 256 * i;
            int row = u >> 2, ch = u & 3;       // 16B chunk ch covers k = ch*8..
            rows[i] = row; chs[i] = ch;
            int gr = ib + row;
            if (gr < M) {
                vh[i] = *(const uint4*)(ah + (size_t)gr * 256 + kk + ch * 8);
                vl[i] = *(const uint4*)(al + (size_t)gr * 256 + kk + ch * 8);
            } else {
                vh[i] = make_uint4(0, 0, 0, 0);
                vl[i] = make_uint4(0, 0, 0, 0);
            }
            uh[i] = *(const uint4*)(wh + (size_t)(jb + row) * Ktot + k0 + ch * 8);
            ul[i] = *(const uint4*)(wl + (size_t)(jb + row) * Ktot + k0 + ch * 8);
        }
        __syncthreads();                 // prior-stage consumers done
        #pragma unroll
        for (int i = 0; i < 2; ++i) {
            int o = rows[i] * BKB + chs[i] * 16;
            *(uint4*)(sAH + o) = vh[i];
            *(uint4*)(sAL + o) = vl[i];
            *(uint4*)(sBH + o) = uh[i];
            *(uint4*)(sBL + o) = ul[i];
        }
        __syncthreads();

        #pragma unroll
        for (int ks = 0; ks < 2; ++ks) {
            const int kb = ks * 32 + q * 4;
            uint32_t AH[4][4], BH[4][2];
            #pragma unroll
            for (int mt = 0; mt < 4; ++mt) {
                const char* base = sAH + (wm * 64 + mt * 16 + r) * BKB + kb;
                AH[mt][0] = *(const uint32_t*)(base);
                AH[mt][1] = *(const uint32_t*)(base + 8 * BKB);
                AH[mt][2] = *(const uint32_t*)(base + 16);
                AH[mt][3] = *(const uint32_t*)(base + 8 * BKB + 16);
            }
            #pragma unroll
            for (int nt = 0; nt < 4; ++nt) {
                const char* base = sBH + (wn * 32 + nt * 8 + r) * BKB + kb;
                BH[nt][0] = *(const uint32_t*)(base);
                BH[nt][1] = *(const uint32_t*)(base + 16);
            }
            #pragma unroll
            for (int mt = 0; mt < 4; ++mt)
                #pragma unroll
                for (int nt = 0; nt < 4; ++nt)
                    mma_bf16(acc[mt][nt], AH[mt][0], AH[mt][1], AH[mt][2], AH[mt][3],
                             BH[nt][0], BH[nt][1]);

            {   // hi(A) * lo(B)
                uint32_t BL[4][2];
                #pragma unroll
                for (int nt = 0; nt < 4; ++nt) {
                    const char* base = sBL + (wn * 32 + nt * 8 + r) * BKB + kb;
                    BL[nt][0] = *(const uint32_t*)(base);
                    BL[nt][1] = *(const uint32_t*)(base + 16);
                }
                #pragma unroll
                for (int mt = 0; mt < 4; ++mt)
                    #pragma unroll
                    for (int nt = 0; nt < 4; ++nt)
                        mma_bf16(acc[mt][nt], AH[mt][0], AH[mt][1], AH[mt][2], AH[mt][3],
                                 BL[nt][0], BL[nt][1]);
            }
            {   // lo(A) * hi(B)
                uint32_t AL[4][4];
                #pragma unroll
                for (int mt = 0; mt < 4; ++mt) {
                    const char* base = sAL + (wm * 64 + mt * 16 + r) * BKB + kb;
                    AL[mt][0] = *(const uint32_t*)(base);
                    AL[mt][1] = *(const uint32_t*)(base + 8 * BKB);
                    AL[mt][2] = *(const uint32_t*)(base + 16);
                    AL[mt][3] = *(const uint32_t*)(base + 8 * BKB + 16);
                }
                #pragma unroll
                for (int mt = 0; mt < 4; ++mt)
                    #pragma unroll
                    for (int nt = 0; nt < 4; ++nt)
                        mma_bf16(acc[mt][nt], AL[mt][0], AL[mt][1], AL[mt][2], AL[mt][3],
                                 BH[nt][0], BH[nt][1]);
            }
        }
    }

    // ---------------- epilogue ----------------
    #pragma unroll
    for (int mt = 0; mt < 4; ++mt) {
        #pragma unroll
        for (int nt = 0; nt < 4; ++nt) {
            int row0 = ib + wm * 64 + mt * 16 + r;
            int col  = jb + wn * 32 + nt * 8 + 2 * q;
            float2 b2 = make_float2(0.f, 0.f);
            if (FUSE) b2 = *(const float2*)&bias[col];
            #pragma unroll
            for (int hf = 0; hf < 2; ++hf) {
                int row = row0 + 8 * hf;
                if (row >= M) continue;
                float o0 = acc[mt][nt][2 * hf + 0];
                float o1 = acc[mt][nt][2 * hf + 1];
                if (FUSE) {
                    float2 rv = *(const float2*)&res[(size_t)row * Ncols + col];
                    o0 = rv.x + fmaxf(o0 + b2.x, 0.f);
                    o1 = rv.y + fmaxf(o1 + b2.y, 0.f);
                }
                *(float2*)&C[(size_t)row * Ncols + col] = make_float2(o0, o1);
                if (SPLIT) {
                    uint32_t hi, lo;
                    split2(o0, o1, hi, lo);
                    *(uint32_t*)(Chi + (size_t)row * Ncols + col) = hi;
                    *(uint32_t*)(Clo + (size_t)row * Ncols + col) = lo;
                }
            }
        }
    }
}

// ---------------- row L2-normalize (128 cols): one warp per row --------------
__global__ void norm_k(float* __restrict__ out) {
    int row = blockIdx.x * 8 + threadIdx.y;  // blockDim (32,8)
    if (row >= NN) return;
    float4* p = (float4*)out + (size_t)row * 32 + threadIdx.x;
    float4 v = *p;
    float s = v.x * v.x + v.y * v.y + v.z * v.z + v.w * v.w;
    #pragma unroll
    for (int off = 16; off > 0; off >>= 1)
        s += __shfl_xor_sync(0xFFFFFFFFu, s, off);
    float r = rsqrtf(s);
    v.x *= r; v.y *= r; v.z *= r; v.w *= r;
    *p = v;
}

// ---------------- launch -----------------------------------------------------
extern "C" void kernel_launch(void* const* d_in, const int* in_sizes, int n_in,
                              void* d_out, int out_size) {
    const float* x     = (const float*)d_in[0];
    const int*   esrc  = (const int*)  d_in[1];
    const int*   edst  = (const int*)  d_in[2];
    const float* ew    = (const float*)d_in[3];
    const float* W_emb = (const float*)d_in[4];
    const float* W_gc1 = (const float*)d_in[5];
    const float* b_gc1 = (const float*)d_in[6];
    const float* W_gc2 = (const float*)d_in[7];
    const float* b_gc2 = (const float*)d_in[8];
    const float* W_fc  = (const float*)d_in[9];
    float* out = (float*)d_out;

    float *h, *h2;
    bf16 *xh, *xl, *hh, *hl, *h2h, *h2l, *ahh, *ahl;
    bf16 *weh, *wel, *w1h, *w1l, *w2h, *w2l, *wfh, *wfl;
    cudaGetSymbolAddress((void**)&h,   g_h);
    cudaGetSymbolAddress((void**)&h2,  g_h2);
    cudaGetSymbolAddress((void**)&xh,  g_xh);  cudaGetSymbolAddress((void**)&xl,  g_xl);
    cudaGetSymbolAddress((void**)&hh,  g_hh);  cudaGetSymbolAddress((void**)&hl,  g_hl);
    cudaGetSymbolAddress((void**)&h2h, g_h2h); cudaGetSymbolAddress((void**)&h2l, g_h2l);
    cudaGetSymbolAddress((void**)&ahh, g_ahh); cudaGetSymbolAddress((void**)&ahl, g_ahl);
    cudaGetSymbolAddress((void**)&weh, g_weh); cudaGetSymbolAddress((void**)&wel, g_wel);
    cudaGetSymbolAddress((void**)&w1h, g_w1h); cudaGetSymbolAddress((void**)&w1l, g_w1l);
    cudaGetSymbolAddress((void**)&w2h, g_w2h); cudaGetSymbolAddress((void**)&w2l, g_w2l);
    cudaGetSymbolAddress((void**)&wfh, g_wfh); cudaGetSymbolAddress((void**)&wfl, g_wfl);

    const int SMEM = 4 * 128 * BKB;  // 73728
    cudaFuncSetAttribute(mma_gemm_k<true,  true >, cudaFuncAttributeMaxDynamicSharedMemorySize, SMEM);
    cudaFuncSetAttribute(mma_gemm_k<false, true >, cudaFuncAttributeMaxDynamicSharedMemorySize, SMEM);
    cudaFuncSetAttribute(mma_gemm_k<false, false>, cudaFuncAttributeMaxDynamicSharedMemorySize, SMEM);

    // CSR build
    zero_cnt_k<<<(NN + 255) / 256, 256>>>();
    count_k  <<<(EE + 255) / 256, 256>>>(edst);
    scan_k   <<<1, 1024>>>();
    scatter_k<<<(EE + 255) / 256, 256>>>(esrc, edst, ew);

    // precompute bf16 hi/lo splits of x and weights
    split_k<<<(NN * INF / 4 + 255) / 256, 256>>>(x, xh, xl, NN * INF);
    split_k<<<(HIDF * INF / 4 + 255) / 256, 256>>>(W_emb, weh, wel, HIDF * INF);
    split_k<<<(HIDF * 2 * HIDF / 4 + 255) / 256, 256>>>(W_gc1, w1h, w1l, HIDF * 2 * HIDF);
    split_k<<<(HIDF * 2 * HIDF / 4 + 255) / 256, 256>>>(W_gc2, w2h, w2l, HIDF * 2 * HIDF);
    split_k<<<(OUTF * HIDF / 4 + 255) / 256, 256>>>(W_fc, wfh, wfl, OUTF * HIDF);

    const int MT = (NN + 127) / 128;   // 157
    dim3 gHid(MT, HIDF / 128);         // 157 x 2
    dim3 gOut(MT, OUTF / 128);         // 157 x 1
    dim3 gblk(5000), gthr(64, 4);

    // h = x @ W_emb^T  (+ bf16 split of h)
    mma_gemm_k<false, true><<<gHid, 256, SMEM>>>(
        xh, xl, nullptr, nullptr, INF, INF, weh, wel,
        nullptr, nullptr, h, hh, hl, NN, HIDF);
    // Ah = A @ h ; h2 = h + relu([h|Ah] @ W_gc1^T + b1)
    gather_k<<<gblk, gthr>>>(h, ahh, ahl);
    mma_gemm_k<true, true><<<gHid, 256, SMEM>>>(
        hh, hl, ahh, ahl, HIDF, 2 * HIDF, w1h, w1l,
        b_gc1, h, h2, h2h, h2l, NN, HIDF);
    // Ah = A @ h2 ; h = h2 + relu([h2|Ah] @ W_gc2^T + b2)
    gather_k<<<gblk, gthr>>>(h2, ahh, ahl);
    mma_gemm_k<true, true><<<gHid, 256, SMEM>>>(
        h2h, h2l, ahh, ahl, HIDF, 2 * HIDF, w2h, w2l,
        b_gc2, h2, h, hh, hl, NN, HIDF);
    // out = h @ W_fc^T ; rows L2-normalized
    mma_gemm_k<false, false><<<gOut, 256, SMEM>>>(
        hh, hl, nullptr, nullptr, HIDF, HIDF, wfh, wfl,
        nullptr, nullptr, out, nullptr, nullptr, NN, OUTF);
    norm_k<<<(NN + 7) / 8, dim3(32, 8)>>>(out);
}

// round 5
// speedup vs baseline: 1.1248x; 1.0338x over previous
#include <cuda_runtime.h>
#include <cuda_bf16.h>
#include <cstdint>

#define NN   20000
#define EE   320000
#define INF  256
#define HIDF 256
#define OUTF 128
#define BKB  144   // padded smem row stride (bytes) -> conflict-free fragments

typedef __nv_bfloat16 bf16;

// ---------------- scratch (device globals; no allocation allowed) ------------
__device__ float g_h [NN * HIDF];
__device__ float g_h2[NN * HIDF];
__device__ bf16  g_xh [NN * HIDF], g_xl [NN * HIDF];
__device__ bf16  g_hh [NN * HIDF], g_hl [NN * HIDF];
__device__ bf16  g_h2h[NN * HIDF], g_h2l[NN * HIDF];
__device__ bf16  g_ahh[NN * HIDF], g_ahl[NN * HIDF];
__device__ bf16  g_weh[HIDF * INF],     g_wel[HIDF * INF];
__device__ bf16  g_w1h[HIDF * 2 * HIDF], g_w1l[HIDF * 2 * HIDF];
__device__ bf16  g_w2h[HIDF * 2 * HIDF], g_w2l[HIDF * 2 * HIDF];
__device__ bf16  g_wfh[OUTF * HIDF],    g_wfl[OUTF * HIDF];
__device__ int   g_cnt[NN];
__device__ int   g_off[NN + 1];
__device__ int   g_fill[NN];
__device__ int   g_csr_src[EE];
__device__ float g_csr_w[EE];

// ---------------- helpers ----------------------------------------------------
__device__ __forceinline__ void split2(float x, float y, uint32_t& hi, uint32_t& lo) {
    bf16 hx = __float2bfloat16_rn(x);
    bf16 hy = __float2bfloat16_rn(y);
    float rx = x - __bfloat162float(hx);
    float ry = y - __bfloat162float(hy);
    __nv_bfloat162 H; H.x = hx; H.y = hy;
    __nv_bfloat162 L = __floats2bfloat162_rn(rx, ry);
    hi = *reinterpret_cast<uint32_t*>(&H);
    lo = *reinterpret_cast<uint32_t*>(&L);
}

__device__ __forceinline__ void mma_bf16(float c[4],
                                         uint32_t a0, uint32_t a1, uint32_t a2, uint32_t a3,
                                         uint32_t b0, uint32_t b1) {
    asm volatile(
        "mma.sync.aligned.m16n8k16.row.col.f32.bf16.bf16.f32 "
        "{%0,%1,%2,%3}, {%4,%5,%6,%7}, {%8,%9}, {%0,%1,%2,%3};"
        : "+f"(c[0]), "+f"(c[1]), "+f"(c[2]), "+f"(c[3])
        : "r"(a0), "r"(a1), "r"(a2), "r"(a3), "r"(b0), "r"(b1));
}

// ---------------- fp32 -> bf16 hi/lo splits ----------------------------------
__global__ void split_k(const float* __restrict__ s, bf16* __restrict__ hi,
                        bf16* __restrict__ lo, int n) {
    int i = (blockIdx.x * blockDim.x + threadIdx.x) * 4;
    if (i >= n) return;
    float4 v = *(const float4*)(s + i);
    uint32_t h0, l0, h1, l1;
    split2(v.x, v.y, h0, l0);
    split2(v.z, v.w, h1, l1);
    *(uint2*)(hi + i) = make_uint2(h0, h1);
    *(uint2*)(lo + i) = make_uint2(l0, l1);
}

// fused split of W_gc1, W_gc2, W_fc in one launch
__global__ void split3_k(const float* __restrict__ s0, bf16* __restrict__ h0, bf16* __restrict__ l0, int n0,
                         const float* __restrict__ s1, bf16* __restrict__ h1, bf16* __restrict__ l1, int n1,
                         const float* __restrict__ s2, bf16* __restrict__ h2, bf16* __restrict__ l2, int n2) {
    int i = (blockIdx.x * blockDim.x + threadIdx.x) * 4;
    const float* s; bf16 *hh, *ll;
    if (i < n0)              { s = s0 + i;            hh = h0 + i;            ll = l0 + i; }
    else if (i < n0 + n1)    { s = s1 + (i - n0);     hh = h1 + (i - n0);     ll = l1 + (i - n0); }
    else if (i < n0 + n1 + n2){ s = s2 + (i - n0 - n1); hh = h2 + (i - n0 - n1); ll = l2 + (i - n0 - n1); }
    else return;
    float4 v = *(const float4*)s;
    uint32_t a, b, c, d;
    split2(v.x, v.y, a, b);
    split2(v.z, v.w, c, d);
    *(uint2*)hh = make_uint2(a, c);
    *(uint2*)ll = make_uint2(b, d);
}

// ---------------- CSR build --------------------------------------------------
__global__ void zero_cnt_k() {
    int i = blockIdx.x * blockDim.x + threadIdx.x;
    if (i < NN) g_cnt[i] = 0;
}

__global__ void count_k(const int* __restrict__ dst) {
    int e = blockIdx.x * blockDim.x + threadIdx.x;
    if (e < EE) atomicAdd(&g_cnt[dst[e]], 1);
}

__global__ void scan_k() {
    __shared__ int s[1024];
    __shared__ int carry;
    int tid = threadIdx.x;
    if (tid == 0) carry = 0;
    __syncthreads();
    for (int base = 0; base < NN; base += 1024) {
        int i = base + tid;
        int v = (i < NN) ? g_cnt[i] : 0;
        s[tid] = v;
        __syncthreads();
        #pragma unroll
        for (int off = 1; off < 1024; off <<= 1) {
            int t = 0;
            if (tid >= off) t = s[tid - off];
            __syncthreads();
            if (tid >= off) s[tid] += t;
            __syncthreads();
        }
        int incl  = s[tid];
        int cbase = carry;
        __syncthreads();
        if (i < NN) {
            int ex = cbase + incl - v;
            g_off[i]  = ex;
            g_fill[i] = ex;
        }
        __syncthreads();
        if (tid == 0) carry = cbase + s[1023];
        __syncthreads();
    }
    if (tid == 0) g_off[NN] = carry;
}

__global__ void scatter_k(const int* __restrict__ src, const int* __restrict__ dst,
                          const float* __restrict__ w) {
    int e = blockIdx.x * blockDim.x + threadIdx.x;
    if (e < EE) {
        int d = dst[e];
        int p = atomicAdd(&g_fill[d], 1);
        g_csr_src[p] = src[e];
        g_csr_w[p]   = w[e];
    }
}

// ---------------- adj_mul gather, 4-way unrolled (MLP>=4) --------------------
__global__ void gather_k(const float* __restrict__ h,
                         bf16* __restrict__ ahh, bf16* __restrict__ ahl) {
    int node = blockIdx.x * 4 + threadIdx.y;
    if (node >= NN) return;
    int beg = g_off[node], end = g_off[node + 1];
    const float4* __restrict__ H = (const float4*)h;
    int t = threadIdx.x;  // 0..63
    float ax = 0.f, ay = 0.f, az = 0.f, aw = 0.f;

    int k = beg;
    for (; k + 4 <= end; k += 4) {
        int4  s4 = *(const int4*)  &g_csr_src[k];   // aligned? k arbitrary -> use scalars
        // NOTE: k not 4-aligned in general; use scalar loads (still batched by compiler)
        int   s0 = g_csr_src[k],     s1 = g_csr_src[k + 1];
        int   s2 = g_csr_src[k + 2], s3 = g_csr_src[k + 3];
        float w0 = g_csr_w[k],       w1 = g_csr_w[k + 1];
        float w2 = g_csr_w[k + 2],   w3 = g_csr_w[k + 3];
        (void)s4;
        float4 v0 = H[(size_t)s0 * 64 + t];
        float4 v1 = H[(size_t)s1 * 64 + t];
        float4 v2 = H[(size_t)s2 * 64 + t];
        float4 v3 = H[(size_t)s3 * 64 + t];
        ax = fmaf(v0.x, w0, fmaf(v1.x, w1, fmaf(v2.x, w2, fmaf(v3.x, w3, ax))));
        ay = fmaf(v0.y, w0, fmaf(v1.y, w1, fmaf(v2.y, w2, fmaf(v3.y, w3, ay))));
        az = fmaf(v0.z, w0, fmaf(v1.z, w1, fmaf(v2.z, w2, fmaf(v3.z, w3, az))));
        aw = fmaf(v0.w, w0, fmaf(v1.w, w1, fmaf(v2.w, w2, fmaf(v3.w, w3, aw))));
    }
    for (; k < end; ++k) {
        int s = g_csr_src[k];
        float w = g_csr_w[k];
        float4 v = H[(size_t)s * 64 + t];
        ax = fmaf(v.x, w, ax); ay = fmaf(v.y, w, ay);
        az = fmaf(v.z, w, az); aw = fmaf(v.w, w, aw);
    }
    uint32_t h0, l0, h1, l1;
    split2(ax, ay, h0, l0);
    split2(az, aw, h1, l1);
    ((uint2*)ahh)[(size_t)node * 64 + t] = make_uint2(h0, h1);
    ((uint2*)ahl)[(size_t)node * 64 + t] = make_uint2(l0, l1);
}

// ---------------- bf16x3 tensor-core GEMM (mma.sync, base PTX) ---------------
template<bool FUSE, bool SPLIT>
__global__ __launch_bounds__(256, 2)
void mma_gemm_k(const bf16* __restrict__ a1h, const bf16* __restrict__ a1l,
                const bf16* __restrict__ a2h, const bf16* __restrict__ a2l,
                int K1, int Ktot,
                const bf16* __restrict__ wh, const bf16* __restrict__ wl,
                const float* __restrict__ bias, const float* __restrict__ res,
                float* __restrict__ C, bf16* __restrict__ Chi, bf16* __restrict__ Clo,
                int M, int Ncols)
{
    extern __shared__ __align__(16) char smem[];
    char* sAH = smem;                 // 128 rows * 144B = 18432 each
    char* sAL = smem + 18432;
    char* sBH = smem + 36864;
    char* sBL = smem + 55296;

    const int tid  = threadIdx.x;
    const int lane = tid & 31, wid = tid >> 5;
    const int wm = wid >> 2, wn = wid & 3;       // warp grid 2 x 4
    const int r = lane >> 2, q = lane & 3;
    const int ib = blockIdx.x * 128, jb = blockIdx.y * 128;

    float acc[4][4][4];
    #pragma unroll
    for (int a = 0; a < 4; ++a)
        #pragma unroll
        for (int b = 0; b < 4; ++b)
            #pragma unroll
            for (int c = 0; c < 4; ++c) acc[a][b][c] = 0.f;

    const int S = Ktot / 32;
    for (int sk = 0; sk < S; ++sk) {
        const int k0 = sk * 32;
        const bf16 *ah, *al; int kk;
        if (k0 < K1) { ah = a1h; al = a1l; kk = k0; }
        else         { ah = a2h; al = a2l; kk = k0 - K1; }

        uint4 vh[2], vl[2], uh[2], ul[2];
        int rows[2], chs[2];
        #pragma unroll
        for (int i = 0; i < 2; ++i) {
            int u = tid + 256 * i;
            int row = u >> 2, ch = u & 3;       // 16B chunk ch covers k = ch*8..
            rows[i] = row; chs[i] = ch;
            int gr = ib + row;
            if (gr < M) {
                vh[i] = *(const uint4*)(ah + (size_t)gr * 256 + kk + ch * 8);
                vl[i] = *(const uint4*)(al + (size_t)gr * 256 + kk + ch * 8);
            } else {
                vh[i] = make_uint4(0, 0, 0, 0);
                vl[i] = make_uint4(0, 0, 0, 0);
            }
            uh[i] = *(const uint4*)(wh + (size_t)(jb + row) * Ktot + k0 + ch * 8);
            ul[i] = *(const uint4*)(wl + (size_t)(jb + row) * Ktot + k0 + ch * 8);
        }
        __syncthreads();                 // prior-stage consumers done
        #pragma unroll
        for (int i = 0; i < 2; ++i) {
            int o = rows[i] * BKB + chs[i] * 16;
            *(uint4*)(sAH + o) = vh[i];
            *(uint4*)(sAL + o) = vl[i];
            *(uint4*)(sBH + o) = uh[i];
            *(uint4*)(sBL + o) = ul[i];
        }
        __syncthreads();

        #pragma unroll
        for (int ks = 0; ks < 2; ++ks) {
            const int kb = ks * 32 + q * 4;
            uint32_t AH[4][4], BH[4][2];
            #pragma unroll
            for (int mt = 0; mt < 4; ++mt) {
                const char* base = sAH + (wm * 64 + mt * 16 + r) * BKB + kb;
                AH[mt][0] = *(const uint32_t*)(base);
                AH[mt][1] = *(const uint32_t*)(base + 8 * BKB);
                AH[mt][2] = *(const uint32_t*)(base + 16);
                AH[mt][3] = *(const uint32_t*)(base + 8 * BKB + 16);
            }
            #pragma unroll
            for (int nt = 0; nt < 4; ++nt) {
                const char* base = sBH + (wn * 32 + nt * 8 + r) * BKB + kb;
                BH[nt][0] = *(const uint32_t*)(base);
                BH[nt][1] = *(const uint32_t*)(base + 16);
            }
            #pragma unroll
            for (int mt = 0; mt < 4; ++mt)
                #pragma unroll
                for (int nt = 0; nt < 4; ++nt)
                    mma_bf16(acc[mt][nt], AH[mt][0], AH[mt][1], AH[mt][2], AH[mt][3],
                             BH[nt][0], BH[nt][1]);

            {   // hi(A) * lo(B)
                uint32_t BL[4][2];
                #pragma unroll
                for (int nt = 0; nt < 4; ++nt) {
                    const char* base = sBL + (wn * 32 + nt * 8 + r) * BKB + kb;
                    BL[nt][0] = *(const uint32_t*)(base);
                    BL[nt][1] = *(const uint32_t*)(base + 16);
                }
                #pragma unroll
                for (int mt = 0; mt < 4; ++mt)
                    #pragma unroll
                    for (int nt = 0; nt < 4; ++nt)
                        mma_bf16(acc[mt][nt], AH[mt][0], AH[mt][1], AH[mt][2], AH[mt][3],
                                 BL[nt][0], BL[nt][1]);
            }
            {   // lo(A) * hi(B)
                uint32_t AL[4][4];
                #pragma unroll
                for (int mt = 0; mt < 4; ++mt) {
                    const char* base = sAL + (wm * 64 + mt * 16 + r) * BKB + kb;
                    AL[mt][0] = *(const uint32_t*)(base);
                    AL[mt][1] = *(const uint32_t*)(base + 8 * BKB);
                    AL[mt][2] = *(const uint32_t*)(base + 16);
                    AL[mt][3] = *(const uint32_t*)(base + 8 * BKB + 16);
                }
                #pragma unroll
                for (int mt = 0; mt < 4; ++mt)
                    #pragma unroll
                    for (int nt = 0; nt < 4; ++nt)
                        mma_bf16(acc[mt][nt], AL[mt][0], AL[mt][1], AL[mt][2], AL[mt][3],
                                 BH[nt][0], BH[nt][1]);
            }
        }
    }

    // ---------------- epilogue ----------------
    #pragma unroll
    for (int mt = 0; mt < 4; ++mt) {
        #pragma unroll
        for (int nt = 0; nt < 4; ++nt) {
            int row0 = ib + wm * 64 + mt * 16 + r;
            int col  = jb + wn * 32 + nt * 8 + 2 * q;
            float2 b2 = make_float2(0.f, 0.f);
            if (FUSE) b2 = *(const float2*)&bias[col];
            #pragma unroll
            for (int hf = 0; hf < 2; ++hf) {
                int row = row0 + 8 * hf;
                if (row >= M) continue;
                float o0 = acc[mt][nt][2 * hf + 0];
                float o1 = acc[mt][nt][2 * hf + 1];
                if (FUSE) {
                    float2 rv = *(const float2*)&res[(size_t)row * Ncols + col];
                    o0 = rv.x + fmaxf(o0 + b2.x, 0.f);
                    o1 = rv.y + fmaxf(o1 + b2.y, 0.f);
                }
                *(float2*)&C[(size_t)row * Ncols + col] = make_float2(o0, o1);
                if (SPLIT) {
                    uint32_t hi, lo;
                    split2(o0, o1, hi, lo);
                    *(uint32_t*)(Chi + (size_t)row * Ncols + col) = hi;
                    *(uint32_t*)(Clo + (size_t)row * Ncols + col) = lo;
                }
            }
        }
    }
}

// ---------------- row L2-normalize (128 cols): one warp per row --------------
__global__ void norm_k(float* __restrict__ out) {
    int row = blockIdx.x * 8 + threadIdx.y;  // blockDim (32,8)
    if (row >= NN) return;
    float4* p = (float4*)out + (size_t)row * 32 + threadIdx.x;
    float4 v = *p;
    float s = v.x * v.x + v.y * v.y + v.z * v.z + v.w * v.w;
    #pragma unroll
    for (int off = 16; off > 0; off >>= 1)
        s += __shfl_xor_sync(0xFFFFFFFFu, s, off);
    float r = rsqrtf(s);
    v.x *= r; v.y *= r; v.z *= r; v.w *= r;
    *p = v;
}

// ---------------- launch -----------------------------------------------------
extern "C" void kernel_launch(void* const* d_in, const int* in_sizes, int n_in,
                              void* d_out, int out_size) {
    const float* x     = (const float*)d_in[0];
    const int*   esrc  = (const int*)  d_in[1];
    const int*   edst  = (const int*)  d_in[2];
    const float* ew    = (const float*)d_in[3];
    const float* W_emb = (const float*)d_in[4];
    const float* W_gc1 = (const float*)d_in[5];
    const float* b_gc1 = (const float*)d_in[6];
    const float* W_gc2 = (const float*)d_in[7];
    const float* b_gc2 = (const float*)d_in[8];
    const float* W_fc  = (const float*)d_in[9];
    float* out = (float*)d_out;

    float *h, *h2;
    bf16 *xh, *xl, *hh, *hl, *h2h, *h2l, *ahh, *ahl;
    bf16 *weh, *wel, *w1h, *w1l, *w2h, *w2l, *wfh, *wfl;
    cudaGetSymbolAddress((void**)&h,   g_h);
    cudaGetSymbolAddress((void**)&h2,  g_h2);
    cudaGetSymbolAddress((void**)&xh,  g_xh);  cudaGetSymbolAddress((void**)&xl,  g_xl);
    cudaGetSymbolAddress((void**)&hh,  g_hh);  cudaGetSymbolAddress((void**)&hl,  g_hl);
    cudaGetSymbolAddress((void**)&h2h, g_h2h); cudaGetSymbolAddress((void**)&h2l, g_h2l);
    cudaGetSymbolAddress((void**)&ahh, g_ahh); cudaGetSymbolAddress((void**)&ahl, g_ahl);
    cudaGetSymbolAddress((void**)&weh, g_weh); cudaGetSymbolAddress((void**)&wel, g_wel);
    cudaGetSymbolAddress((void**)&w1h, g_w1h); cudaGetSymbolAddress((void**)&w1l, g_w1l);
    cudaGetSymbolAddress((void**)&w2h, g_w2h); cudaGetSymbolAddress((void**)&w2l, g_w2l);
    cudaGetSymbolAddress((void**)&wfh, g_wfh); cudaGetSymbolAddress((void**)&wfl, g_wfl);

    const int SMEM = 4 * 128 * BKB;  // 73728
    cudaFuncSetAttribute(mma_gemm_k<true,  true >, cudaFuncAttributeMaxDynamicSharedMemorySize, SMEM);
    cudaFuncSetAttribute(mma_gemm_k<false, true >, cudaFuncAttributeMaxDynamicSharedMemorySize, SMEM);
    cudaFuncSetAttribute(mma_gemm_k<false, false>, cudaFuncAttributeMaxDynamicSharedMemorySize, SMEM);

    const int MT = (NN + 127) / 128;   // 157
    dim3 gHid(MT, HIDF / 128);         // 157 x 2
    dim3 gOut(MT, OUTF / 128);         // 157 x 1
    dim3 gblk(5000), gthr(64, 4);

    // -- launch order arranged so my index-3 launch (ncu capture slot) is the
    //    emb GEMM: split_x(0), split_We(1), zero(2), gemm_emb(3), ...
    split_k<<<(NN * INF / 4 + 255) / 256, 256>>>(x, xh, xl, NN * INF);                 // 0
    split_k<<<(HIDF * INF / 4 + 255) / 256, 256>>>(W_emb, weh, wel, HIDF * INF);       // 1
    zero_cnt_k<<<(NN + 255) / 256, 256>>>();                                           // 2
    mma_gemm_k<false, true><<<gHid, 256, SMEM>>>(                                      // 3 (ncu)
        xh, xl, nullptr, nullptr, INF, INF, weh, wel,
        nullptr, nullptr, h, hh, hl, NN, HIDF);
    count_k  <<<(EE + 255) / 256, 256>>>(edst);                                        // 4
    scan_k   <<<1, 1024>>>();                                                          // 5
    scatter_k<<<(EE + 255) / 256, 256>>>(esrc, edst, ew);                              // 6
    split3_k<<<((2 * HIDF * 2 * HIDF + OUTF * HIDF) / 4 + 255) / 256, 256>>>(          // 7
        W_gc1, w1h, w1l, HIDF * 2 * HIDF,
        W_gc2, w2h, w2l, HIDF * 2 * HIDF,
        W_fc,  wfh, wfl, OUTF * HIDF);

    // Ah = A @ h ; h2 = h + relu([h|Ah] @ W_gc1^T + b1)
    gather_k<<<gblk, gthr>>>(h, ahh, ahl);                                             // 8
    mma_gemm_k<true, true><<<gHid, 256, SMEM>>>(                                       // 9
        hh, hl, ahh, ahl, HIDF, 2 * HIDF, w1h, w1l,
        b_gc1, h, h2, h2h, h2l, NN, HIDF);
    // Ah = A @ h2 ; h = h2 + relu([h2|Ah] @ W_gc2^T + b2)
    gather_k<<<gblk, gthr>>>(h2, ahh, ahl);                                            // 10
    mma_gemm_k<true, true><<<gHid, 256, SMEM>>>(                                       // 11
        h2h, h2l, ahh, ahl, HIDF, 2 * HIDF, w2h, w2l,
        b_gc2, h2, h, hh, hl, NN, HIDF);
    // out = h @ W_fc^T ; rows L2-normalized
    mma_gemm_k<false, false><<<gOut, 256, SMEM>>>(                                     // 12
        hh, hl, nullptr, nullptr, HIDF, HIDF, wfh, wfl,
        nullptr, nullptr, out, nullptr, nullptr, NN, OUTF);
    norm_k<<<(NN + 7) / 8, dim3(32, 8)>>>(out);                                        // 13
}

// round 6
// speedup vs baseline: 2.0214x; 1.7970x over previous
#include <cuda_runtime.h>
#include <cuda_bf16.h>
#include <cstdint>

#define NN   20000
#define EE   320000
#define INF  256
#define HIDF 256
#define OUTF 128
#define RS   80      // padded smem row stride (bytes): conflict-free ldmatrix
#define MATB (128 * RS)          // 10240 bytes per matrix tile
#define STGB (4 * MATB)          // 40960 bytes per stage (AH, AL, BH, BL)

typedef __nv_bfloat16 bf16;

// ---------------- scratch (device globals; no allocation allowed) ------------
__device__ float g_h [NN * HIDF];
__device__ float g_h2[NN * HIDF];
__device__ bf16  g_xh [NN * HIDF], g_xl [NN * HIDF];
__device__ bf16  g_hh [NN * HIDF], g_hl [NN * HIDF];
__device__ bf16  g_h2h[NN * HIDF], g_h2l[NN * HIDF];
__device__ bf16  g_ahh[NN * HIDF], g_ahl[NN * HIDF];
__device__ bf16  g_weh[HIDF * INF],      g_wel[HIDF * INF];
__device__ bf16  g_w1h[HIDF * 2 * HIDF], g_w1l[HIDF * 2 * HIDF];
__device__ bf16  g_w2h[HIDF * 2 * HIDF], g_w2l[HIDF * 2 * HIDF];
__device__ bf16  g_wfh[OUTF * HIDF],     g_wfl[OUTF * HIDF];
__device__ int   g_cnt[NN];
__device__ int   g_off[NN + 1];
__device__ int   g_fill[NN];
__device__ int   g_csr_src[EE];
__device__ float g_csr_w[EE];

// ---------------- helpers ----------------------------------------------------
__device__ __forceinline__ uint32_t smem_u32(const void* p) {
    uint32_t a;
    asm("{ .reg .u64 t; cvta.to.shared.u64 t, %1; cvt.u32.u64 %0, t; }"
        : "=r"(a) : "l"(p));
    return a;
}

__device__ __forceinline__ void split2(float x, float y, uint32_t& hi, uint32_t& lo) {
    bf16 hx = __float2bfloat16_rn(x);
    bf16 hy = __float2bfloat16_rn(y);
    float rx = x - __bfloat162float(hx);
    float ry = y - __bfloat162float(hy);
    __nv_bfloat162 H; H.x = hx; H.y = hy;
    __nv_bfloat162 L = __floats2bfloat162_rn(rx, ry);
    hi = *reinterpret_cast<uint32_t*>(&H);
    lo = *reinterpret_cast<uint32_t*>(&L);
}

__device__ __forceinline__ void mma_bf16(float c[4],
                                         uint32_t a0, uint32_t a1, uint32_t a2, uint32_t a3,
                                         uint32_t b0, uint32_t b1) {
    asm volatile(
        "mma.sync.aligned.m16n8k16.row.col.f32.bf16.bf16.f32 "
        "{%0,%1,%2,%3}, {%4,%5,%6,%7}, {%8,%9}, {%0,%1,%2,%3};"
        : "+f"(c[0]), "+f"(c[1]), "+f"(c[2]), "+f"(c[3])
        : "r"(a0), "r"(a1), "r"(a2), "r"(a3), "r"(b0), "r"(b1));
}

#define LDSM_X4(r0, r1, r2, r3, addr) \
    asm volatile("ldmatrix.sync.aligned.m8n8.x4.shared.b16 {%0,%1,%2,%3}, [%4];" \
                 : "=r"(r0), "=r"(r1), "=r"(r2), "=r"(r3) : "r"(addr))

#define CP_ASYNC16(dst, src, sz) \
    asm volatile("cp.async.cg.shared.global [%0], [%1], 16, %2;" \
                 :: "r"(dst), "l"(src), "r"(sz) : "memory")

#define CP_COMMIT() asm volatile("cp.async.commit_group;" ::: "memory")

// ---------------- fp32 -> bf16 hi/lo splits ----------------------------------
__global__ void split_k(const float* __restrict__ s, bf16* __restrict__ hi,
                        bf16* __restrict__ lo, int n) {
    int i = (blockIdx.x * blockDim.x + threadIdx.x) * 4;
    if (i >= n) return;
    float4 v = *(const float4*)(s + i);
    uint32_t h0, l0, h1, l1;
    split2(v.x, v.y, h0, l0);
    split2(v.z, v.w, h1, l1);
    *(uint2*)(hi + i) = make_uint2(h0, h1);
    *(uint2*)(lo + i) = make_uint2(l0, l1);
}

__global__ void split3_k(const float* __restrict__ s0, bf16* __restrict__ h0, bf16* __restrict__ l0, int n0,
                         const float* __restrict__ s1, bf16* __restrict__ h1, bf16* __restrict__ l1, int n1,
                         const float* __restrict__ s2, bf16* __restrict__ h2, bf16* __restrict__ l2, int n2) {
    int i = (blockIdx.x * blockDim.x + threadIdx.x) * 4;
    const float* s; bf16 *hh, *ll;
    if (i < n0)               { s = s0 + i;             hh = h0 + i;             ll = l0 + i; }
    else if (i < n0 + n1)     { s = s1 + (i - n0);      hh = h1 + (i - n0);      ll = l1 + (i - n0); }
    else if (i < n0 + n1 + n2){ s = s2 + (i - n0 - n1); hh = h2 + (i - n0 - n1); ll = l2 + (i - n0 - n1); }
    else return;
    float4 v = *(const float4*)s;
    uint32_t a, b, c, d;
    split2(v.x, v.y, a, b);
    split2(v.z, v.w, c, d);
    *(uint2*)hh = make_uint2(a, c);
    *(uint2*)ll = make_uint2(b, d);
}

// ---------------- CSR build --------------------------------------------------
__global__ void zero_cnt_k() {
    int i = blockIdx.x * blockDim.x + threadIdx.x;
    if (i < NN) g_cnt[i] = 0;
}

__global__ void count_k(const int* __restrict__ dst) {
    int e = blockIdx.x * blockDim.x + threadIdx.x;
    if (e < EE) atomicAdd(&g_cnt[dst[e]], 1);
}

__global__ void scan_k() {
    __shared__ int s[1024];
    __shared__ int carry;
    int tid = threadIdx.x;
    if (tid == 0) carry = 0;
    __syncthreads();
    for (int base = 0; base < NN; base += 1024) {
        int i = base + tid;
        int v = (i < NN) ? g_cnt[i] : 0;
        s[tid] = v;
        __syncthreads();
        #pragma unroll
        for (int off = 1; off < 1024; off <<= 1) {
            int t = 0;
            if (tid >= off) t = s[tid - off];
            __syncthreads();
            if (tid >= off) s[tid] += t;
            __syncthreads();
        }
        int incl  = s[tid];
        int cbase = carry;
        __syncthreads();
        if (i < NN) {
            int ex = cbase + incl - v;
            g_off[i]  = ex;
            g_fill[i] = ex;
        }
        __syncthreads();
        if (tid == 0) carry = cbase + s[1023];
        __syncthreads();
    }
    if (tid == 0) g_off[NN] = carry;
}

__global__ void scatter_k(const int* __restrict__ src, const int* __restrict__ dst,
                          const float* __restrict__ w) {
    int e = blockIdx.x * blockDim.x + threadIdx.x;
    if (e < EE) {
        int d = dst[e];
        int p = atomicAdd(&g_fill[d], 1);
        g_csr_src[p] = src[e];
        g_csr_w[p]   = w[e];
    }
}

// ---------------- adj_mul gather, 4-way unrolled (MLP>=4) --------------------
__global__ void gather_k(const float* __restrict__ h,
                         bf16* __restrict__ ahh, bf16* __restrict__ ahl) {
    int node = blockIdx.x * 4 + threadIdx.y;
    if (node >= NN) return;
    int beg = g_off[node], end = g_off[node + 1];
    const float4* __restrict__ H = (const float4*)h;
    int t = threadIdx.x;  // 0..63
    float ax = 0.f, ay = 0.f, az = 0.f, aw = 0.f;

    int k = beg;
    for (; k + 4 <= end; k += 4) {
        int   s0 = g_csr_src[k],     s1 = g_csr_src[k + 1];
        int   s2 = g_csr_src[k + 2], s3 = g_csr_src[k + 3];
        float w0 = g_csr_w[k],       w1 = g_csr_w[k + 1];
        float w2 = g_csr_w[k + 2],   w3 = g_csr_w[k + 3];
        float4 v0 = H[(size_t)s0 * 64 + t];
        float4 v1 = H[(size_t)s1 * 64 + t];
        float4 v2 = H[(size_t)s2 * 64 + t];
        float4 v3 = H[(size_t)s3 * 64 + t];
        ax = fmaf(v0.x, w0, fmaf(v1.x, w1, fmaf(v2.x, w2, fmaf(v3.x, w3, ax))));
        ay = fmaf(v0.y, w0, fmaf(v1.y, w1, fmaf(v2.y, w2, fmaf(v3.y, w3, ay))));
        az = fmaf(v0.z, w0, fmaf(v1.z, w1, fmaf(v2.z, w2, fmaf(v3.z, w3, az))));
        aw = fmaf(v0.w, w0, fmaf(v1.w, w1, fmaf(v2.w, w2, fmaf(v3.w, w3, aw))));
    }
    for (; k < end; ++k) {
        int s = g_csr_src[k];
        float w = g_csr_w[k];
        float4 v = H[(size_t)s * 64 + t];
        ax = fmaf(v.x, w, ax); ay = fmaf(v.y, w, ay);
        az = fmaf(v.z, w, az); aw = fmaf(v.w, w, aw);
    }
    uint32_t h0, l0, h1, l1;
    split2(ax, ay, h0, l0);
    split2(az, aw, h1, l1);
    ((uint2*)ahh)[(size_t)node * 64 + t] = make_uint2(h0, h1);
    ((uint2*)ahl)[(size_t)node * 64 + t] = make_uint2(l0, l1);
}

// ---------------- bf16x3 tensor-core GEMM: cp.async + ldmatrix ---------------
// C = epi( [A1|A2] @ W^T ). A arrays row stride 256 (K1 = 256 always).
// Block 128x128, 8 warps (2x4), warp 64x32. K staged 32-deep, double-buffered.
// smem per stage: AH | AL | BH | BL, 128 rows x 64B data padded to RS=80B.
template<bool FUSE, bool SPLIT>
__global__ __launch_bounds__(256, 2)
void mma_gemm_k(const bf16* __restrict__ a1h, const bf16* __restrict__ a1l,
                const bf16* __restrict__ a2h, const bf16* __restrict__ a2l,
                int Ktot,
                const bf16* __restrict__ wh, const bf16* __restrict__ wl,
                const float* __restrict__ bias, const float* __restrict__ res,
                float* __restrict__ C, bf16* __restrict__ Chi, bf16* __restrict__ Clo,
                int M, int Ncols)
{
    extern __shared__ __align__(16) char smem[];
    const uint32_t sb = smem_u32(smem);
    const int tid  = threadIdx.x;
    const int lane = tid & 31, wid = tid >> 5;
    const int wm = wid >> 2, wn = wid & 3;
    const int r = lane >> 2, q = lane & 3;
    const int ib = blockIdx.x * 128, jb = blockIdx.y * 128;
    const int S = Ktot / 32;

    float acc[4][4][4];
    #pragma unroll
    for (int a = 0; a < 4; ++a)
        #pragma unroll
        for (int b = 0; b < 4; ++b)
            #pragma unroll
            for (int c = 0; c < 4; ++c) acc[a][b][c] = 0.f;

    // async fill of stage s into buffer s&1 (8 x 16B per thread)
    auto fill = [&](int s) {
        const int k0 = s * 32;
        const uint32_t stb = sb + (s & 1) * STGB;
        #pragma unroll
        for (int i = 0; i < 8; ++i) {
            int g = i * 256 + tid;
            int mat = g >> 9, idx = g & 511;
            int row = idx >> 2, c = idx & 3;
            uint32_t dst = stb + mat * MATB + row * RS + c * 16;
            const bf16* src;
            int sz = 16;
            if (mat < 2) {
                const bf16* a = (k0 < 256) ? (mat == 0 ? a1h : a1l)
                                           : (mat == 0 ? a2h : a2l);
                int gr = ib + row;
                if (gr >= M) { gr = 0; sz = 0; }
                src = a + (size_t)gr * 256 + (k0 & 255) + c * 8;
            } else {
                src = ((mat == 2) ? wh : wl) + (size_t)(jb + row) * Ktot + k0 + c * 8;
            }
            CP_ASYNC16(dst, src, sz);
        }
        CP_COMMIT();
    };

    fill(0);

    for (int s = 0; s < S; ++s) {
        if (s + 1 < S) {
            fill(s + 1);
            asm volatile("cp.async.wait_group 1;" ::: "memory");
        } else {
            asm volatile("cp.async.wait_group 0;" ::: "memory");
        }
        __syncthreads();

        const uint32_t stb = sb + (s & 1) * STGB;
        const uint32_t aBase = stb;
        const uint32_t bBase = stb + 2 * MATB;

        #pragma unroll
        for (int ks = 0; ks < 2; ++ks) {
            const uint32_t aCol = ks * 32 + ((lane >> 4) << 4);
            const uint32_t bCol = ks * 32 + (((lane >> 3) & 1) << 4);
            const int aRow = (lane & 15);
            const int bRow = (lane & 7) + ((lane >> 4) << 3);

            uint32_t AH[4][4], BH[4][2];
            #pragma unroll
            for (int mt = 0; mt < 4; ++mt) {
                uint32_t ad = aBase + (uint32_t)(wm * 64 + mt * 16 + aRow) * RS + aCol;
                LDSM_X4(AH[mt][0], AH[mt][1], AH[mt][2], AH[mt][3], ad);
            }
            #pragma unroll
            for (int p = 0; p < 2; ++p) {
                uint32_t bd = bBase + (uint32_t)(wn * 32 + p * 16 + bRow) * RS + bCol;
                LDSM_X4(BH[2*p][0], BH[2*p][1], BH[2*p+1][0], BH[2*p+1][1], bd);
            }
            #pragma unroll
            for (int mt = 0; mt < 4; ++mt)
                #pragma unroll
                for (int nt = 0; nt < 4; ++nt)
                    mma_bf16(acc[mt][nt], AH[mt][0], AH[mt][1], AH[mt][2], AH[mt][3],
                             BH[nt][0], BH[nt][1]);

            {   // hi(A) * lo(B)
                uint32_t BL[4][2];
                #pragma unroll
                for (int p = 0; p < 2; ++p) {
                    uint32_t bd = bBase + MATB + (uint32_t)(wn * 32 + p * 16 + bRow) * RS + bCol;
                    LDSM_X4(BL[2*p][0], BL[2*p][1], BL[2*p+1][0], BL[2*p+1][1], bd);
                }
                #pragma unroll
                for (int mt = 0; mt < 4; ++mt)
                    #pragma unroll
                    for (int nt = 0; nt < 4; ++nt)
                        mma_bf16(acc[mt][nt], AH[mt][0], AH[mt][1], AH[mt][2], AH[mt][3],
                                 BL[nt][0], BL[nt][1]);
            }
            {   // lo(A) * hi(B)
                uint32_t AL[4][4];
                #pragma unroll
                for (int mt = 0; mt < 4; ++mt) {
                    uint32_t ad = aBase + MATB + (uint32_t)(wm * 64 + mt * 16 + aRow) * RS + aCol;
                    LDSM_X4(AL[mt][0], AL[mt][1], AL[mt][2], AL[mt][3], ad);
                }
                #pragma unroll
                for (int mt = 0; mt < 4; ++mt)
                    #pragma unroll
                    for (int nt = 0; nt < 4; ++nt)
                        mma_bf16(acc[mt][nt], AL[mt][0], AL[mt][1], AL[mt][2], AL[mt][3],
                                 BH[nt][0], BH[nt][1]);
            }
        }
        __syncthreads();
    }

    // ---------------- epilogue ----------------
    #pragma unroll
    for (int mt = 0; mt < 4; ++mt) {
        #pragma unroll
        for (int nt = 0; nt < 4; ++nt) {
            int row0 = ib + wm * 64 + mt * 16 + r;
            int col  = jb + wn * 32 + nt * 8 + 2 * q;
            float2 b2 = make_float2(0.f, 0.f);
            if (FUSE) b2 = *(const float2*)&bias[col];
            #pragma unroll
            for (int hf = 0; hf < 2; ++hf) {
                int row = row0 + 8 * hf;
                if (row >= M) continue;
                float o0 = acc[mt][nt][2 * hf + 0];
                float o1 = acc[mt][nt][2 * hf + 1];
                if (FUSE) {
                    float2 rv = *(const float2*)&res[(size_t)row * Ncols + col];
                    o0 = rv.x + fmaxf(o0 + b2.x, 0.f);
                    o1 = rv.y + fmaxf(o1 + b2.y, 0.f);
                }
                *(float2*)&C[(size_t)row * Ncols + col] = make_float2(o0, o1);
                if (SPLIT) {
                    uint32_t hi, lo;
                    split2(o0, o1, hi, lo);
                    *(uint32_t*)(Chi + (size_t)row * Ncols + col) = hi;
                    *(uint32_t*)(Clo + (size_t)row * Ncols + col) = lo;
                }
            }
        }
    }
}

// ---------------- row L2-normalize (128 cols): one warp per row --------------
__global__ void norm_k(float* __restrict__ out) {
    int row = blockIdx.x * 8 + threadIdx.y;  // blockDim (32,8)
    if (row >= NN) return;
    float4* p = (float4*)out + (size_t)row * 32 + threadIdx.x;
    float4 v = *p;
    float s = v.x * v.x + v.y * v.y + v.z * v.z + v.w * v.w;
    #pragma unroll
    for (int off = 16; off > 0; off >>= 1)
        s += __shfl_xor_sync(0xFFFFFFFFu, s, off);
    float r = rsqrtf(s);
    v.x *= r; v.y *= r; v.z *= r; v.w *= r;
    *p = v;
}

// ---------------- launch -----------------------------------------------------
extern "C" void kernel_launch(void* const* d_in, const int* in_sizes, int n_in,
                              void* d_out, int out_size) {
    const float* x     = (const float*)d_in[0];
    const int*   esrc  = (const int*)  d_in[1];
    const int*   edst  = (const int*)  d_in[2];
    const float* ew    = (const float*)d_in[3];
    const float* W_emb = (const float*)d_in[4];
    const float* W_gc1 = (const float*)d_in[5];
    const float* b_gc1 = (const float*)d_in[6];
    const float* W_gc2 = (const float*)d_in[7];
    const float* b_gc2 = (const float*)d_in[8];
    const float* W_fc  = (const float*)d_in[9];
    float* out = (float*)d_out;

    float *h, *h2;
    bf16 *xh, *xl, *hh, *hl, *h2h, *h2l, *ahh, *ahl;
    bf16 *weh, *wel, *w1h, *w1l, *w2h, *w2l, *wfh, *wfl;
    cudaGetSymbolAddress((void**)&h,   g_h);
    cudaGetSymbolAddress((void**)&h2,  g_h2);
    cudaGetSymbolAddress((void**)&xh,  g_xh);  cudaGetSymbolAddress((void**)&xl,  g_xl);
    cudaGetSymbolAddress((void**)&hh,  g_hh);  cudaGetSymbolAddress((void**)&hl,  g_hl);
    cudaGetSymbolAddress((void**)&h2h, g_h2h); cudaGetSymbolAddress((void**)&h2l, g_h2l);
    cudaGetSymbolAddress((void**)&ahh, g_ahh); cudaGetSymbolAddress((void**)&ahl, g_ahl);
    cudaGetSymbolAddress((void**)&weh, g_weh); cudaGetSymbolAddress((void**)&wel, g_wel);
    cudaGetSymbolAddress((void**)&w1h, g_w1h); cudaGetSymbolAddress((void**)&w1l, g_w1l);
    cudaGetSymbolAddress((void**)&w2h, g_w2h); cudaGetSymbolAddress((void**)&w2l, g_w2l);
    cudaGetSymbolAddress((void**)&wfh, g_wfh); cudaGetSymbolAddress((void**)&wfl, g_wfl);

    const int SMEM = 2 * STGB;  // 81920
    cudaFuncSetAttribute(mma_gemm_k<true,  true >, cudaFuncAttributeMaxDynamicSharedMemorySize, SMEM);
    cudaFuncSetAttribute(mma_gemm_k<false, true >, cudaFuncAttributeMaxDynamicSharedMemorySize, SMEM);
    cudaFuncSetAttribute(mma_gemm_k<false, false>, cudaFuncAttributeMaxDynamicSharedMemorySize, SMEM);

    const int MT = (NN + 127) / 128;   // 157
    dim3 gHid(MT, HIDF / 128);         // 157 x 2
    dim3 gOut(MT, OUTF / 128);         // 157 x 1
    dim3 gblk(5000), gthr(64, 4);

    // index-3 launch = emb GEMM (ncu capture slot)
    split_k<<<(NN * INF / 4 + 255) / 256, 256>>>(x, xh, xl, NN * INF);                 // 0
    split_k<<<(HIDF * INF / 4 + 255) / 256, 256>>>(W_emb, weh, wel, HIDF * INF);       // 1
    zero_cnt_k<<<(NN + 255) / 256, 256>>>();                                           // 2
    mma_gemm_k<false, true><<<gHid, 256, SMEM>>>(                                      // 3 (ncu)
        xh, xl, nullptr, nullptr, INF, weh, wel,
        nullptr, nullptr, h, hh, hl, NN, HIDF);
    count_k  <<<(EE + 255) / 256, 256>>>(edst);                                        // 4
    scan_k   <<<1, 1024>>>();                                                          // 5
    scatter_k<<<(EE + 255) / 256, 256>>>(esrc, edst, ew);                              // 6
    split3_k<<<((2 * HIDF * 2 * HIDF + OUTF * HIDF) / 4 + 255) / 256, 256>>>(          // 7
        W_gc1, w1h, w1l, HIDF * 2 * HIDF,
        W_gc2, w2h, w2l, HIDF * 2 * HIDF,
        W_fc,  wfh, wfl, OUTF * HIDF);

    // Ah = A @ h ; h2 = h + relu([h|Ah] @ W_gc1^T + b1)
    gather_k<<<gblk, gthr>>>(h, ahh, ahl);                                             // 8
    mma_gemm_k<true, true><<<gHid, 256, SMEM>>>(                                       // 9
        hh, hl, ahh, ahl, 2 * HIDF, w1h, w1l,
        b_gc1, h, h2, h2h, h2l, NN, HIDF);
    // Ah = A @ h2 ; h = h2 + relu([h2|Ah] @ W_gc2^T + b2)
    gather_k<<<gblk, gthr>>>(h2, ahh, ahl);                                            // 10
    mma_gemm_k<true, true><<<gHid, 256, SMEM>>>(                                       // 11
        h2h, h2l, ahh, ahl, 2 * HIDF, w2h, w2l,
        b_gc2, h2, h, hh, hl, NN, HIDF);
    // out = h @ W_fc^T ; rows L2-normalized
    mma_gemm_k<false, false><<<gOut, 256, SMEM>>>(                                     // 12
        hh, hl, nullptr, nullptr, HIDF, wfh, wfl,
        nullptr, nullptr, out, nullptr, nullptr, NN, OUTF);
    norm_k<<<(NN + 7) / 8, dim3(32, 8)>>>(out);                                        // 13
}

// round 7
// speedup vs baseline: 2.0377x; 1.0080x over previous
#include <cuda_runtime.h>
#include <cuda_bf16.h>
#include <cstdint>

#define NN   20000
#define EE   320000
#define INF  256
#define HIDF 256
#define OUTF 128
#define RS   80      // padded smem row stride (bytes): conflict-free ldmatrix
#define MATB (128 * RS)          // 10240 bytes per matrix tile
#define STGB (4 * MATB)          // 40960 bytes per stage (AH, AL, BH, BL)

typedef __nv_bfloat16 bf16;

// ---------------- scratch (device globals; no allocation allowed) ------------
__device__ float g_h [NN * HIDF];
__device__ float g_h2[NN * HIDF];
__device__ bf16  g_xh [NN * HIDF], g_xl [NN * HIDF];
__device__ bf16  g_hh [NN * HIDF], g_hl [NN * HIDF];
__device__ bf16  g_h2h[NN * HIDF], g_h2l[NN * HIDF];
__device__ bf16  g_ahh[NN * HIDF], g_ahl[NN * HIDF];
__device__ bf16  g_weh[HIDF * INF],      g_wel[HIDF * INF];
__device__ bf16  g_w1h[HIDF * 2 * HIDF], g_w1l[HIDF * 2 * HIDF];
__device__ bf16  g_w2h[HIDF * 2 * HIDF], g_w2l[HIDF * 2 * HIDF];
__device__ bf16  g_wfh[OUTF * HIDF],     g_wfl[OUTF * HIDF];
__device__ int   g_cnt[NN];
__device__ int   g_off[NN + 1];
__device__ int   g_fill[NN];
__device__ int   g_csr_src[EE];
__device__ float g_csr_w[EE];

// ---------------- helpers ----------------------------------------------------
__device__ __forceinline__ uint32_t smem_u32(const void* p) {
    uint32_t a;
    asm("{ .reg .u64 t; cvta.to.shared.u64 t, %1; cvt.u32.u64 %0, t; }"
        : "=r"(a) : "l"(p));
    return a;
}

__device__ __forceinline__ void split2(float x, float y, uint32_t& hi, uint32_t& lo) {
    bf16 hx = __float2bfloat16_rn(x);
    bf16 hy = __float2bfloat16_rn(y);
    float rx = x - __bfloat162float(hx);
    float ry = y - __bfloat162float(hy);
    __nv_bfloat162 H; H.x = hx; H.y = hy;
    __nv_bfloat162 L = __floats2bfloat162_rn(rx, ry);
    hi = *reinterpret_cast<uint32_t*>(&H);
    lo = *reinterpret_cast<uint32_t*>(&L);
}

__device__ __forceinline__ void mma_bf16(float c[4],
                                         uint32_t a0, uint32_t a1, uint32_t a2, uint32_t a3,
                                         uint32_t b0, uint32_t b1) {
    asm volatile(
        "mma.sync.aligned.m16n8k16.row.col.f32.bf16.bf16.f32 "
        "{%0,%1,%2,%3}, {%4,%5,%6,%7}, {%8,%9}, {%0,%1,%2,%3};"
        : "+f"(c[0]), "+f"(c[1]), "+f"(c[2]), "+f"(c[3])
        : "r"(a0), "r"(a1), "r"(a2), "r"(a3), "r"(b0), "r"(b1));
}

#define LDSM_X4(r0, r1, r2, r3, addr) \
    asm volatile("ldmatrix.sync.aligned.m8n8.x4.shared.b16 {%0,%1,%2,%3}, [%4];" \
                 : "=r"(r0), "=r"(r1), "=r"(r2), "=r"(r3) : "r"(addr))

#define CP_ASYNC16(dst, src, sz) \
    asm volatile("cp.async.cg.shared.global [%0], [%1], 16, %2;" \
                 :: "r"(dst), "l"(src), "r"(sz) : "memory")

#define CP_COMMIT() asm volatile("cp.async.commit_group;" ::: "memory")

// ---------------- fp32 -> bf16 hi/lo splits ----------------------------------
__global__ void split_k(const float* __restrict__ s, bf16* __restrict__ hi,
                        bf16* __restrict__ lo, int n) {
    int i = (blockIdx.x * blockDim.x + threadIdx.x) * 4;
    if (i >= n) return;
    float4 v = *(const float4*)(s + i);
    uint32_t h0, l0, h1, l1;
    split2(v.x, v.y, h0, l0);
    split2(v.z, v.w, h1, l1);
    *(uint2*)(hi + i) = make_uint2(h0, h1);
    *(uint2*)(lo + i) = make_uint2(l0, l1);
}

__global__ void split3_k(const float* __restrict__ s0, bf16* __restrict__ h0, bf16* __restrict__ l0, int n0,
                         const float* __restrict__ s1, bf16* __restrict__ h1, bf16* __restrict__ l1, int n1,
                         const float* __restrict__ s2, bf16* __restrict__ h2, bf16* __restrict__ l2, int n2) {
    int i = (blockIdx.x * blockDim.x + threadIdx.x) * 4;
    const float* s; bf16 *hh, *ll;
    if (i < n0)               { s = s0 + i;             hh = h0 + i;             ll = l0 + i; }
    else if (i < n0 + n1)     { s = s1 + (i - n0);      hh = h1 + (i - n0);      ll = l1 + (i - n0); }
    else if (i < n0 + n1 + n2){ s = s2 + (i - n0 - n1); hh = h2 + (i - n0 - n1); ll = l2 + (i - n0 - n1); }
    else return;
    float4 v = *(const float4*)s;
    uint32_t a, b, c, d;
    split2(v.x, v.y, a, b);
    split2(v.z, v.w, c, d);
    *(uint2*)hh = make_uint2(a, c);
    *(uint2*)ll = make_uint2(b, d);
}

// ---------------- CSR build --------------------------------------------------
__global__ void zero_cnt_k() {
    int i = blockIdx.x * blockDim.x + threadIdx.x;
    if (i < NN) g_cnt[i] = 0;
}

__global__ void count_k(const int* __restrict__ dst) {
    int e = blockIdx.x * blockDim.x + threadIdx.x;
    if (e < EE) atomicAdd(&g_cnt[dst[e]], 1);
}

__global__ void scan_k() {
    __shared__ int s[1024];
    __shared__ int carry;
    int tid = threadIdx.x;
    if (tid == 0) carry = 0;
    __syncthreads();
    for (int base = 0; base < NN; base += 1024) {
        int i = base + tid;
        int v = (i < NN) ? g_cnt[i] : 0;
        s[tid] = v;
        __syncthreads();
        #pragma unroll
        for (int off = 1; off < 1024; off <<= 1) {
            int t = 0;
            if (tid >= off) t = s[tid - off];
            __syncthreads();
            if (tid >= off) s[tid] += t;
            __syncthreads();
        }
        int incl  = s[tid];
        int cbase = carry;
        __syncthreads();
        if (i < NN) {
            int ex = cbase + incl - v;
            g_off[i]  = ex;
            g_fill[i] = ex;
        }
        __syncthreads();
        if (tid == 0) carry = cbase + s[1023];
        __syncthreads();
    }
    if (tid == 0) g_off[NN] = carry;
}

__global__ void scatter_k(const int* __restrict__ src, const int* __restrict__ dst,
                          const float* __restrict__ w) {
    int e = blockIdx.x * blockDim.x + threadIdx.x;
    if (e < EE) {
        int d = dst[e];
        int p = atomicAdd(&g_fill[d], 1);
        g_csr_src[p] = src[e];
        g_csr_w[p]   = w[e];
    }
}

// ---------------- adj_mul gather, 4-way unrolled (MLP>=4) --------------------
__global__ void gather_k(const float* __restrict__ h,
                         bf16* __restrict__ ahh, bf16* __restrict__ ahl) {
    int node = blockIdx.x * 4 + threadIdx.y;
    if (node >= NN) return;
    int beg = g_off[node], end = g_off[node + 1];
    const float4* __restrict__ H = (const float4*)h;
    int t = threadIdx.x;  // 0..63
    float ax = 0.f, ay = 0.f, az = 0.f, aw = 0.f;

    int k = beg;
    for (; k + 4 <= end; k += 4) {
        int   s0 = g_csr_src[k],     s1 = g_csr_src[k + 1];
        int   s2 = g_csr_src[k + 2], s3 = g_csr_src[k + 3];
        float w0 = g_csr_w[k],       w1 = g_csr_w[k + 1];
        float w2 = g_csr_w[k + 2],   w3 = g_csr_w[k + 3];
        float4 v0 = H[(size_t)s0 * 64 + t];
        float4 v1 = H[(size_t)s1 * 64 + t];
        float4 v2 = H[(size_t)s2 * 64 + t];
        float4 v3 = H[(size_t)s3 * 64 + t];
        ax = fmaf(v0.x, w0, fmaf(v1.x, w1, fmaf(v2.x, w2, fmaf(v3.x, w3, ax))));
        ay = fmaf(v0.y, w0, fmaf(v1.y, w1, fmaf(v2.y, w2, fmaf(v3.y, w3, ay))));
        az = fmaf(v0.z, w0, fmaf(v1.z, w1, fmaf(v2.z, w2, fmaf(v3.z, w3, az))));
        aw = fmaf(v0.w, w0, fmaf(v1.w, w1, fmaf(v2.w, w2, fmaf(v3.w, w3, aw))));
    }
    for (; k < end; ++k) {
        int s = g_csr_src[k];
        float w = g_csr_w[k];
        float4 v = H[(size_t)s * 64 + t];
        ax = fmaf(v.x, w, ax); ay = fmaf(v.y, w, ay);
        az = fmaf(v.z, w, az); aw = fmaf(v.w, w, aw);
    }
    uint32_t h0, l0, h1, l1;
    split2(ax, ay, h0, l0);
    split2(az, aw, h1, l1);
    ((uint2*)ahh)[(size_t)node * 64 + t] = make_uint2(h0, h1);
    ((uint2*)ahl)[(size_t)node * 64 + t] = make_uint2(l0, l1);
}

// ---------------- bf16x3 tensor-core GEMM: cp.async + ldmatrix ---------------
// C = epi( [A1|A2] @ W^T ). A arrays row stride 256 (K1 = 256 always).
// Block 128x128, 8 warps (2x4), warp 64x32. K staged 32-deep, double-buffered.
// smem per stage: AH | AL | BH | BL, 128 rows x 64B data padded to RS=80B.
template<bool FUSE, bool SPLIT>
__global__ __launch_bounds__(256, 2)
void mma_gemm_k(const bf16* __restrict__ a1h, const bf16* __restrict__ a1l,
                const bf16* __restrict__ a2h, const bf16* __restrict__ a2l,
                int Ktot,
                const bf16* __restrict__ wh, const bf16* __restrict__ wl,
                const float* __restrict__ bias, const float* __restrict__ res,
                float* __restrict__ C, bf16* __restrict__ Chi, bf16* __restrict__ Clo,
                int M, int Ncols)
{
    extern __shared__ __align__(16) char smem[];
    const uint32_t sb = smem_u32(smem);
    const int tid  = threadIdx.x;
    const int lane = tid & 31, wid = tid >> 5;
    const int wm = wid >> 2, wn = wid & 3;
    const int r = lane >> 2, q = lane & 3;
    const int ib = blockIdx.x * 128, jb = blockIdx.y * 128;
    const int S = Ktot / 32;

    float acc[4][4][4];
    #pragma unroll
    for (int a = 0; a < 4; ++a)
        #pragma unroll
        for (int b = 0; b < 4; ++b)
            #pragma unroll
            for (int c = 0; c < 4; ++c) acc[a][b][c] = 0.f;

    // async fill of stage s into buffer s&1 (8 x 16B per thread)
    auto fill = [&](int s) {
        const int k0 = s * 32;
        const uint32_t stb = sb + (s & 1) * STGB;
        #pragma unroll
        for (int i = 0; i < 8; ++i) {
            int g = i * 256 + tid;
            int mat = g >> 9, idx = g & 511;
            int row = idx >> 2, c = idx & 3;
            uint32_t dst = stb + mat * MATB + row * RS + c * 16;
            const bf16* src;
            int sz = 16;
            if (mat < 2) {
                const bf16* a = (k0 < 256) ? (mat == 0 ? a1h : a1l)
                                           : (mat == 0 ? a2h : a2l);
                int gr = ib + row;
                if (gr >= M) { gr = 0; sz = 0; }
                src = a + (size_t)gr * 256 + (k0 & 255) + c * 8;
            } else {
                src = ((mat == 2) ? wh : wl) + (size_t)(jb + row) * Ktot + k0 + c * 8;
            }
            CP_ASYNC16(dst, src, sz);
        }
        CP_COMMIT();
    };

    fill(0);

    for (int s = 0; s < S; ++s) {
        if (s + 1 < S) {
            fill(s + 1);
            asm volatile("cp.async.wait_group 1;" ::: "memory");
        } else {
            asm volatile("cp.async.wait_group 0;" ::: "memory");
        }
        __syncthreads();

        const uint32_t stb = sb + (s & 1) * STGB;
        const uint32_t aBase = stb;
        const uint32_t bBase = stb + 2 * MATB;

        #pragma unroll
        for (int ks = 0; ks < 2; ++ks) {
            const uint32_t aCol = ks * 32 + ((lane >> 4) << 4);
            const uint32_t bCol = ks * 32 + (((lane >> 3) & 1) << 4);
            const int aRow = (lane & 15);
            const int bRow = (lane & 7) + ((lane >> 4) << 3);

            uint32_t AH[4][4], BH[4][2];
            #pragma unroll
            for (int mt = 0; mt < 4; ++mt) {
                uint32_t ad = aBase + (uint32_t)(wm * 64 + mt * 16 + aRow) * RS + aCol;
                LDSM_X4(AH[mt][0], AH[mt][1], AH[mt][2], AH[mt][3], ad);
            }
            #pragma unroll
            for (int p = 0; p < 2; ++p) {
                uint32_t bd = bBase + (uint32_t)(wn * 32 + p * 16 + bRow) * RS + bCol;
                LDSM_X4(BH[2*p][0], BH[2*p][1], BH[2*p+1][0], BH[2*p+1][1], bd);
            }
            #pragma unroll
            for (int mt = 0; mt < 4; ++mt)
                #pragma unroll
                for (int nt = 0; nt < 4; ++nt)
                    mma_bf16(acc[mt][nt], AH[mt][0], AH[mt][1], AH[mt][2], AH[mt][3],
                             BH[nt][0], BH[nt][1]);

            {   // hi(A) * lo(B)
                uint32_t BL[4][2];
                #pragma unroll
                for (int p = 0; p < 2; ++p) {
                    uint32_t bd = bBase + MATB + (uint32_t)(wn * 32 + p * 16 + bRow) * RS + bCol;
                    LDSM_X4(BL[2*p][0], BL[2*p][1], BL[2*p+1][0], BL[2*p+1][1], bd);
                }
                #pragma unroll
                for (int mt = 0; mt < 4; ++mt)
                    #pragma unroll
                    for (int nt = 0; nt < 4; ++nt)
                        mma_bf16(acc[mt][nt], AH[mt][0], AH[mt][1], AH[mt][2], AH[mt][3],
                                 BL[nt][0], BL[nt][1]);
            }
            {   // lo(A) * hi(B)
                uint32_t AL[4][4];
                #pragma unroll
                for (int mt = 0; mt < 4; ++mt) {
                    uint32_t ad = aBase + MATB + (uint32_t)(wm * 64 + mt * 16 + aRow) * RS + aCol;
                    LDSM_X4(AL[mt][0], AL[mt][1], AL[mt][2], AL[mt][3], ad);
                }
                #pragma unroll
                for (int mt = 0; mt < 4; ++mt)
                    #pragma unroll
                    for (int nt = 0; nt < 4; ++nt)
                        mma_bf16(acc[mt][nt], AL[mt][0], AL[mt][1], AL[mt][2], AL[mt][3],
                                 BH[nt][0], BH[nt][1]);
            }
        }
        __syncthreads();
    }

    // ---------------- epilogue ----------------
    #pragma unroll
    for (int mt = 0; mt < 4; ++mt) {
        #pragma unroll
        for (int nt = 0; nt < 4; ++nt) {
            int row0 = ib + wm * 64 + mt * 16 + r;
            int col  = jb + wn * 32 + nt * 8 + 2 * q;
            float2 b2 = make_float2(0.f, 0.f);
            if (FUSE) b2 = *(const float2*)&bias[col];
            #pragma unroll
            for (int hf = 0; hf < 2; ++hf) {
                int row = row0 + 8 * hf;
                if (row >= M) continue;
                float o0 = acc[mt][nt][2 * hf + 0];
                float o1 = acc[mt][nt][2 * hf + 1];
                if (FUSE) {
                    float2 rv = *(const float2*)&res[(size_t)row * Ncols + col];
                    o0 = rv.x + fmaxf(o0 + b2.x, 0.f);
                    o1 = rv.y + fmaxf(o1 + b2.y, 0.f);
                }
                *(float2*)&C[(size_t)row * Ncols + col] = make_float2(o0, o1);
                if (SPLIT) {
                    uint32_t hi, lo;
                    split2(o0, o1, hi, lo);
                    *(uint32_t*)(Chi + (size_t)row * Ncols + col) = hi;
                    *(uint32_t*)(Clo + (size_t)row * Ncols + col) = lo;
                }
            }
        }
    }
}

// ---------------- row L2-normalize (128 cols): one warp per row --------------
__global__ void norm_k(float* __restrict__ out) {
    int row = blockIdx.x * 8 + threadIdx.y;  // blockDim (32,8)
    if (row >= NN) return;
    float4* p = (float4*)out + (size_t)row * 32 + threadIdx.x;
    float4 v = *p;
    float s = v.x * v.x + v.y * v.y + v.z * v.z + v.w * v.w;
    #pragma unroll
    for (int off = 16; off > 0; off >>= 1)
        s += __shfl_xor_sync(0xFFFFFFFFu, s, off);
    float r = rsqrtf(s);
    v.x *= r; v.y *= r; v.z *= r; v.w *= r;
    *p = v;
}

// ---------------- launch -----------------------------------------------------
extern "C" void kernel_launch(void* const* d_in, const int* in_sizes, int n_in,
                              void* d_out, int out_size) {
    const float* x     = (const float*)d_in[0];
    const int*   esrc  = (const int*)  d_in[1];
    const int*   edst  = (const int*)  d_in[2];
    const float* ew    = (const float*)d_in[3];
    const float* W_emb = (const float*)d_in[4];
    const float* W_gc1 = (const float*)d_in[5];
    const float* b_gc1 = (const float*)d_in[6];
    const float* W_gc2 = (const float*)d_in[7];
    const float* b_gc2 = (const float*)d_in[8];
    const float* W_fc  = (const float*)d_in[9];
    float* out = (float*)d_out;

    float *h, *h2;
    bf16 *xh, *xl, *hh, *hl, *h2h, *h2l, *ahh, *ahl;
    bf16 *weh, *wel, *w1h, *w1l, *w2h, *w2l, *wfh, *wfl;
    cudaGetSymbolAddress((void**)&h,   g_h);
    cudaGetSymbolAddress((void**)&h2,  g_h2);
    cudaGetSymbolAddress((void**)&xh,  g_xh);  cudaGetSymbolAddress((void**)&xl,  g_xl);
    cudaGetSymbolAddress((void**)&hh,  g_hh);  cudaGetSymbolAddress((void**)&hl,  g_hl);
    cudaGetSymbolAddress((void**)&h2h, g_h2h); cudaGetSymbolAddress((void**)&h2l, g_h2l);
    cudaGetSymbolAddress((void**)&ahh, g_ahh); cudaGetSymbolAddress((void**)&ahl, g_ahl);
    cudaGetSymbolAddress((void**)&weh, g_weh); cudaGetSymbolAddress((void**)&wel, g_wel);
    cudaGetSymbolAddress((void**)&w1h, g_w1h); cudaGetSymbolAddress((void**)&w1l, g_w1l);
    cudaGetSymbolAddress((void**)&w2h, g_w2h); cudaGetSymbolAddress((void**)&w2l, g_w2l);
    cudaGetSymbolAddress((void**)&wfh, g_wfh); cudaGetSymbolAddress((void**)&wfl, g_wfl);

    const int SMEM = 2 * STGB;  // 81920
    cudaFuncSetAttribute(mma_gemm_k<true,  true >, cudaFuncAttributeMaxDynamicSharedMemorySize, SMEM);
    cudaFuncSetAttribute(mma_gemm_k<false, true >, cudaFuncAttributeMaxDynamicSharedMemorySize, SMEM);
    cudaFuncSetAttribute(mma_gemm_k<false, false>, cudaFuncAttributeMaxDynamicSharedMemorySize, SMEM);

    const int MT = (NN + 127) / 128;   // 157
    dim3 gHid(MT, HIDF / 128);         // 157 x 2
    dim3 gOut(MT, OUTF / 128);         // 157 x 1
    dim3 gblk(5000), gthr(64, 4);

    // index-3 launch = emb GEMM (ncu capture slot)
    split_k<<<(NN * INF / 4 + 255) / 256, 256>>>(x, xh, xl, NN * INF);                 // 0
    split_k<<<(HIDF * INF / 4 + 255) / 256, 256>>>(W_emb, weh, wel, HIDF * INF);       // 1
    zero_cnt_k<<<(NN + 255) / 256, 256>>>();                                           // 2
    mma_gemm_k<false, true><<<gHid, 256, SMEM>>>(                                      // 3 (ncu)
        xh, xl, nullptr, nullptr, INF, weh, wel,
        nullptr, nullptr, h, hh, hl, NN, HIDF);
    count_k  <<<(EE + 255) / 256, 256>>>(edst);                                        // 4
    scan_k   <<<1, 1024>>>();                                                          // 5
    scatter_k<<<(EE + 255) / 256, 256>>>(esrc, edst, ew);                              // 6
    split3_k<<<((2 * HIDF * 2 * HIDF + OUTF * HIDF) / 4 + 255) / 256, 256>>>(          // 7
        W_gc1, w1h, w1l, HIDF * 2 * HIDF,
        W_gc2, w2h, w2l, HIDF * 2 * HIDF,
        W_fc,  wfh, wfl, OUTF * HIDF);

    // Ah = A @ h ; h2 = h + relu([h|Ah] @ W_gc1^T + b1)
    gather_k<<<gblk, gthr>>>(h, ahh, ahl);                                             // 8
    mma_gemm_k<true, true><<<gHid, 256, SMEM>>>(                                       // 9
        hh, hl, ahh, ahl, 2 * HIDF, w1h, w1l,
        b_gc1, h, h2, h2h, h2l, NN, HIDF);
    // Ah = A @ h2 ; h = h2 + relu([h2|Ah] @ W_gc2^T + b2)
    gather_k<<<gblk, gthr>>>(h2, ahh, ahl);                                            // 10
    mma_gemm_k<true, true><<<gHid, 256, SMEM>>>(                                       // 11
        h2h, h2l, ahh, ahl, 2 * HIDF, w2h, w2l,
        b_gc2, h2, h, hh, hl, NN, HIDF);
    // out = h @ W_fc^T ; rows L2-normalized
    mma_gemm_k<false, false><<<gOut, 256, SMEM>>>(                                     // 12
        hh, hl, nullptr, nullptr, HIDF, wfh, wfl,
        nullptr, nullptr, out, nullptr, nullptr, NN, OUTF);
    norm_k<<<(NN + 7) / 8, dim3(32, 8)>>>(out);                                        // 13
}

// round 8
// speedup vs baseline: 2.2085x; 1.0838x over previous
#include <cuda_runtime.h>
#include <cuda_bf16.h>
#include <cstdint>

#define NN   20000
#define EE   320000
#define INF  256
#define HIDF 256
#define OUTF 128
#define MATB 8192                // 128 rows x 64B, XOR-swizzled
#define STGB (4 * MATB)          // 32768 per stage (AH, AL, BH, BL)
#define NSTG 3                   // ring depth

typedef __nv_bfloat16 bf16;

// ---------------- scratch (device globals; no allocation allowed) ------------
__device__ float g_h [NN * HIDF];
__device__ float g_h2[NN * HIDF];
__device__ bf16  g_xh [NN * HIDF], g_xl [NN * HIDF];
__device__ bf16  g_hh [NN * HIDF], g_hl [NN * HIDF];
__device__ bf16  g_h2h[NN * HIDF], g_h2l[NN * HIDF];
__device__ bf16  g_ahh[NN * HIDF], g_ahl[NN * HIDF];
__device__ bf16  g_weh[HIDF * INF],      g_wel[HIDF * INF];
__device__ bf16  g_w1h[HIDF * 2 * HIDF], g_w1l[HIDF * 2 * HIDF];
__device__ bf16  g_w2h[HIDF * 2 * HIDF], g_w2l[HIDF * 2 * HIDF];
__device__ bf16  g_wfh[OUTF * HIDF],     g_wfl[OUTF * HIDF];
__device__ int   g_cnt[NN];
__device__ int   g_off[NN + 1];
__device__ int   g_fill[NN];
__device__ int   g_csr_src[EE];
__device__ float g_csr_w[EE];

// ---------------- helpers ----------------------------------------------------
__device__ __forceinline__ uint32_t smem_u32(const void* p) {
    uint32_t a;
    asm("{ .reg .u64 t; cvta.to.shared.u64 t, %1; cvt.u32.u64 %0, t; }"
        : "=r"(a) : "l"(p));
    return a;
}

__device__ __forceinline__ void split2(float x, float y, uint32_t& hi, uint32_t& lo) {
    bf16 hx = __float2bfloat16_rn(x);
    bf16 hy = __float2bfloat16_rn(y);
    float rx = x - __bfloat162float(hx);
    float ry = y - __bfloat162float(hy);
    __nv_bfloat162 H; H.x = hx; H.y = hy;
    __nv_bfloat162 L = __floats2bfloat162_rn(rx, ry);
    hi = *reinterpret_cast<uint32_t*>(&H);
    lo = *reinterpret_cast<uint32_t*>(&L);
}

__device__ __forceinline__ void mma_bf16(float c[4],
                                         uint32_t a0, uint32_t a1, uint32_t a2, uint32_t a3,
                                         uint32_t b0, uint32_t b1) {
    asm volatile(
        "mma.sync.aligned.m16n8k16.row.col.f32.bf16.bf16.f32 "
        "{%0,%1,%2,%3}, {%4,%5,%6,%7}, {%8,%9}, {%0,%1,%2,%3};"
        : "+f"(c[0]), "+f"(c[1]), "+f"(c[2]), "+f"(c[3])
        : "r"(a0), "r"(a1), "r"(a2), "r"(a3), "r"(b0), "r"(b1));
}

#define LDSM_X4(r0, r1, r2, r3, addr) \
    asm volatile("ldmatrix.sync.aligned.m8n8.x4.shared.b16 {%0,%1,%2,%3}, [%4];" \
                 : "=r"(r0), "=r"(r1), "=r"(r2), "=r"(r3) : "r"(addr))

#define CP_ASYNC16(dst, src, sz) \
    asm volatile("cp.async.cg.shared.global [%0], [%1], 16, %2;" \
                 :: "r"(dst), "l"(src), "r"(sz) : "memory")

#define CP_COMMIT() asm volatile("cp.async.commit_group;" ::: "memory")

// XOR-swizzled offset of 16B chunk c in row r (row stride 64B data, no pad)
__device__ __forceinline__ uint32_t swz(int row, int chunk) {
    return (uint32_t)(row * 64 + ((chunk ^ ((row >> 1) & 3)) << 4));
}

// ---------------- fp32 -> bf16 hi/lo splits ----------------------------------
__global__ void split_k(const float* __restrict__ s, bf16* __restrict__ hi,
                        bf16* __restrict__ lo, int n) {
    int i = (blockIdx.x * blockDim.x + threadIdx.x) * 4;
    if (i >= n) return;
    float4 v = *(const float4*)(s + i);
    uint32_t h0, l0, h1, l1;
    split2(v.x, v.y, h0, l0);
    split2(v.z, v.w, h1, l1);
    *(uint2*)(hi + i) = make_uint2(h0, h1);
    *(uint2*)(lo + i) = make_uint2(l0, l1);
}

__global__ void split3_k(const float* __restrict__ s0, bf16* __restrict__ h0, bf16* __restrict__ l0, int n0,
                         const float* __restrict__ s1, bf16* __restrict__ h1, bf16* __restrict__ l1, int n1,
                         const float* __restrict__ s2, bf16* __restrict__ h2, bf16* __restrict__ l2, int n2) {
    int i = (blockIdx.x * blockDim.x + threadIdx.x) * 4;
    const float* s; bf16 *hh, *ll;
    if (i < n0)               { s = s0 + i;             hh = h0 + i;             ll = l0 + i; }
    else if (i < n0 + n1)     { s = s1 + (i - n0);      hh = h1 + (i - n0);      ll = l1 + (i - n0); }
    else if (i < n0 + n1 + n2){ s = s2 + (i - n0 - n1); hh = h2 + (i - n0 - n1); ll = l2 + (i - n0 - n1); }
    else return;
    float4 v = *(const float4*)s;
    uint32_t a, b, c, d;
    split2(v.x, v.y, a, b);
    split2(v.z, v.w, c, d);
    *(uint2*)hh = make_uint2(a, c);
    *(uint2*)ll = make_uint2(b, d);
}

// ---------------- CSR build --------------------------------------------------
__global__ void zero_cnt_k() {
    int i = blockIdx.x * blockDim.x + threadIdx.x;
    if (i < NN) g_cnt[i] = 0;
}

__global__ void count_k(const int* __restrict__ dst) {
    int e = blockIdx.x * blockDim.x + threadIdx.x;
    if (e < EE) atomicAdd(&g_cnt[dst[e]], 1);
}

__global__ void scan_k() {
    __shared__ int s[1024];
    __shared__ int carry;
    int tid = threadIdx.x;
    if (tid == 0) carry = 0;
    __syncthreads();
    for (int base = 0; base < NN; base += 1024) {
        int i = base + tid;
        int v = (i < NN) ? g_cnt[i] : 0;
        s[tid] = v;
        __syncthreads();
        #pragma unroll
        for (int off = 1; off < 1024; off <<= 1) {
            int t = 0;
            if (tid >= off) t = s[tid - off];
            __syncthreads();
            if (tid >= off) s[tid] += t;
            __syncthreads();
        }
        int incl  = s[tid];
        int cbase = carry;
        __syncthreads();
        if (i < NN) {
            int ex = cbase + incl - v;
            g_off[i]  = ex;
            g_fill[i] = ex;
        }
        __syncthreads();
        if (tid == 0) carry = cbase + s[1023];
        __syncthreads();
    }
    if (tid == 0) g_off[NN] = carry;
}

__global__ void scatter_k(const int* __restrict__ src, const int* __restrict__ dst,
                          const float* __restrict__ w) {
    int e = blockIdx.x * blockDim.x + threadIdx.x;
    if (e < EE) {
        int d = dst[e];
        int p = atomicAdd(&g_fill[d], 1);
        g_csr_src[p] = src[e];
        g_csr_w[p]   = w[e];
    }
}

// ---------------- adj_mul gather, 4-way unrolled (MLP>=4) --------------------
__global__ void gather_k(const float* __restrict__ h,
                         bf16* __restrict__ ahh, bf16* __restrict__ ahl) {
    int node = blockIdx.x * 4 + threadIdx.y;
    if (node >= NN) return;
    int beg = g_off[node], end = g_off[node + 1];
    const float4* __restrict__ H = (const float4*)h;
    int t = threadIdx.x;  // 0..63
    float ax = 0.f, ay = 0.f, az = 0.f, aw = 0.f;

    int k = beg;
    for (; k + 4 <= end; k += 4) {
        int   s0 = g_csr_src[k],     s1 = g_csr_src[k + 1];
        int   s2 = g_csr_src[k + 2], s3 = g_csr_src[k + 3];
        float w0 = g_csr_w[k],       w1 = g_csr_w[k + 1];
        float w2 = g_csr_w[k + 2],   w3 = g_csr_w[k + 3];
        float4 v0 = H[(size_t)s0 * 64 + t];
        float4 v1 = H[(size_t)s1 * 64 + t];
        float4 v2 = H[(size_t)s2 * 64 + t];
        float4 v3 = H[(size_t)s3 * 64 + t];
        ax = fmaf(v0.x, w0, fmaf(v1.x, w1, fmaf(v2.x, w2, fmaf(v3.x, w3, ax))));
        ay = fmaf(v0.y, w0, fmaf(v1.y, w1, fmaf(v2.y, w2, fmaf(v3.y, w3, ay))));
        az = fmaf(v0.z, w0, fmaf(v1.z, w1, fmaf(v2.z, w2, fmaf(v3.z, w3, az))));
        aw = fmaf(v0.w, w0, fmaf(v1.w, w1, fmaf(v2.w, w2, fmaf(v3.w, w3, aw))));
    }
    for (; k < end; ++k) {
        int s = g_csr_src[k];
        float w = g_csr_w[k];
        float4 v = H[(size_t)s * 64 + t];
        ax = fmaf(v.x, w, ax); ay = fmaf(v.y, w, ay);
        az = fmaf(v.z, w, az); aw = fmaf(v.w, w, aw);
    }
    uint32_t h0, l0, h1, l1;
    split2(ax, ay, h0, l0);
    split2(az, aw, h1, l1);
    ((uint2*)ahh)[(size_t)node * 64 + t] = make_uint2(h0, h1);
    ((uint2*)ahl)[(size_t)node * 64 + t] = make_uint2(l0, l1);
}

// ---------------- bf16x3 tensor-core GEMM: 3-stage cp.async ring -------------
// C = epi( [A1|A2] @ W^T ). A arrays row stride 256. Block 128x128, 8 warps
// (2x4), warp 64x32. K staged 32-deep, 3-buffer ring, ONE barrier per stage.
// smem matrix layout: 128 rows x 64B, 16B chunk c of row r at swz(r, c).
template<bool FUSE, bool SPLIT>
__global__ __launch_bounds__(256, 2)
void mma_gemm_k(const bf16* __restrict__ a1h, const bf16* __restrict__ a1l,
                const bf16* __restrict__ a2h, const bf16* __restrict__ a2l,
                int Ktot,
                const bf16* __restrict__ wh, const bf16* __restrict__ wl,
                const float* __restrict__ bias, const float* __restrict__ res,
                float* __restrict__ C, bf16* __restrict__ Chi, bf16* __restrict__ Clo,
                int M, int Ncols)
{
    extern __shared__ __align__(16) char smem[];
    const uint32_t sb = smem_u32(smem);
    const int tid  = threadIdx.x;
    const int lane = tid & 31, wid = tid >> 5;
    const int wm = wid >> 2, wn = wid & 3;
    const int r = lane >> 2, q = lane & 3;
    const int ib = blockIdx.x * 128, jb = blockIdx.y * 128;
    const int S = Ktot / 32;

    float acc[4][4][4];
    #pragma unroll
    for (int a = 0; a < 4; ++a)
        #pragma unroll
        for (int b = 0; b < 4; ++b)
            #pragma unroll
            for (int c = 0; c < 4; ++c) acc[a][b][c] = 0.f;

    // async fill of stage s into ring buffer s % NSTG (8 x 16B per thread)
    auto fill = [&](int s) {
        const int k0 = s * 32;
        const uint32_t stb = sb + (s % NSTG) * STGB;
        #pragma unroll
        for (int i = 0; i < 8; ++i) {
            int g = i * 256 + tid;
            int mat = g >> 9, idx = g & 511;
            int row = idx >> 2, c = idx & 3;
            uint32_t dst = stb + mat * MATB + swz(row, c);
            const bf16* src;
            int sz = 16;
            if (mat < 2) {
                const bf16* a = (k0 < 256) ? (mat == 0 ? a1h : a1l)
                                           : (mat == 0 ? a2h : a2l);
                int gr = ib + row;
                if (gr >= M) { gr = 0; sz = 0; }
                src = a + (size_t)gr * 256 + (k0 & 255) + c * 8;
            } else {
                src = ((mat == 2) ? wh : wl) + (size_t)(jb + row) * Ktot + k0 + c * 8;
            }
            CP_ASYNC16(dst, src, sz);
        }
        CP_COMMIT();
    };

    fill(0);
    if (S > 1) fill(1);

    for (int s = 0; s < S; ++s) {
        if (s + 1 < S) asm volatile("cp.async.wait_group 1;" ::: "memory");
        else           asm volatile("cp.async.wait_group 0;" ::: "memory");
        __syncthreads();                 // single barrier per stage
        if (s + 2 < S) fill(s + 2);      // writes ring (s+2)%3: free since stage s-1

        const uint32_t stb = sb + (s % NSTG) * STGB;
        const uint32_t aBase = stb;
        const uint32_t bBase = stb + 2 * MATB;

        #pragma unroll
        for (int ks = 0; ks < 2; ++ks) {
            const int aChunk = ks * 2 + (lane >> 4);
            const int bChunk = ks * 2 + ((lane >> 3) & 1);
            const int aRow = (lane & 15);
            const int bRow = (lane & 7) + ((lane >> 4) << 3);

            uint32_t AH[4][4], BH[4][2];
            #pragma unroll
            for (int mt = 0; mt < 4; ++mt) {
                uint32_t ad = aBase + swz(wm * 64 + mt * 16 + aRow, aChunk);
                LDSM_X4(AH[mt][0], AH[mt][1], AH[mt][2], AH[mt][3], ad);
            }
            #pragma unroll
            for (int p = 0; p < 2; ++p) {
                uint32_t bd = bBase + swz(wn * 32 + p * 16 + bRow, bChunk);
                LDSM_X4(BH[2*p][0], BH[2*p][1], BH[2*p+1][0], BH[2*p+1][1], bd);
            }
            #pragma unroll
            for (int mt = 0; mt < 4; ++mt)
                #pragma unroll
                for (int nt = 0; nt < 4; ++nt)
                    mma_bf16(acc[mt][nt], AH[mt][0], AH[mt][1], AH[mt][2], AH[mt][3],
                             BH[nt][0], BH[nt][1]);

            {   // hi(A) * lo(B)
                uint32_t BL[4][2];
                #pragma unroll
                for (int p = 0; p < 2; ++p) {
                    uint32_t bd = bBase + MATB + swz(wn * 32 + p * 16 + bRow, bChunk);
                    LDSM_X4(BL[2*p][0], BL[2*p][1], BL[2*p+1][0], BL[2*p+1][1], bd);
                }
                #pragma unroll
                for (int mt = 0; mt < 4; ++mt)
                    #pragma unroll
                    for (int nt = 0; nt < 4; ++nt)
                        mma_bf16(acc[mt][nt], AH[mt][0], AH[mt][1], AH[mt][2], AH[mt][3],
                                 BL[nt][0], BL[nt][1]);
            }
            {   // lo(A) * hi(B)
                uint32_t AL[4][4];
                #pragma unroll
                for (int mt = 0; mt < 4; ++mt) {
                    uint32_t ad = aBase + MATB + swz(wm * 64 + mt * 16 + aRow, aChunk);
                    LDSM_X4(AL[mt][0], AL[mt][1], AL[mt][2], AL[mt][3], ad);
                }
                #pragma unroll
                for (int mt = 0; mt < 4; ++mt)
                    #pragma unroll
                    for (int nt = 0; nt < 4; ++nt)
                        mma_bf16(acc[mt][nt], AL[mt][0], AL[mt][1], AL[mt][2], AL[mt][3],
                                 BH[nt][0], BH[nt][1]);
            }
        }
    }

    // ---------------- epilogue ----------------
    #pragma unroll
    for (int mt = 0; mt < 4; ++mt) {
        #pragma unroll
        for (int nt = 0; nt < 4; ++nt) {
            int row0 = ib + wm * 64 + mt * 16 + r;
            int col  = jb + wn * 32 + nt * 8 + 2 * q;
            float2 b2 = make_float2(0.f, 0.f);
            if (FUSE) b2 = *(const float2*)&bias[col];
            #pragma unroll
            for (int hf = 0; hf < 2; ++hf) {
                int row = row0 + 8 * hf;
                if (row >= M) continue;
                float o0 = acc[mt][nt][2 * hf + 0];
                float o1 = acc[mt][nt][2 * hf + 1];
                if (FUSE) {
                    float2 rv = *(const float2*)&res[(size_t)row * Ncols + col];
                    o0 = rv.x + fmaxf(o0 + b2.x, 0.f);
                    o1 = rv.y + fmaxf(o1 + b2.y, 0.f);
                }
                *(float2*)&C[(size_t)row * Ncols + col] = make_float2(o0, o1);
                if (SPLIT) {
                    uint32_t hi, lo;
                    split2(o0, o1, hi, lo);
                    *(uint32_t*)(Chi + (size_t)row * Ncols + col) = hi;
                    *(uint32_t*)(Clo + (size_t)row * Ncols + col) = lo;
                }
            }
        }
    }
}

// ---------------- row L2-normalize (128 cols): one warp per row --------------
__global__ void norm_k(float* __restrict__ out) {
    int row = blockIdx.x * 8 + threadIdx.y;  // blockDim (32,8)
    if (row >= NN) return;
    float4* p = (float4*)out + (size_t)row * 32 + threadIdx.x;
    float4 v = *p;
    float s = v.x * v.x + v.y * v.y + v.z * v.z + v.w * v.w;
    #pragma unroll
    for (int off = 16; off > 0; off >>= 1)
        s += __shfl_xor_sync(0xFFFFFFFFu, s, off);
    float r = rsqrtf(s);
    v.x *= r; v.y *= r; v.z *= r; v.w *= r;
    *p = v;
}

// ---------------- launch -----------------------------------------------------
extern "C" void kernel_launch(void* const* d_in, const int* in_sizes, int n_in,
                              void* d_out, int out_size) {
    const float* x     = (const float*)d_in[0];
    const int*   esrc  = (const int*)  d_in[1];
    const int*   edst  = (const int*)  d_in[2];
    const float* ew    = (const float*)d_in[3];
    const float* W_emb = (const float*)d_in[4];
    const float* W_gc1 = (const float*)d_in[5];
    const float* b_gc1 = (const float*)d_in[6];
    const float* W_gc2 = (const float*)d_in[7];
    const float* b_gc2 = (const float*)d_in[8];
    const float* W_fc  = (const float*)d_in[9];
    float* out = (float*)d_out;

    float *h, *h2;
    bf16 *xh, *xl, *hh, *hl, *h2h, *h2l, *ahh, *ahl;
    bf16 *weh, *wel, *w1h, *w1l, *w2h, *w2l, *wfh, *wfl;
    cudaGetSymbolAddress((void**)&h,   g_h);
    cudaGetSymbolAddress((void**)&h2,  g_h2);
    cudaGetSymbolAddress((void**)&xh,  g_xh);  cudaGetSymbolAddress((void**)&xl,  g_xl);
    cudaGetSymbolAddress((void**)&hh,  g_hh);  cudaGetSymbolAddress((void**)&hl,  g_hl);
    cudaGetSymbolAddress((void**)&h2h, g_h2h); cudaGetSymbolAddress((void**)&h2l, g_h2l);
    cudaGetSymbolAddress((void**)&ahh, g_ahh); cudaGetSymbolAddress((void**)&ahl, g_ahl);
    cudaGetSymbolAddress((void**)&weh, g_weh); cudaGetSymbolAddress((void**)&wel, g_wel);
    cudaGetSymbolAddress((void**)&w1h, g_w1h); cudaGetSymbolAddress((void**)&w1l, g_w1l);
    cudaGetSymbolAddress((void**)&w2h, g_w2h); cudaGetSymbolAddress((void**)&w2l, g_w2l);
    cudaGetSymbolAddress((void**)&wfh, g_wfh); cudaGetSymbolAddress((void**)&wfl, g_wfl);

    const int SMEM = NSTG * STGB;  // 98304
    cudaFuncSetAttribute(mma_gemm_k<true,  true >, cudaFuncAttributeMaxDynamicSharedMemorySize, SMEM);
    cudaFuncSetAttribute(mma_gemm_k<false, true >, cudaFuncAttributeMaxDynamicSharedMemorySize, SMEM);
    cudaFuncSetAttribute(mma_gemm_k<false, false>, cudaFuncAttributeMaxDynamicSharedMemorySize, SMEM);

    const int MT = (NN + 127) / 128;   // 157
    dim3 gHid(MT, HIDF / 128);         // 157 x 2
    dim3 gOut(MT, OUTF / 128);         // 157 x 1
    dim3 gblk(5000), gthr(64, 4);

    // index-3 launch = emb GEMM (ncu capture slot)
    split_k<<<(NN * INF / 4 + 255) / 256, 256>>>(x, xh, xl, NN * INF);                 // 0
    split_k<<<(HIDF * INF / 4 + 255) / 256, 256>>>(W_emb, weh, wel, HIDF * INF);       // 1
    zero_cnt_k<<<(NN + 255) / 256, 256>>>();                                           // 2
    mma_gemm_k<false, true><<<gHid, 256, SMEM>>>(                                      // 3 (ncu)
        xh, xl, nullptr, nullptr, INF, weh, wel,
        nullptr, nullptr, h, hh, hl, NN, HIDF);
    count_k  <<<(EE + 255) / 256, 256>>>(edst);                                        // 4
    scan_k   <<<1, 1024>>>();                                                          // 5
    scatter_k<<<(EE + 255) / 256, 256>>>(esrc, edst, ew);                              // 6
    split3_k<<<((2 * HIDF * 2 * HIDF + OUTF * HIDF) / 4 + 255) / 256, 256>>>(          // 7
        W_gc1, w1h, w1l, HIDF * 2 * HIDF,
        W_gc2, w2h, w2l, HIDF * 2 * HIDF,
        W_fc,  wfh, wfl, OUTF * HIDF);

    // Ah = A @ h ; h2 = h + relu([h|Ah] @ W_gc1^T + b1)
    gather_k<<<gblk, gthr>>>(h, ahh, ahl);                                             // 8
    mma_gemm_k<true, true><<<gHid, 256, SMEM>>>(                                       // 9
        hh, hl, ahh, ahl, 2 * HIDF, w1h, w1l,
        b_gc1, h, h2, h2h, h2l, NN, HIDF);
    // Ah = A @ h2 ; h = h2 + relu([h2|Ah] @ W_gc2^T + b2)
    gather_k<<<gblk, gthr>>>(h2, ahh, ahl);                                            // 10
    mma_gemm_k<true, true><<<gHid, 256, SMEM>>>(                                       // 11
        h2h, h2l, ahh, ahl, 2 * HIDF, w2h, w2l,
        b_gc2, h2, h, hh, hl, NN, HIDF);
    // out = h @ W_fc^T ; rows L2-normalized
    mma_gemm_k<false, false><<<gOut, 256, SMEM>>>(                                     // 12
        hh, hl, nullptr, nullptr, HIDF, wfh, wfl,
        nullptr, nullptr, out, nullptr, nullptr, NN, OUTF);
    norm_k<<<(NN + 7) / 8, dim3(32, 8)>>>(out);                                        // 13
}

// round 9
// speedup vs baseline: 2.3837x; 1.0794x over previous
#include <cuda_runtime.h>
#include <cuda_bf16.h>
#include <cstdint>

#define NN   20000
#define EE   320000
#define INF  256
#define HIDF 256
#define OUTF 128
#define BM   144                 // M tile (9 x 16)
#define ABYT 9216                // 144 rows x 64B per A matrix
#define BBYT 8192                // 128 rows x 64B per B matrix
#define STGB (2 * ABYT + 2 * BBYT)   // 34816 per stage
#define NSTG 3

typedef __nv_bfloat16 bf16;

// ---------------- scratch (device globals; no allocation allowed) ------------
__device__ float g_h [NN * HIDF];
__device__ float g_h2[NN * HIDF];
__device__ bf16  g_xh [NN * HIDF], g_xl [NN * HIDF];
__device__ bf16  g_hh [NN * HIDF], g_hl [NN * HIDF];
__device__ bf16  g_h2h[NN * HIDF], g_h2l[NN * HIDF];
__device__ bf16  g_ahh[NN * HIDF], g_ahl[NN * HIDF];
__device__ bf16  g_weh[HIDF * INF],      g_wel[HIDF * INF];
__device__ bf16  g_w1h[HIDF * 2 * HIDF], g_w1l[HIDF * 2 * HIDF];
__device__ bf16  g_w2h[HIDF * 2 * HIDF], g_w2l[HIDF * 2 * HIDF];
__device__ bf16  g_wfh[OUTF * HIDF],     g_wfl[OUTF * HIDF];
__device__ int   g_cnt[NN];
__device__ int   g_off[NN + 1];
__device__ int   g_fill[NN];
__device__ int   g_csr_src[EE];
__device__ float g_csr_w[EE];

// ---------------- helpers ----------------------------------------------------
__device__ __forceinline__ uint32_t smem_u32(const void* p) {
    uint32_t a;
    asm("{ .reg .u64 t; cvta.to.shared.u64 t, %1; cvt.u32.u64 %0, t; }"
        : "=r"(a) : "l"(p));
    return a;
}

__device__ __forceinline__ void split2(float x, float y, uint32_t& hi, uint32_t& lo) {
    bf16 hx = __float2bfloat16_rn(x);
    bf16 hy = __float2bfloat16_rn(y);
    float rx = x - __bfloat162float(hx);
    float ry = y - __bfloat162float(hy);
    __nv_bfloat162 H; H.x = hx; H.y = hy;
    __nv_bfloat162 L = __floats2bfloat162_rn(rx, ry);
    hi = *reinterpret_cast<uint32_t*>(&H);
    lo = *reinterpret_cast<uint32_t*>(&L);
}

__device__ __forceinline__ void mma_bf16(float c[4],
                                         uint32_t a0, uint32_t a1, uint32_t a2, uint32_t a3,
                                         uint32_t b0, uint32_t b1) {
    asm volatile(
        "mma.sync.aligned.m16n8k16.row.col.f32.bf16.bf16.f32 "
        "{%0,%1,%2,%3}, {%4,%5,%6,%7}, {%8,%9}, {%0,%1,%2,%3};"
        : "+f"(c[0]), "+f"(c[1]), "+f"(c[2]), "+f"(c[3])
        : "r"(a0), "r"(a1), "r"(a2), "r"(a3), "r"(b0), "r"(b1));
}

#define LDSM_X4(r0, r1, r2, r3, addr) \
    asm volatile("ldmatrix.sync.aligned.m8n8.x4.shared.b16 {%0,%1,%2,%3}, [%4];" \
                 : "=r"(r0), "=r"(r1), "=r"(r2), "=r"(r3) : "r"(addr))

#define CP_ASYNC16(dst, src, sz) \
    asm volatile("cp.async.cg.shared.global [%0], [%1], 16, %2;" \
                 :: "r"(dst), "l"(src), "r"(sz) : "memory")

#define CP_COMMIT() asm volatile("cp.async.commit_group;" ::: "memory")

// XOR-swizzled offset of 16B chunk c in row r (row stride 64B data, no pad)
__device__ __forceinline__ uint32_t swz(int row, int chunk) {
    return (uint32_t)(row * 64 + ((chunk ^ ((row >> 1) & 3)) << 4));
}

// ---------------- fp32 -> bf16 hi/lo splits ----------------------------------
__global__ void split_k(const float* __restrict__ s, bf16* __restrict__ hi,
                        bf16* __restrict__ lo, int n) {
    int i = (blockIdx.x * blockDim.x + threadIdx.x) * 4;
    if (i >= n) return;
    float4 v = *(const float4*)(s + i);
    uint32_t h0, l0, h1, l1;
    split2(v.x, v.y, h0, l0);
    split2(v.z, v.w, h1, l1);
    *(uint2*)(hi + i) = make_uint2(h0, h1);
    *(uint2*)(lo + i) = make_uint2(l0, l1);
}

__global__ void split3_k(const float* __restrict__ s0, bf16* __restrict__ h0, bf16* __restrict__ l0, int n0,
                         const float* __restrict__ s1, bf16* __restrict__ h1, bf16* __restrict__ l1, int n1,
                         const float* __restrict__ s2, bf16* __restrict__ h2, bf16* __restrict__ l2, int n2) {
    int i = (blockIdx.x * blockDim.x + threadIdx.x) * 4;
    const float* s; bf16 *hh, *ll;
    if (i < n0)               { s = s0 + i;             hh = h0 + i;             ll = l0 + i; }
    else if (i < n0 + n1)     { s = s1 + (i - n0);      hh = h1 + (i - n0);      ll = l1 + (i - n0); }
    else if (i < n0 + n1 + n2){ s = s2 + (i - n0 - n1); hh = h2 + (i - n0 - n1); ll = l2 + (i - n0 - n1); }
    else return;
    float4 v = *(const float4*)s;
    uint32_t a, b, c, d;
    split2(v.x, v.y, a, b);
    split2(v.z, v.w, c, d);
    *(uint2*)hh = make_uint2(a, c);
    *(uint2*)ll = make_uint2(b, d);
}

// ---------------- CSR build --------------------------------------------------
__global__ void zero_cnt_k() {
    int i = blockIdx.x * blockDim.x + threadIdx.x;
    if (i < NN) g_cnt[i] = 0;
}

__global__ void count_k(const int* __restrict__ dst) {
    int e = blockIdx.x * blockDim.x + threadIdx.x;
    if (e < EE) atomicAdd(&g_cnt[dst[e]], 1);
}

__global__ void scan_k() {
    __shared__ int s[1024];
    __shared__ int carry;
    int tid = threadIdx.x;
    if (tid == 0) carry = 0;
    __syncthreads();
    for (int base = 0; base < NN; base += 1024) {
        int i = base + tid;
        int v = (i < NN) ? g_cnt[i] : 0;
        s[tid] = v;
        __syncthreads();
        #pragma unroll
        for (int off = 1; off < 1024; off <<= 1) {
            int t = 0;
            if (tid >= off) t = s[tid - off];
            __syncthreads();
            if (tid >= off) s[tid] += t;
            __syncthreads();
        }
        int incl  = s[tid];
        int cbase = carry;
        __syncthreads();
        if (i < NN) {
            int ex = cbase + incl - v;
            g_off[i]  = ex;
            g_fill[i] = ex;
        }
        __syncthreads();
        if (tid == 0) carry = cbase + s[1023];
        __syncthreads();
    }
    if (tid == 0) g_off[NN] = carry;
}

__global__ void scatter_k(const int* __restrict__ src, const int* __restrict__ dst,
                          const float* __restrict__ w) {
    int e = blockIdx.x * blockDim.x + threadIdx.x;
    if (e < EE) {
        int d = dst[e];
        int p = atomicAdd(&g_fill[d], 1);
        g_csr_src[p] = src[e];
        g_csr_w[p]   = w[e];
    }
}

// ---------------- adj_mul gather, 4-way unrolled (MLP>=4) --------------------
__global__ void gather_k(const float* __restrict__ h,
                         bf16* __restrict__ ahh, bf16* __restrict__ ahl) {
    int node = blockIdx.x * 4 + threadIdx.y;
    if (node >= NN) return;
    int beg = g_off[node], end = g_off[node + 1];
    const float4* __restrict__ H = (const float4*)h;
    int t = threadIdx.x;  // 0..63
    float ax = 0.f, ay = 0.f, az = 0.f, aw = 0.f;

    int k = beg;
    for (; k + 4 <= end; k += 4) {
        int   s0 = g_csr_src[k],     s1 = g_csr_src[k + 1];
        int   s2 = g_csr_src[k + 2], s3 = g_csr_src[k + 3];
        float w0 = g_csr_w[k],       w1 = g_csr_w[k + 1];
        float w2 = g_csr_w[k + 2],   w3 = g_csr_w[k + 3];
        float4 v0 = H[(size_t)s0 * 64 + t];
        float4 v1 = H[(size_t)s1 * 64 + t];
        float4 v2 = H[(size_t)s2 * 64 + t];
        float4 v3 = H[(size_t)s3 * 64 + t];
        ax = fmaf(v0.x, w0, fmaf(v1.x, w1, fmaf(v2.x, w2, fmaf(v3.x, w3, ax))));
        ay = fmaf(v0.y, w0, fmaf(v1.y, w1, fmaf(v2.y, w2, fmaf(v3.y, w3, ay))));
        az = fmaf(v0.z, w0, fmaf(v1.z, w1, fmaf(v2.z, w2, fmaf(v3.z, w3, az))));
        aw = fmaf(v0.w, w0, fmaf(v1.w, w1, fmaf(v2.w, w2, fmaf(v3.w, w3, aw))));
    }
    for (; k < end; ++k) {
        int s = g_csr_src[k];
        float w = g_csr_w[k];
        float4 v = H[(size_t)s * 64 + t];
        ax = fmaf(v.x, w, ax); ay = fmaf(v.y, w, ay);
        az = fmaf(v.z, w, az); aw = fmaf(v.w, w, aw);
    }
    uint32_t h0, l0, h1, l1;
    split2(ax, ay, h0, l0);
    split2(az, aw, h1, l1);
    ((uint2*)ahh)[(size_t)node * 64 + t] = make_uint2(h0, h1);
    ((uint2*)ahl)[(size_t)node * 64 + t] = make_uint2(l0, l1);
}

// ---------------- bf16x3 tensor-core GEMM: 144x128 tile, single wave ---------
// C = epi( [A1|A2] @ W^T ). A row stride 256. 384 threads, 12 warps (3x4),
// warp 48x32 (mt=3, nt=4). K staged 32-deep, 3-buffer ring, 1 barrier/stage.
// Grid 139 x (Ncols/128): 278 CTAs at 2/SM = single wave (296 slots).
template<bool FUSE, bool SPLIT>
__global__ __launch_bounds__(384, 2)
void mma_gemm_k(const bf16* __restrict__ a1h, const bf16* __restrict__ a1l,
                const bf16* __restrict__ a2h, const bf16* __restrict__ a2l,
                int Ktot,
                const bf16* __restrict__ wh, const bf16* __restrict__ wl,
                const float* __restrict__ bias, const float* __restrict__ res,
                float* __restrict__ C, bf16* __restrict__ Chi, bf16* __restrict__ Clo,
                int M, int Ncols)
{
    extern __shared__ __align__(16) char smem[];
    const uint32_t sb = smem_u32(smem);
    const int tid  = threadIdx.x;
    const int lane = tid & 31, wid = tid >> 5;
    const int wm = wid >> 2, wn = wid & 3;     // 3 x 4 warp grid
    const int r = lane >> 2, q = lane & 3;
    const int ib = blockIdx.x * BM, jb = blockIdx.y * 128;
    const int S = Ktot / 32;

    float acc[3][4][4];
    #pragma unroll
    for (int a = 0; a < 3; ++a)
        #pragma unroll
        for (int b = 0; b < 4; ++b)
            #pragma unroll
            for (int c = 0; c < 4; ++c) acc[a][b][c] = 0.f;

    // async fill of stage s into ring buffer s % NSTG.
    // chunks: AH 576, AL 576 (144 rows x 4), BH 512, BL 512 -> 2176 x 16B.
    auto fill = [&](int s) {
        const int k0 = s * 32;
        const uint32_t stb = sb + (s % NSTG) * STGB;
        #pragma unroll
        for (int i = 0; i < 6; ++i) {
            int g = i * 384 + tid;
            if (g < 2176) {
                if (g < 1152) {
                    int mat = (g >= 576);
                    int idx = g - mat * 576;
                    int row = idx >> 2, c = idx & 3;
                    uint32_t dst = stb + mat * ABYT + swz(row, c);
                    const bf16* a = (k0 < 256) ? (mat ? a1l : a1h)
                                               : (mat ? a2l : a2h);
                    int gr = ib + row, sz = 16;
                    if (gr >= M) { gr = 0; sz = 0; }
                    CP_ASYNC16(dst, a + (size_t)gr * 256 + (k0 & 255) + c * 8, sz);
                } else {
                    int g2 = g - 1152;
                    int mat = (g2 >= 512);
                    int idx = g2 - mat * 512;
                    int row = idx >> 2, c = idx & 3;
                    uint32_t dst = stb + 2 * ABYT + mat * BBYT + swz(row, c);
                    const bf16* w = mat ? wl : wh;
                    CP_ASYNC16(dst, w + (size_t)(jb + row) * Ktot + k0 + c * 8, 16);
                }
            }
        }
        CP_COMMIT();
    };

    fill(0);
    if (S > 1) fill(1);

    for (int s = 0; s < S; ++s) {
        if (s + 1 < S) asm volatile("cp.async.wait_group 1;" ::: "memory");
        else           asm volatile("cp.async.wait_group 0;" ::: "memory");
        __syncthreads();                 // single barrier per stage
        if (s + 2 < S) fill(s + 2);      // ring (s+2)%3: stage s-1's buffer, free

        const uint32_t stb = sb + (s % NSTG) * STGB;
        const uint32_t ahB = stb;
        const uint32_t alB = stb + ABYT;
        const uint32_t bhB = stb + 2 * ABYT;
        const uint32_t blB = stb + 2 * ABYT + BBYT;

        #pragma unroll
        for (int ks = 0; ks < 2; ++ks) {
            const int aChunk = ks * 2 + (lane >> 4);
            const int bChunk = ks * 2 + ((lane >> 3) & 1);
            const int aRow = (lane & 15);
            const int bRow = (lane & 7) + ((lane >> 4) << 3);

            uint32_t AH[3][4], BH[4][2];
            #pragma unroll
            for (int mt = 0; mt < 3; ++mt) {
                uint32_t ad = ahB + swz(wm * 48 + mt * 16 + aRow, aChunk);
                LDSM_X4(AH[mt][0], AH[mt][1], AH[mt][2], AH[mt][3], ad);
            }
            #pragma unroll
            for (int p = 0; p < 2; ++p) {
                uint32_t bd = bhB + swz(wn * 32 + p * 16 + bRow, bChunk);
                LDSM_X4(BH[2*p][0], BH[2*p][1], BH[2*p+1][0], BH[2*p+1][1], bd);
            }
            #pragma unroll
            for (int mt = 0; mt < 3; ++mt)
                #pragma unroll
                for (int nt = 0; nt < 4; ++nt)
                    mma_bf16(acc[mt][nt], AH[mt][0], AH[mt][1], AH[mt][2], AH[mt][3],
                             BH[nt][0], BH[nt][1]);

            {   // hi(A) * lo(B)
                uint32_t BL[4][2];
                #pragma unroll
                for (int p = 0; p < 2; ++p) {
                    uint32_t bd = blB + swz(wn * 32 + p * 16 + bRow, bChunk);
                    LDSM_X4(BL[2*p][0], BL[2*p][1], BL[2*p+1][0], BL[2*p+1][1], bd);
                }
                #pragma unroll
                for (int mt = 0; mt < 3; ++mt)
                    #pragma unroll
                    for (int nt = 0; nt < 4; ++nt)
                        mma_bf16(acc[mt][nt], AH[mt][0], AH[mt][1], AH[mt][2], AH[mt][3],
                                 BL[nt][0], BL[nt][1]);
            }
            {   // lo(A) * hi(B)
                uint32_t AL[3][4];
                #pragma unroll
                for (int mt = 0; mt < 3; ++mt) {
                    uint32_t ad = alB + swz(wm * 48 + mt * 16 + aRow, aChunk);
                    LDSM_X4(AL[mt][0], AL[mt][1], AL[mt][2], AL[mt][3], ad);
                }
                #pragma unroll
                for (int mt = 0; mt < 3; ++mt)
                    #pragma unroll
                    for (int nt = 0; nt < 4; ++nt)
                        mma_bf16(acc[mt][nt], AL[mt][0], AL[mt][1], AL[mt][2], AL[mt][3],
                                 BH[nt][0], BH[nt][1]);
            }
        }
    }

    // ---------------- epilogue ----------------
    #pragma unroll
    for (int mt = 0; mt < 3; ++mt) {
        #pragma unroll
        for (int nt = 0; nt < 4; ++nt) {
            int row0 = ib + wm * 48 + mt * 16 + r;
            int col  = jb + wn * 32 + nt * 8 + 2 * q;
            float2 b2 = make_float2(0.f, 0.f);
            if (FUSE) b2 = *(const float2*)&bias[col];
            #pragma unroll
            for (int hf = 0; hf < 2; ++hf) {
                int row = row0 + 8 * hf;
                if (row >= M) continue;
                float o0 = acc[mt][nt][2 * hf + 0];
                float o1 = acc[mt][nt][2 * hf + 1];
                if (FUSE) {
                    float2 rv = *(const float2*)&res[(size_t)row * Ncols + col];
                    o0 = rv.x + fmaxf(o0 + b2.x, 0.f);
                    o1 = rv.y + fmaxf(o1 + b2.y, 0.f);
                }
                *(float2*)&C[(size_t)row * Ncols + col] = make_float2(o0, o1);
                if (SPLIT) {
                    uint32_t hi, lo;
                    split2(o0, o1, hi, lo);
                    *(uint32_t*)(Chi + (size_t)row * Ncols + col) = hi;
                    *(uint32_t*)(Clo + (size_t)row * Ncols + col) = lo;
                }
            }
        }
    }
}

// ---------------- row L2-normalize (128 cols): one warp per row --------------
__global__ void norm_k(float* __restrict__ out) {
    int row = blockIdx.x * 8 + threadIdx.y;  // blockDim (32,8)
    if (row >= NN) return;
    float4* p = (float4*)out + (size_t)row * 32 + threadIdx.x;
    float4 v = *p;
    float s = v.x * v.x + v.y * v.y + v.z * v.z + v.w * v.w;
    #pragma unroll
    for (int off = 16; off > 0; off >>= 1)
        s += __shfl_xor_sync(0xFFFFFFFFu, s, off);
    float r = rsqrtf(s);
    v.x *= r; v.y *= r; v.z *= r; v.w *= r;
    *p = v;
}

// ---------------- launch -----------------------------------------------------
extern "C" void kernel_launch(void* const* d_in, const int* in_sizes, int n_in,
                              void* d_out, int out_size) {
    const float* x     = (const float*)d_in[0];
    const int*   esrc  = (const int*)  d_in[1];
    const int*   edst  = (const int*)  d_in[2];
    const float* ew    = (const float*)d_in[3];
    const float* W_emb = (const float*)d_in[4];
    const float* W_gc1 = (const float*)d_in[5];
    const float* b_gc1 = (const float*)d_in[6];
    const float* W_gc2 = (const float*)d_in[7];
    const float* b_gc2 = (const float*)d_in[8];
    const float* W_fc  = (const float*)d_in[9];
    float* out = (float*)d_out;

    float *h, *h2;
    bf16 *xh, *xl, *hh, *hl, *h2h, *h2l, *ahh, *ahl;
    bf16 *weh, *wel, *w1h, *w1l, *w2h, *w2l, *wfh, *wfl;
    cudaGetSymbolAddress((void**)&h,   g_h);
    cudaGetSymbolAddress((void**)&h2,  g_h2);
    cudaGetSymbolAddress((void**)&xh,  g_xh);  cudaGetSymbolAddress((void**)&xl,  g_xl);
    cudaGetSymbolAddress((void**)&hh,  g_hh);  cudaGetSymbolAddress((void**)&hl,  g_hl);
    cudaGetSymbolAddress((void**)&h2h, g_h2h); cudaGetSymbolAddress((void**)&h2l, g_h2l);
    cudaGetSymbolAddress((void**)&ahh, g_ahh); cudaGetSymbolAddress((void**)&ahl, g_ahl);
    cudaGetSymbolAddress((void**)&weh, g_weh); cudaGetSymbolAddress((void**)&wel, g_wel);
    cudaGetSymbolAddress((void**)&w1h, g_w1h); cudaGetSymbolAddress((void**)&w1l, g_w1l);
    cudaGetSymbolAddress((void**)&w2h, g_w2h); cudaGetSymbolAddress((void**)&w2l, g_w2l);
    cudaGetSymbolAddress((void**)&wfh, g_wfh); cudaGetSymbolAddress((void**)&wfl, g_wfl);

    const int SMEM = NSTG * STGB;  // 104448
    cudaFuncSetAttribute(mma_gemm_k<true,  true >, cudaFuncAttributeMaxDynamicSharedMemorySize, SMEM);
    cudaFuncSetAttribute(mma_gemm_k<false, true >, cudaFuncAttributeMaxDynamicSharedMemorySize, SMEM);
    cudaFuncSetAttribute(mma_gemm_k<false, false>, cudaFuncAttributeMaxDynamicSharedMemorySize, SMEM);

    const int MT = (NN + BM - 1) / BM;  // 139
    dim3 gHid(MT, HIDF / 128);          // 139 x 2 = 278 CTAs (one wave @2/SM)
    dim3 gOut(MT, OUTF / 128);          // 139 x 1
    dim3 gblk(5000), gthr(64, 4);

    // index-3 launch = emb GEMM (ncu capture slot)
    split_k<<<(NN * INF / 4 + 255) / 256, 256>>>(x, xh, xl, NN * INF);                 // 0
    split_k<<<(HIDF * INF / 4 + 255) / 256, 256>>>(W_emb, weh, wel, HIDF * INF);       // 1
    zero_cnt_k<<<(NN + 255) / 256, 256>>>();                                           // 2
    mma_gemm_k<false, true><<<gHid, 384, SMEM>>>(                                      // 3 (ncu)
        xh, xl, nullptr, nullptr, INF, weh, wel,
        nullptr, nullptr, h, hh, hl, NN, HIDF);
    count_k  <<<(EE + 255) / 256, 256>>>(edst);                                        // 4
    scan_k   <<<1, 1024>>>();                                                          // 5
    scatter_k<<<(EE + 255) / 256, 256>>>(esrc, edst, ew);                              // 6
    split3_k<<<((2 * HIDF * 2 * HIDF + OUTF * HIDF) / 4 + 255) / 256, 256>>>(          // 7
        W_gc1, w1h, w1l, HIDF * 2 * HIDF,
        W_gc2, w2h, w2l, HIDF * 2 * HIDF,
        W_fc,  wfh, wfl, OUTF * HIDF);

    // Ah = A @ h ; h2 = h + relu([h|Ah] @ W_gc1^T + b1)
    gather_k<<<gblk, gthr>>>(h, ahh, ahl);                                             // 8
    mma_gemm_k<true, true><<<gHid, 384, SMEM>>>(                                       // 9
        hh, hl, ahh, ahl, 2 * HIDF, w1h, w1l,
        b_gc1, h, h2, h2h, h2l, NN, HIDF);
    // Ah = A @ h2 ; h = h2 + relu([h2|Ah] @ W_gc2^T + b2)
    gather_k<<<gblk, gthr>>>(h2, ahh, ahl);                                            // 10
    mma_gemm_k<true, true><<<gHid, 384, SMEM>>>(                                       // 11
        h2h, h2l, ahh, ahl, 2 * HIDF, w2h, w2l,
        b_gc2, h2, h, hh, hl, NN, HIDF);
    // out = h @ W_fc^T ; rows L2-normalized
    mma_gemm_k<false, false><<<gOut, 384, SMEM>>>(                                     // 12
        hh, hl, nullptr, nullptr, HIDF, wfh, wfl,
        nullptr, nullptr, out, nullptr, nullptr, NN, OUTF);
    norm_k<<<(NN + 7) / 8, dim3(32, 8)>>>(out);                                        // 13
}

// round 10
// speedup vs baseline: 2.5116x; 1.0536x over previous
#include <cuda_runtime.h>
#include <cuda_bf16.h>
#include <cstdint>

#define NN   20000
#define EE   320000
#define INF  256
#define HIDF 256
#define OUTF 128
#define BM   144                 // M tile (9 x 16)
#define ABYT 9216                // 144 rows x 64B per A matrix
#define BBYT 8192                // 128 rows x 64B per B matrix
#define STGB (2 * ABYT + 2 * BBYT)   // 34816 per stage
#define NSTG 3

typedef __nv_bfloat16 bf16;

// ---------------- scratch (device globals; no allocation allowed) ------------
__device__ float g_h [NN * HIDF];
__device__ float g_h2[NN * HIDF];
__device__ bf16  g_xh [NN * HIDF], g_xl [NN * HIDF];
__device__ bf16  g_hh [NN * HIDF], g_hl [NN * HIDF];
__device__ bf16  g_h2h[NN * HIDF], g_h2l[NN * HIDF];
__device__ bf16  g_ahh[NN * HIDF], g_ahl[NN * HIDF];
__device__ bf16  g_weh[HIDF * INF],      g_wel[HIDF * INF];
__device__ bf16  g_w1h[HIDF * 2 * HIDF], g_w1l[HIDF * 2 * HIDF];
__device__ bf16  g_w2h[HIDF * 2 * HIDF], g_w2l[HIDF * 2 * HIDF];
__device__ bf16  g_wfh[OUTF * HIDF],     g_wfl[OUTF * HIDF];
__device__ int   g_cnt[NN];
__device__ int   g_off[NN + 1];
__device__ int   g_fill[NN];
__device__ int   g_csr_src[EE];
__device__ float g_csr_w[EE];

// ---------------- helpers ----------------------------------------------------
__device__ __forceinline__ uint32_t smem_u32(const void* p) {
    uint32_t a;
    asm("{ .reg .u64 t; cvta.to.shared.u64 t, %1; cvt.u32.u64 %0, t; }"
        : "=r"(a) : "l"(p));
    return a;
}

__device__ __forceinline__ void split2(float x, float y, uint32_t& hi, uint32_t& lo) {
    bf16 hx = __float2bfloat16_rn(x);
    bf16 hy = __float2bfloat16_rn(y);
    float rx = x - __bfloat162float(hx);
    float ry = y - __bfloat162float(hy);
    __nv_bfloat162 H; H.x = hx; H.y = hy;
    __nv_bfloat162 L = __floats2bfloat162_rn(rx, ry);
    hi = *reinterpret_cast<uint32_t*>(&H);
    lo = *reinterpret_cast<uint32_t*>(&L);
}

__device__ __forceinline__ void mma_bf16(float c[4],
                                         uint32_t a0, uint32_t a1, uint32_t a2, uint32_t a3,
                                         uint32_t b0, uint32_t b1) {
    asm volatile(
        "mma.sync.aligned.m16n8k16.row.col.f32.bf16.bf16.f32 "
        "{%0,%1,%2,%3}, {%4,%5,%6,%7}, {%8,%9}, {%0,%1,%2,%3};"
        : "+f"(c[0]), "+f"(c[1]), "+f"(c[2]), "+f"(c[3])
        : "r"(a0), "r"(a1), "r"(a2), "r"(a3), "r"(b0), "r"(b1));
}

#define LDSM_X4(r0, r1, r2, r3, addr) \
    asm volatile("ldmatrix.sync.aligned.m8n8.x4.shared.b16 {%0,%1,%2,%3}, [%4];" \
                 : "=r"(r0), "=r"(r1), "=r"(r2), "=r"(r3) : "r"(addr))

#define CP_ASYNC16(dst, src, sz) \
    asm volatile("cp.async.cg.shared.global [%0], [%1], 16, %2;" \
                 :: "r"(dst), "l"(src), "r"(sz) : "memory")

#define CP_COMMIT() asm volatile("cp.async.commit_group;" ::: "memory")

// XOR-swizzled offset of 16B chunk c in row r (row stride 64B data, no pad)
__device__ __forceinline__ uint32_t swz(int row, int chunk) {
    return (uint32_t)(row * 64 + ((chunk ^ ((row >> 1) & 3)) << 4));
}

// ---------------- fp32 -> bf16 hi/lo splits ----------------------------------
__global__ void split_k(const float* __restrict__ s, bf16* __restrict__ hi,
                        bf16* __restrict__ lo, int n) {
    int i = (blockIdx.x * blockDim.x + threadIdx.x) * 4;
    if (i >= n) return;
    float4 v = *(const float4*)(s + i);
    uint32_t h0, l0, h1, l1;
    split2(v.x, v.y, h0, l0);
    split2(v.z, v.w, h1, l1);
    *(uint2*)(hi + i) = make_uint2(h0, h1);
    *(uint2*)(lo + i) = make_uint2(l0, l1);
}

__global__ void split3_k(const float* __restrict__ s0, bf16* __restrict__ h0, bf16* __restrict__ l0, int n0,
                         const float* __restrict__ s1, bf16* __restrict__ h1, bf16* __restrict__ l1, int n1,
                         const float* __restrict__ s2, bf16* __restrict__ h2, bf16* __restrict__ l2, int n2) {
    int i = (blockIdx.x * blockDim.x + threadIdx.x) * 4;
    const float* s; bf16 *hh, *ll;
    if (i < n0)               { s = s0 + i;             hh = h0 + i;             ll = l0 + i; }
    else if (i < n0 + n1)     { s = s1 + (i - n0);      hh = h1 + (i - n0);      ll = l1 + (i - n0); }
    else if (i < n0 + n1 + n2){ s = s2 + (i - n0 - n1); hh = h2 + (i - n0 - n1); ll = l2 + (i - n0 - n1); }
    else return;
    float4 v = *(const float4*)s;
    uint32_t a, b, c, d;
    split2(v.x, v.y, a, b);
    split2(v.z, v.w, c, d);
    *(uint2*)hh = make_uint2(a, c);
    *(uint2*)ll = make_uint2(b, d);
}

// ---------------- CSR build --------------------------------------------------
__global__ void zero_cnt_k() {
    int i = blockIdx.x * blockDim.x + threadIdx.x;
    if (i < NN) g_cnt[i] = 0;
}

__global__ void count_k(const int* __restrict__ dst) {
    int e = blockIdx.x * blockDim.x + threadIdx.x;
    if (e < EE) atomicAdd(&g_cnt[dst[e]], 1);
}

__global__ void scan_k() {
    __shared__ int s[1024];
    __shared__ int carry;
    int tid = threadIdx.x;
    if (tid == 0) carry = 0;
    __syncthreads();
    for (int base = 0; base < NN; base += 1024) {
        int i = base + tid;
        int v = (i < NN) ? g_cnt[i] : 0;
        s[tid] = v;
        __syncthreads();
        #pragma unroll
        for (int off = 1; off < 1024; off <<= 1) {
            int t = 0;
            if (tid >= off) t = s[tid - off];
            __syncthreads();
            if (tid >= off) s[tid] += t;
            __syncthreads();
        }
        int incl  = s[tid];
        int cbase = carry;
        __syncthreads();
        if (i < NN) {
            int ex = cbase + incl - v;
            g_off[i]  = ex;
            g_fill[i] = ex;
        }
        __syncthreads();
        if (tid == 0) carry = cbase + s[1023];
        __syncthreads();
    }
    if (tid == 0) g_off[NN] = carry;
}

__global__ void scatter_k(const int* __restrict__ src, const int* __restrict__ dst,
                          const float* __restrict__ w) {
    int e = blockIdx.x * blockDim.x + threadIdx.x;
    if (e < EE) {
        int d = dst[e];
        int p = atomicAdd(&g_fill[d], 1);
        g_csr_src[p] = src[e];
        g_csr_w[p]   = w[e];
    }
}

// ---------------- adj_mul gather, 4-way unrolled (MLP>=4) --------------------
__global__ void gather_k(const float* __restrict__ h,
                         bf16* __restrict__ ahh, bf16* __restrict__ ahl) {
    int node = blockIdx.x * 4 + threadIdx.y;
    if (node >= NN) return;
    int beg = g_off[node], end = g_off[node + 1];
    const float4* __restrict__ H = (const float4*)h;
    int t = threadIdx.x;  // 0..63
    float ax = 0.f, ay = 0.f, az = 0.f, aw = 0.f;

    int k = beg;
    for (; k + 4 <= end; k += 4) {
        int   s0 = g_csr_src[k],     s1 = g_csr_src[k + 1];
        int   s2 = g_csr_src[k + 2], s3 = g_csr_src[k + 3];
        float w0 = g_csr_w[k],       w1 = g_csr_w[k + 1];
        float w2 = g_csr_w[k + 2],   w3 = g_csr_w[k + 3];
        float4 v0 = H[(size_t)s0 * 64 + t];
        float4 v1 = H[(size_t)s1 * 64 + t];
        float4 v2 = H[(size_t)s2 * 64 + t];
        float4 v3 = H[(size_t)s3 * 64 + t];
        ax = fmaf(v0.x, w0, fmaf(v1.x, w1, fmaf(v2.x, w2, fmaf(v3.x, w3, ax))));
        ay = fmaf(v0.y, w0, fmaf(v1.y, w1, fmaf(v2.y, w2, fmaf(v3.y, w3, ay))));
        az = fmaf(v0.z, w0, fmaf(v1.z, w1, fmaf(v2.z, w2, fmaf(v3.z, w3, az))));
        aw = fmaf(v0.w, w0, fmaf(v1.w, w1, fmaf(v2.w, w2, fmaf(v3.w, w3, aw))));
    }
    for (; k < end; ++k) {
        int s = g_csr_src[k];
        float w = g_csr_w[k];
        float4 v = H[(size_t)s * 64 + t];
        ax = fmaf(v.x, w, ax); ay = fmaf(v.y, w, ay);
        az = fmaf(v.z, w, az); aw = fmaf(v.w, w, aw);
    }
    uint32_t h0, l0, h1, l1;
    split2(ax, ay, h0, l0);
    split2(az, aw, h1, l1);
    ((uint2*)ahh)[(size_t)node * 64 + t] = make_uint2(h0, h1);
    ((uint2*)ahl)[(size_t)node * 64 + t] = make_uint2(l0, l1);
}

// ---------------- bf16x3 tensor-core GEMM: 144x128, register-lean ------------
// C = epi( [A1|A2] @ W^T ). A row stride 256. 384 threads, 12 warps (3x4),
// warp 48x32 (mt=3, nt=4). K staged 32-deep, 3-buffer ring, 1 barrier/stage.
// Inner loop streams A fragments one mt at a time (B frags resident):
// peak live regs ~78 < 85 cap -> no spills at 2 CTA/SM.
template<bool FUSE, bool SPLIT>
__global__ __launch_bounds__(384, 2)
void mma_gemm_k(const bf16* __restrict__ a1h, const bf16* __restrict__ a1l,
                const bf16* __restrict__ a2h, const bf16* __restrict__ a2l,
                int Ktot,
                const bf16* __restrict__ wh, const bf16* __restrict__ wl,
                const float* __restrict__ bias, const float* __restrict__ res,
                float* __restrict__ C, bf16* __restrict__ Chi, bf16* __restrict__ Clo,
                int M, int Ncols)
{
    extern __shared__ __align__(16) char smem[];
    const uint32_t sb = smem_u32(smem);
    const int tid  = threadIdx.x;
    const int lane = tid & 31, wid = tid >> 5;
    const int wm = wid >> 2, wn = wid & 3;     // 3 x 4 warp grid
    const int r = lane >> 2, q = lane & 3;
    const int ib = blockIdx.x * BM, jb = blockIdx.y * 128;
    const int S = Ktot / 32;

    // precomputed fragment rows (loop-invariant)
    const int aRow = wm * 48 + (lane & 15);
    const int bRow = wn * 32 + (lane & 7) + ((lane >> 4) << 3);
    const int aChk = (lane >> 4);
    const int bChk = ((lane >> 3) & 1);

    float acc[3][4][4];
    #pragma unroll
    for (int a = 0; a < 3; ++a)
        #pragma unroll
        for (int b = 0; b < 4; ++b)
            #pragma unroll
            for (int c = 0; c < 4; ++c) acc[a][b][c] = 0.f;

    // async fill of stage s into ring buffer s % NSTG.
    // chunks: AH 576, AL 576 (144 rows x 4), BH 512, BL 512 -> 2176 x 16B.
    auto fill = [&](int s) {
        const int k0 = s * 32;
        const uint32_t stb = sb + (s % NSTG) * STGB;
        #pragma unroll
        for (int i = 0; i < 6; ++i) {
            int g = i * 384 + tid;
            if (g < 2176) {
                if (g < 1152) {
                    int mat = (g >= 576);
                    int idx = g - mat * 576;
                    int row = idx >> 2, c = idx & 3;
                    uint32_t dst = stb + mat * ABYT + swz(row, c);
                    const bf16* a = (k0 < 256) ? (mat ? a1l : a1h)
                                               : (mat ? a2l : a2h);
                    int gr = ib + row, sz = 16;
                    if (gr >= M) { gr = 0; sz = 0; }
                    CP_ASYNC16(dst, a + (size_t)gr * 256 + (k0 & 255) + c * 8, sz);
                } else {
                    int g2 = g - 1152;
                    int mat = (g2 >= 512);
                    int idx = g2 - mat * 512;
                    int row = idx >> 2, c = idx & 3;
                    uint32_t dst = stb + 2 * ABYT + mat * BBYT + swz(row, c);
                    const bf16* w = mat ? wl : wh;
                    CP_ASYNC16(dst, w + (size_t)(jb + row) * Ktot + k0 + c * 8, 16);
                }
            }
        }
        CP_COMMIT();
    };

    fill(0);
    if (S > 1) fill(1);

    for (int s = 0; s < S; ++s) {
        if (s + 1 < S) asm volatile("cp.async.wait_group 1;" ::: "memory");
        else           asm volatile("cp.async.wait_group 0;" ::: "memory");
        __syncthreads();                 // single barrier per stage
        if (s + 2 < S) fill(s + 2);      // ring (s+2)%3: stage s-1's buffer, free

        const uint32_t stb = sb + (s % NSTG) * STGB;
        const uint32_t ahB = stb;
        const uint32_t alB = stb + ABYT;
        const uint32_t bhB = stb + 2 * ABYT;
        const uint32_t blB = stb + 2 * ABYT + BBYT;

        #pragma unroll
        for (int ks = 0; ks < 2; ++ks) {
            const int aChunk = ks * 2 + aChk;
            const int bChunk = ks * 2 + bChk;

            // B fragments resident: BH + BL = 16 regs
            uint32_t BH[4][2], BL[4][2];
            #pragma unroll
            for (int p = 0; p < 2; ++p) {
                uint32_t bd = bhB + swz(bRow + p * 16, bChunk);
                LDSM_X4(BH[2*p][0], BH[2*p][1], BH[2*p+1][0], BH[2*p+1][1], bd);
            }
            #pragma unroll
            for (int p = 0; p < 2; ++p) {
                uint32_t bd = blB + swz(bRow + p * 16, bChunk);
                LDSM_X4(BL[2*p][0], BL[2*p][1], BL[2*p+1][0], BL[2*p+1][1], bd);
            }

            // stream A one mt-row at a time: 4 regs, reused for hi then lo
            #pragma unroll
            for (int mt = 0; mt < 3; ++mt) {
                uint32_t A0, A1, A2, A3;
                LDSM_X4(A0, A1, A2, A3, ahB + swz(aRow + mt * 16, aChunk));
                #pragma unroll
                for (int nt = 0; nt < 4; ++nt)
                    mma_bf16(acc[mt][nt], A0, A1, A2, A3, BH[nt][0], BH[nt][1]);
                #pragma unroll
                for (int nt = 0; nt < 4; ++nt)
                    mma_bf16(acc[mt][nt], A0, A1, A2, A3, BL[nt][0], BL[nt][1]);
                LDSM_X4(A0, A1, A2, A3, alB + swz(aRow + mt * 16, aChunk));
                #pragma unroll
                for (int nt = 0; nt < 4; ++nt)
                    mma_bf16(acc[mt][nt], A0, A1, A2, A3, BH[nt][0], BH[nt][1]);
            }
        }
    }

    // ---------------- epilogue ----------------
    #pragma unroll
    for (int mt = 0; mt < 3; ++mt) {
        #pragma unroll
        for (int nt = 0; nt < 4; ++nt) {
            int row0 = ib + wm * 48 + mt * 16 + r;
            int col  = jb + wn * 32 + nt * 8 + 2 * q;
            float2 b2 = make_float2(0.f, 0.f);
            if (FUSE) b2 = *(const float2*)&bias[col];
            #pragma unroll
            for (int hf = 0; hf < 2; ++hf) {
                int row = row0 + 8 * hf;
                if (row >= M) continue;
                float o0 = acc[mt][nt][2 * hf + 0];
                float o1 = acc[mt][nt][2 * hf + 1];
                if (FUSE) {
                    float2 rv = *(const float2*)&res[(size_t)row * Ncols + col];
                    o0 = rv.x + fmaxf(o0 + b2.x, 0.f);
                    o1 = rv.y + fmaxf(o1 + b2.y, 0.f);
                }
                *(float2*)&C[(size_t)row * Ncols + col] = make_float2(o0, o1);
                if (SPLIT) {
                    uint32_t hi, lo;
                    split2(o0, o1, hi, lo);
                    *(uint32_t*)(Chi + (size_t)row * Ncols + col) = hi;
                    *(uint32_t*)(Clo + (size_t)row * Ncols + col) = lo;
                }
            }
        }
    }
}

// ---------------- row L2-normalize (128 cols): one warp per row --------------
__global__ void norm_k(float* __restrict__ out) {
    int row = blockIdx.x * 8 + threadIdx.y;  // blockDim (32,8)
    if (row >= NN) return;
    float4* p = (float4*)out + (size_t)row * 32 + threadIdx.x;
    float4 v = *p;
    float s = v.x * v.x + v.y * v.y + v.z * v.z + v.w * v.w;
    #pragma unroll
    for (int off = 16; off > 0; off >>= 1)
        s += __shfl_xor_sync(0xFFFFFFFFu, s, off);
    float r = rsqrtf(s);
    v.x *= r; v.y *= r; v.z *= r; v.w *= r;
    *p = v;
}

// ---------------- launch -----------------------------------------------------
extern "C" void kernel_launch(void* const* d_in, const int* in_sizes, int n_in,
                              void* d_out, int out_size) {
    const float* x     = (const float*)d_in[0];
    const int*   esrc  = (const int*)  d_in[1];
    const int*   edst  = (const int*)  d_in[2];
    const float* ew    = (const float*)d_in[3];
    const float* W_emb = (const float*)d_in[4];
    const float* W_gc1 = (const float*)d_in[5];
    const float* b_gc1 = (const float*)d_in[6];
    const float* W_gc2 = (const float*)d_in[7];
    const float* b_gc2 = (const float*)d_in[8];
    const float* W_fc  = (const float*)d_in[9];
    float* out = (float*)d_out;

    float *h, *h2;
    bf16 *xh, *xl, *hh, *hl, *h2h, *h2l, *ahh, *ahl;
    bf16 *weh, *wel, *w1h, *w1l, *w2h, *w2l, *wfh, *wfl;
    cudaGetSymbolAddress((void**)&h,   g_h);
    cudaGetSymbolAddress((void**)&h2,  g_h2);
    cudaGetSymbolAddress((void**)&xh,  g_xh);  cudaGetSymbolAddress((void**)&xl,  g_xl);
    cudaGetSymbolAddress((void**)&hh,  g_hh);  cudaGetSymbolAddress((void**)&hl,  g_hl);
    cudaGetSymbolAddress((void**)&h2h, g_h2h); cudaGetSymbolAddress((void**)&h2l, g_h2l);
    cudaGetSymbolAddress((void**)&ahh, g_ahh); cudaGetSymbolAddress((void**)&ahl, g_ahl);
    cudaGetSymbolAddress((void**)&weh, g_weh); cudaGetSymbolAddress((void**)&wel, g_wel);
    cudaGetSymbolAddress((void**)&w1h, g_w1h); cudaGetSymbolAddress((void**)&w1l, g_w1l);
    cudaGetSymbolAddress((void**)&w2h, g_w2h); cudaGetSymbolAddress((void**)&w2l, g_w2l);
    cudaGetSymbolAddress((void**)&wfh, g_wfh); cudaGetSymbolAddress((void**)&wfl, g_wfl);

    const int SMEM = NSTG * STGB;  // 104448
    cudaFuncSetAttribute(mma_gemm_k<true,  true >, cudaFuncAttributeMaxDynamicSharedMemorySize, SMEM);
    cudaFuncSetAttribute(mma_gemm_k<false, true >, cudaFuncAttributeMaxDynamicSharedMemorySize, SMEM);
    cudaFuncSetAttribute(mma_gemm_k<false, false>, cudaFuncAttributeMaxDynamicSharedMemorySize, SMEM);

    const int MT = (NN + BM - 1) / BM;  // 139
    dim3 gHid(MT, HIDF / 128);          // 139 x 2 = 278 CTAs (one wave @2/SM)
    dim3 gOut(MT, OUTF / 128);          // 139 x 1
    dim3 gblk(5000), gthr(64, 4);

    // index-3 launch = emb GEMM (ncu capture slot)
    split_k<<<(NN * INF / 4 + 255) / 256, 256>>>(x, xh, xl, NN * INF);                 // 0
    split_k<<<(HIDF * INF / 4 + 255) / 256, 256>>>(W_emb, weh, wel, HIDF * INF);       // 1
    zero_cnt_k<<<(NN + 255) / 256, 256>>>();                                           // 2
    mma_gemm_k<false, true><<<gHid, 384, SMEM>>>(                                      // 3 (ncu)
        xh, xl, nullptr, nullptr, INF, weh, wel,
        nullptr, nullptr, h, hh, hl, NN, HIDF);
    count_k  <<<(EE + 255) / 256, 256>>>(edst);                                        // 4
    scan_k   <<<1, 1024>>>();                                                          // 5
    scatter_k<<<(EE + 255) / 256, 256>>>(esrc, edst, ew);                              // 6
    split3_k<<<((2 * HIDF * 2 * HIDF + OUTF * HIDF) / 4 + 255) / 256, 256>>>(          // 7
        W_gc1, w1h, w1l, HIDF * 2 * HIDF,
        W_gc2, w2h, w2l, HIDF * 2 * HIDF,
        W_fc,  wfh, wfl, OUTF * HIDF);

    // Ah = A @ h ; h2 = h + relu([h|Ah] @ W_gc1^T + b1)
    gather_k<<<gblk, gthr>>>(h, ahh, ahl);                                             // 8
    mma_gemm_k<true, true><<<gHid, 384, SMEM>>>(                                       // 9
        hh, hl, ahh, ahl, 2 * HIDF, w1h, w1l,
        b_gc1, h, h2, h2h, h2l, NN, HIDF);
    // Ah = A @ h2 ; h = h2 + relu([h2|Ah] @ W_gc2^T + b2)
    gather_k<<<gblk, gthr>>>(h2, ahh, ahl);                                            // 10
    mma_gemm_k<true, true><<<gHid, 384, SMEM>>>(                                       // 11
        h2h, h2l, ahh, ahl, 2 * HIDF, w2h, w2l,
        b_gc2, h2, h, hh, hl, NN, HIDF);
    // out = h @ W_fc^T ; rows L2-normalized
    mma_gemm_k<false, false><<<gOut, 384, SMEM>>>(                                     // 12
        hh, hl, nullptr, nullptr, HIDF, wfh, wfl,
        nullptr, nullptr, out, nullptr, nullptr, NN, OUTF);
    norm_k<<<(NN + 7) / 8, dim3(32, 8)>>>(out);                                        // 13
}

// round 11
// speedup vs baseline: 2.5727x; 1.0243x over previous
#include <cuda_runtime.h>
#include <cuda_bf16.h>
#include <cstdint>

#define NN   20000
#define EE   320000
#define INF  256
#define HIDF 256
#define OUTF 128
#define BM   144                 // M tile (9 x 16)
#define ABYT 9216                // 144 rows x 64B per A matrix
#define NSTG 4                   // cp.async ring depth

typedef __nv_bfloat16 bf16;

// ---------------- scratch (device globals; no allocation allowed) ------------
__device__ float g_h [NN * HIDF];
__device__ float g_h2[NN * HIDF];
__device__ bf16  g_xh [NN * HIDF], g_xl [NN * HIDF];
__device__ bf16  g_hh [NN * HIDF], g_hl [NN * HIDF];
__device__ bf16  g_h2h[NN * HIDF], g_h2l[NN * HIDF];
__device__ bf16  g_ahh[NN * HIDF], g_ahl[NN * HIDF];
__device__ bf16  g_weh[HIDF * INF],      g_wel[HIDF * INF];
__device__ bf16  g_w1h[HIDF * 2 * HIDF], g_w1l[HIDF * 2 * HIDF];
__device__ bf16  g_w2h[HIDF * 2 * HIDF], g_w2l[HIDF * 2 * HIDF];
__device__ bf16  g_wfh[OUTF * HIDF],     g_wfl[OUTF * HIDF];
__device__ int   g_cnt[NN];
__device__ int   g_off[NN + 1];
__device__ int   g_fill[NN];
__device__ int   g_csr_src[EE];
__device__ float g_csr_w[EE];

// ---------------- helpers ----------------------------------------------------
__device__ __forceinline__ uint32_t smem_u32(const void* p) {
    uint32_t a;
    asm("{ .reg .u64 t; cvta.to.shared.u64 t, %1; cvt.u32.u64 %0, t; }"
        : "=r"(a) : "l"(p));
    return a;
}

__device__ __forceinline__ void split2(float x, float y, uint32_t& hi, uint32_t& lo) {
    bf16 hx = __float2bfloat16_rn(x);
    bf16 hy = __float2bfloat16_rn(y);
    float rx = x - __bfloat162float(hx);
    float ry = y - __bfloat162float(hy);
    __nv_bfloat162 H; H.x = hx; H.y = hy;
    __nv_bfloat162 L = __floats2bfloat162_rn(rx, ry);
    hi = *reinterpret_cast<uint32_t*>(&H);
    lo = *reinterpret_cast<uint32_t*>(&L);
}

__device__ __forceinline__ void mma_bf16(float c[4],
                                         uint32_t a0, uint32_t a1, uint32_t a2, uint32_t a3,
                                         uint32_t b0, uint32_t b1) {
    asm volatile(
        "mma.sync.aligned.m16n8k16.row.col.f32.bf16.bf16.f32 "
        "{%0,%1,%2,%3}, {%4,%5,%6,%7}, {%8,%9}, {%0,%1,%2,%3};"
        : "+f"(c[0]), "+f"(c[1]), "+f"(c[2]), "+f"(c[3])
        : "r"(a0), "r"(a1), "r"(a2), "r"(a3), "r"(b0), "r"(b1));
}

#define LDSM_X4(r0, r1, r2, r3, addr) \
    asm volatile("ldmatrix.sync.aligned.m8n8.x4.shared.b16 {%0,%1,%2,%3}, [%4];" \
                 : "=r"(r0), "=r"(r1), "=r"(r2), "=r"(r3) : "r"(addr))

#define CP_ASYNC16(dst, src, sz) \
    asm volatile("cp.async.cg.shared.global [%0], [%1], 16, %2;" \
                 :: "r"(dst), "l"(src), "r"(sz) : "memory")

#define CP_COMMIT() asm volatile("cp.async.commit_group;" ::: "memory")

// XOR-swizzled offset of 16B chunk c in row r (row stride 64B data, no pad)
__device__ __forceinline__ uint32_t swz(int row, int chunk) {
    return (uint32_t)(row * 64 + ((chunk ^ ((row >> 1) & 3)) << 4));
}

// ---------------- fp32 -> bf16 hi/lo splits ----------------------------------
__global__ void split_k(const float* __restrict__ s, bf16* __restrict__ hi,
                        bf16* __restrict__ lo, int n) {
    int i = (blockIdx.x * blockDim.x + threadIdx.x) * 4;
    if (i >= n) return;
    float4 v = *(const float4*)(s + i);
    uint32_t h0, l0, h1, l1;
    split2(v.x, v.y, h0, l0);
    split2(v.z, v.w, h1, l1);
    *(uint2*)(hi + i) = make_uint2(h0, h1);
    *(uint2*)(lo + i) = make_uint2(l0, l1);
}

__global__ void split3_k(const float* __restrict__ s0, bf16* __restrict__ h0, bf16* __restrict__ l0, int n0,
                         const float* __restrict__ s1, bf16* __restrict__ h1, bf16* __restrict__ l1, int n1,
                         const float* __restrict__ s2, bf16* __restrict__ h2, bf16* __restrict__ l2, int n2) {
    int i = (blockIdx.x * blockDim.x + threadIdx.x) * 4;
    const float* s; bf16 *hh, *ll;
    if (i < n0)               { s = s0 + i;             hh = h0 + i;             ll = l0 + i; }
    else if (i < n0 + n1)     { s = s1 + (i - n0);      hh = h1 + (i - n0);      ll = l1 + (i - n0); }
    else if (i < n0 + n1 + n2){ s = s2 + (i - n0 - n1); hh = h2 + (i - n0 - n1); ll = l2 + (i - n0 - n1); }
    else return;
    float4 v = *(const float4*)s;
    uint32_t a, b, c, d;
    split2(v.x, v.y, a, b);
    split2(v.z, v.w, c, d);
    *(uint2*)hh = make_uint2(a, c);
    *(uint2*)ll = make_uint2(b, d);
}

// ---------------- CSR build --------------------------------------------------
__global__ void zero_cnt_k() {
    int i = blockIdx.x * blockDim.x + threadIdx.x;
    if (i < NN) g_cnt[i] = 0;
}

__global__ void count_k(const int* __restrict__ dst) {
    int e = blockIdx.x * blockDim.x + threadIdx.x;
    if (e < EE) atomicAdd(&g_cnt[dst[e]], 1);
}

__global__ void scan_k() {
    __shared__ int s[1024];
    __shared__ int carry;
    int tid = threadIdx.x;
    if (tid == 0) carry = 0;
    __syncthreads();
    for (int base = 0; base < NN; base += 1024) {
        int i = base + tid;
        int v = (i < NN) ? g_cnt[i] : 0;
        s[tid] = v;
        __syncthreads();
        #pragma unroll
        for (int off = 1; off < 1024; off <<= 1) {
            int t = 0;
            if (tid >= off) t = s[tid - off];
            __syncthreads();
            if (tid >= off) s[tid] += t;
            __syncthreads();
        }
        int incl  = s[tid];
        int cbase = carry;
        __syncthreads();
        if (i < NN) {
            int ex = cbase + incl - v;
            g_off[i]  = ex;
            g_fill[i] = ex;
        }
        __syncthreads();
        if (tid == 0) carry = cbase + s[1023];
        __syncthreads();
    }
    if (tid == 0) g_off[NN] = carry;
}

__global__ void scatter_k(const int* __restrict__ src, const int* __restrict__ dst,
                          const float* __restrict__ w) {
    int e = blockIdx.x * blockDim.x + threadIdx.x;
    if (e < EE) {
        int d = dst[e];
        int p = atomicAdd(&g_fill[d], 1);
        g_csr_src[p] = src[e];
        g_csr_w[p]   = w[e];
    }
}

// ---------------- adj_mul gather, 4-way unrolled (MLP>=4) --------------------
__global__ void gather_k(const float* __restrict__ h,
                         bf16* __restrict__ ahh, bf16* __restrict__ ahl) {
    int node = blockIdx.x * 4 + threadIdx.y;
    if (node >= NN) return;
    int beg = g_off[node], end = g_off[node + 1];
    const float4* __restrict__ H = (const float4*)h;
    int t = threadIdx.x;  // 0..63
    float ax = 0.f, ay = 0.f, az = 0.f, aw = 0.f;

    int k = beg;
    for (; k + 4 <= end; k += 4) {
        int   s0 = g_csr_src[k],     s1 = g_csr_src[k + 1];
        int   s2 = g_csr_src[k + 2], s3 = g_csr_src[k + 3];
        float w0 = g_csr_w[k],       w1 = g_csr_w[k + 1];
        float w2 = g_csr_w[k + 2],   w3 = g_csr_w[k + 3];
        float4 v0 = H[(size_t)s0 * 64 + t];
        float4 v1 = H[(size_t)s1 * 64 + t];
        float4 v2 = H[(size_t)s2 * 64 + t];
        float4 v3 = H[(size_t)s3 * 64 + t];
        ax = fmaf(v0.x, w0, fmaf(v1.x, w1, fmaf(v2.x, w2, fmaf(v3.x, w3, ax))));
        ay = fmaf(v0.y, w0, fmaf(v1.y, w1, fmaf(v2.y, w2, fmaf(v3.y, w3, ay))));
        az = fmaf(v0.z, w0, fmaf(v1.z, w1, fmaf(v2.z, w2, fmaf(v3.z, w3, az))));
        aw = fmaf(v0.w, w0, fmaf(v1.w, w1, fmaf(v2.w, w2, fmaf(v3.w, w3, aw))));
    }
    for (; k < end; ++k) {
        int s = g_csr_src[k];
        float w = g_csr_w[k];
        float4 v = H[(size_t)s * 64 + t];
        ax = fmaf(v.x, w, ax); ay = fmaf(v.y, w, ay);
        az = fmaf(v.z, w, az); aw = fmaf(v.w, w, aw);
    }
    uint32_t h0, l0, h1, l1;
    split2(ax, ay, h0, l0);
    split2(az, aw, h1, l1);
    ((uint2*)ahh)[(size_t)node * 64 + t] = make_uint2(h0, h1);
    ((uint2*)ahl)[(size_t)node * 64 + t] = make_uint2(l0, l1);
}

// ---------------- bf16x3 tensor-core GEMM: 144xBN tile, 1 CTA/SM -------------
// C = epi( [A1|A2] @ W^T ). A row stride 256. 384 threads, 12 warps (3x4),
// warp tile 48 x (BN/4), NT = BN/32 n-fragments. K staged 32-deep, 4-buffer
// cp.async ring with constant-3 outstanding groups. Grid 139 x 1 = one wave
// at 1 CTA/SM (smem-limited). Fat warp tiles cut smem LDS traffic ~1.5x.
template<int BN, bool FUSE, bool SPLIT>
__global__ __launch_bounds__(384)
void mma_gemm_k(const bf16* __restrict__ a1h, const bf16* __restrict__ a1l,
                const bf16* __restrict__ a2h, const bf16* __restrict__ a2l,
                int Ktot,
                const bf16* __restrict__ wh, const bf16* __restrict__ wl,
                const float* __restrict__ bias, const float* __restrict__ res,
                float* __restrict__ C, bf16* __restrict__ Chi, bf16* __restrict__ Clo,
                int M, int Ncols)
{
    constexpr int NT   = BN / 32;            // n-fragments per warp (8 or 4)
    constexpr int BBYT = BN * 64;            // bytes per B matrix tile
    constexpr int STGB = 2 * ABYT + 2 * BBYT;
    constexpr int NCHK = 1152 + 8 * BN;      // 16B chunks per stage
    constexpr int ITER = (NCHK + 383) / 384;

    extern __shared__ __align__(16) char smem[];
    const uint32_t sb = smem_u32(smem);
    const int tid  = threadIdx.x;
    const int lane = tid & 31, wid = tid >> 5;
    const int wm = wid >> 2, wn = wid & 3;     // 3 x 4 warp grid
    const int r = lane >> 2, q = lane & 3;
    const int ib = blockIdx.x * BM, jb = blockIdx.y * BN;
    const int S = Ktot / 32;

    const int aRow = wm * 48 + (lane & 15);
    const int bRow = wn * (BN / 4) + (lane & 7) + ((lane >> 4) << 3);
    const int aChk = (lane >> 4);
    const int bChk = ((lane >> 3) & 1);

    float acc[3][NT][4];
    #pragma unroll
    for (int a = 0; a < 3; ++a)
        #pragma unroll
        for (int b = 0; b < NT; ++b)
            #pragma unroll
            for (int c = 0; c < 4; ++c) acc[a][b][c] = 0.f;

    // async fill of stage s into ring buffer s % NSTG; always commits a group.
    auto fill = [&](int s) {
        if (s < S) {
            const int k0 = s * 32;
            const uint32_t stb = sb + (s % NSTG) * STGB;
            #pragma unroll
            for (int i = 0; i < ITER; ++i) {
                int g = i * 384 + tid;
                if (g < NCHK) {
                    if (g < 1152) {
                        int mat = (g >= 576);
                        int idx = g - mat * 576;
                        int row = idx >> 2, c = idx & 3;
                        uint32_t dst = stb + mat * ABYT + swz(row, c);
                        const bf16* a = (k0 < 256) ? (mat ? a1l : a1h)
                                                   : (mat ? a2l : a2h);
                        int gr = ib + row, sz = 16;
                        if (gr >= M) { gr = 0; sz = 0; }
                        CP_ASYNC16(dst, a + (size_t)gr * 256 + (k0 & 255) + c * 8, sz);
                    } else {
                        int g2 = g - 1152;
                        int mat = (g2 >= 4 * BN);
                        int idx = g2 - mat * 4 * BN;
                        int row = idx >> 2, c = idx & 3;
                        uint32_t dst = stb + 2 * ABYT + mat * BBYT + swz(row, c);
                        const bf16* w = mat ? wl : wh;
                        CP_ASYNC16(dst, w + (size_t)(jb + row) * Ktot + k0 + c * 8, 16);
                    }
                }
            }
        }
        CP_COMMIT();
    };

    fill(0); fill(1); fill(2);          // 3 groups outstanding

    for (int s = 0; s < S; ++s) {
        asm volatile("cp.async.wait_group 2;" ::: "memory");  // fill(s) done
        __syncthreads();
        fill(s + 3);                    // ring (s+3)%4 = stage s-1's buffer

        const uint32_t stb = sb + (s % NSTG) * STGB;
        const uint32_t ahB = stb;
        const uint32_t alB = stb + ABYT;
        const uint32_t bhB = stb + 2 * ABYT;
        const uint32_t blB = stb + 2 * ABYT + BBYT;

        #pragma unroll
        for (int ks = 0; ks < 2; ++ks) {
            const int aChunk = ks * 2 + aChk;
            const int bChunk = ks * 2 + bChk;

            // B fragments resident: BH + BL = 2*NT regs each pair
            uint32_t BH[NT][2], BL[NT][2];
            #pragma unroll
            for (int p = 0; p < NT / 2; ++p) {
                uint32_t bd = bhB + swz(bRow + p * 16, bChunk);
                LDSM_X4(BH[2*p][0], BH[2*p][1], BH[2*p+1][0], BH[2*p+1][1], bd);
            }
            #pragma unroll
            for (int p = 0; p < NT / 2; ++p) {
                uint32_t bd = blB + swz(bRow + p * 16, bChunk);
                LDSM_X4(BL[2*p][0], BL[2*p][1], BL[2*p+1][0], BL[2*p+1][1], bd);
            }

            // stream A one mt-row at a time: 4 regs, reused for hi then lo
            #pragma unroll
            for (int mt = 0; mt < 3; ++mt) {
                uint32_t A0, A1, A2, A3;
                LDSM_X4(A0, A1, A2, A3, ahB + swz(aRow + mt * 16, aChunk));
                #pragma unroll
                for (int nt = 0; nt < NT; ++nt)
                    mma_bf16(acc[mt][nt], A0, A1, A2, A3, BH[nt][0], BH[nt][1]);
                #pragma unroll
                for (int nt = 0; nt < NT; ++nt)
                    mma_bf16(acc[mt][nt], A0, A1, A2, A3, BL[nt][0], BL[nt][1]);
                LDSM_X4(A0, A1, A2, A3, alB + swz(aRow + mt * 16, aChunk));
                #pragma unroll
                for (int nt = 0; nt < NT; ++nt)
                    mma_bf16(acc[mt][nt], A0, A1, A2, A3, BH[nt][0], BH[nt][1]);
            }
        }
    }

    // ---------------- epilogue ----------------
    #pragma unroll
    for (int mt = 0; mt < 3; ++mt) {
        #pragma unroll
        for (int nt = 0; nt < NT; ++nt) {
            int row0 = ib + wm * 48 + mt * 16 + r;
            int col  = jb + wn * (BN / 4) + nt * 8 + 2 * q;
            float2 b2 = make_float2(0.f, 0.f);
            if (FUSE) b2 = *(const float2*)&bias[col];
            #pragma unroll
            for (int hf = 0; hf < 2; ++hf) {
                int row = row0 + 8 * hf;
                if (row >= M) continue;
                float o0 = acc[mt][nt][2 * hf + 0];
                float o1 = acc[mt][nt][2 * hf + 1];
                if (FUSE) {
                    float2 rv = *(const float2*)&res[(size_t)row * Ncols + col];
                    o0 = rv.x + fmaxf(o0 + b2.x, 0.f);
                    o1 = rv.y + fmaxf(o1 + b2.y, 0.f);
                }
                *(float2*)&C[(size_t)row * Ncols + col] = make_float2(o0, o1);
                if (SPLIT) {
                    uint32_t hi, lo;
                    split2(o0, o1, hi, lo);
                    *(uint32_t*)(Chi + (size_t)row * Ncols + col) = hi;
                    *(uint32_t*)(Clo + (size_t)row * Ncols + col) = lo;
                }
            }
        }
    }
}

// ---------------- row L2-normalize (128 cols): one warp per row --------------
__global__ void norm_k(float* __restrict__ out) {
    int row = blockIdx.x * 8 + threadIdx.y;  // blockDim (32,8)
    if (row >= NN) return;
    float4* p = (float4*)out + (size_t)row * 32 + threadIdx.x;
    float4 v = *p;
    float s = v.x * v.x + v.y * v.y + v.z * v.z + v.w * v.w;
    #pragma unroll
    for (int off = 16; off > 0; off >>= 1)
        s += __shfl_xor_sync(0xFFFFFFFFu, s, off);
    float r = rsqrtf(s);
    v.x *= r; v.y *= r; v.z *= r; v.w *= r;
    *p = v;
}

// ---------------- launch -----------------------------------------------------
extern "C" void kernel_launch(void* const* d_in, const int* in_sizes, int n_in,
                              void* d_out, int out_size) {
    const float* x     = (const float*)d_in[0];
    const int*   esrc  = (const int*)  d_in[1];
    const int*   edst  = (const int*)  d_in[2];
    const float* ew    = (const float*)d_in[3];
    const float* W_emb = (const float*)d_in[4];
    const float* W_gc1 = (const float*)d_in[5];
    const float* b_gc1 = (const float*)d_in[6];
    const float* W_gc2 = (const float*)d_in[7];
    const float* b_gc2 = (const float*)d_in[8];
    const float* W_fc  = (const float*)d_in[9];
    float* out = (float*)d_out;

    float *h, *h2;
    bf16 *xh, *xl, *hh, *hl, *h2h, *h2l, *ahh, *ahl;
    bf16 *weh, *wel, *w1h, *w1l, *w2h, *w2l, *wfh, *wfl;
    cudaGetSymbolAddress((void**)&h,   g_h);
    cudaGetSymbolAddress((void**)&h2,  g_h2);
    cudaGetSymbolAddress((void**)&xh,  g_xh);  cudaGetSymbolAddress((void**)&xl,  g_xl);
    cudaGetSymbolAddress((void**)&hh,  g_hh);  cudaGetSymbolAddress((void**)&hl,  g_hl);
    cudaGetSymbolAddress((void**)&h2h, g_h2h); cudaGetSymbolAddress((void**)&h2l, g_h2l);
    cudaGetSymbolAddress((void**)&ahh, g_ahh); cudaGetSymbolAddress((void**)&ahl, g_ahl);
    cudaGetSymbolAddress((void**)&weh, g_weh); cudaGetSymbolAddress((void**)&wel, g_wel);
    cudaGetSymbolAddress((void**)&w1h, g_w1h); cudaGetSymbolAddress((void**)&w1l, g_w1l);
    cudaGetSymbolAddress((void**)&w2h, g_w2h); cudaGetSymbolAddress((void**)&w2l, g_w2l);
    cudaGetSymbolAddress((void**)&wfh, g_wfh); cudaGetSymbolAddress((void**)&wfl, g_wfl);

    const int SMEM256 = NSTG * (2 * ABYT + 2 * 256 * 64);  // 204800
    const int SMEM128 = NSTG * (2 * ABYT + 2 * 128 * 64);  // 139264
    cudaFuncSetAttribute(mma_gemm_k<256, true,  true >, cudaFuncAttributeMaxDynamicSharedMemorySize, SMEM256);
    cudaFuncSetAttribute(mma_gemm_k<256, false, true >, cudaFuncAttributeMaxDynamicSharedMemorySize, SMEM256);
    cudaFuncSetAttribute(mma_gemm_k<128, false, false>, cudaFuncAttributeMaxDynamicSharedMemorySize, SMEM128);

    const int MT = (NN + BM - 1) / BM;  // 139 -> one wave at 1 CTA/SM
    dim3 gHid(MT, 1);
    dim3 gOut(MT, 1);
    dim3 gblk(5000), gthr(64, 4);

    // index-3 launch = emb GEMM (ncu capture slot)
    split_k<<<(NN * INF / 4 + 255) / 256, 256>>>(x, xh, xl, NN * INF);                 // 0
    split_k<<<(HIDF * INF / 4 + 255) / 256, 256>>>(W_emb, weh, wel, HIDF * INF);       // 1
    zero_cnt_k<<<(NN + 255) / 256, 256>>>();                                           // 2
    mma_gemm_k<256, false, true><<<gHid, 384, SMEM256>>>(                              // 3 (ncu)
        xh, xl, nullptr, nullptr, INF, weh, wel,
        nullptr, nullptr, h, hh, hl, NN, HIDF);
    count_k  <<<(EE + 255) / 256, 256>>>(edst);                                        // 4
    scan_k   <<<1, 1024>>>();                                                          // 5
    scatter_k<<<(EE + 255) / 256, 256>>>(esrc, edst, ew);                              // 6
    split3_k<<<((2 * HIDF * 2 * HIDF + OUTF * HIDF) / 4 + 255) / 256, 256>>>(          // 7
        W_gc1, w1h, w1l, HIDF * 2 * HIDF,
        W_gc2, w2h, w2l, HIDF * 2 * HIDF,
        W_fc,  wfh, wfl, OUTF * HIDF);

    // Ah = A @ h ; h2 = h + relu([h|Ah] @ W_gc1^T + b1)
    gather_k<<<gblk, gthr>>>(h, ahh, ahl);                                             // 8
    mma_gemm_k<256, true, true><<<gHid, 384, SMEM256>>>(                               // 9
        hh, hl, ahh, ahl, 2 * HIDF, w1h, w1l,
        b_gc1, h, h2, h2h, h2l, NN, HIDF);
    // Ah = A @ h2 ; h = h2 + relu([h2|Ah] @ W_gc2^T + b2)
    gather_k<<<gblk, gthr>>>(h2, ahh, ahl);                                            // 10
    mma_gemm_k<256, true, true><<<gHid, 384, SMEM256>>>(                               // 11
        h2h, h2l, ahh, ahl, 2 * HIDF, w2h, w2l,
        b_gc2, h2, h, hh, hl, NN, HIDF);
    // out = h @ W_fc^T ; rows L2-normalized
    mma_gemm_k<128, false, false><<<gOut, 384, SMEM128>>>(                             // 12
        hh, hl, nullptr, nullptr, HIDF, wfh, wfl,
        nullptr, nullptr, out, nullptr, nullptr, NN, OUTF);
    norm_k<<<(NN + 7) / 8, dim3(32, 8)>>>(out);                                        // 13
}

// round 12
// speedup vs baseline: 3.0199x; 1.1738x over previous
#include <cuda_runtime.h>
#include <cuda_fp16.h>
#include <cstdint>

#define NN   20000
#define EE   320000
#define INF  256
#define HIDF 256
#define OUTF 128
#define BM   144                 // M tile (9 x 16)
#define ABYT 9216                // 144 rows x 64B per A matrix
#define NSTG 4                   // cp.async ring depth

typedef __half f16;

// ---------------- scratch (device globals; no allocation allowed) ------------
__device__ float g_h [NN * HIDF];
__device__ float g_h2[NN * HIDF];
__device__ f16   g_xh [NN * HIDF], g_xl [NN * HIDF];
__device__ f16   g_hh [NN * HIDF], g_hl [NN * HIDF];
__device__ f16   g_h2h[NN * HIDF], g_h2l[NN * HIDF];
__device__ f16   g_ahh[NN * HIDF], g_ahl[NN * HIDF];
__device__ f16   g_we[HIDF * INF];
__device__ f16   g_w1[HIDF * 2 * HIDF];
__device__ f16   g_w2[HIDF * 2 * HIDF];
__device__ f16   g_wf[OUTF * HIDF];
__device__ int   g_cnt[NN];
__device__ int   g_off[NN + 1];
__device__ int   g_fill[NN];
__device__ int   g_csr_src[EE];
__device__ float g_csr_w[EE];

// ---------------- helpers ----------------------------------------------------
__device__ __forceinline__ uint32_t smem_u32(const void* p) {
    uint32_t a;
    asm("{ .reg .u64 t; cvta.to.shared.u64 t, %1; cvt.u32.u64 %0, t; }"
        : "=r"(a) : "l"(p));
    return a;
}

// fp16 hi/lo split of two fp32 values, packed as half2 words
__device__ __forceinline__ void split2h(float x, float y, uint32_t& hi, uint32_t& lo) {
    f16 hx = __float2half_rn(x);
    f16 hy = __float2half_rn(y);
    float rx = x - __half2float(hx);
    float ry = y - __half2float(hy);
    __half2 H = __halves2half2(hx, hy);
    __half2 L = __floats2half2_rn(rx, ry);
    hi = *reinterpret_cast<uint32_t*>(&H);
    lo = *reinterpret_cast<uint32_t*>(&L);
}

__device__ __forceinline__ void mma_f16(float c[4],
                                        uint32_t a0, uint32_t a1, uint32_t a2, uint32_t a3,
                                        uint32_t b0, uint32_t b1) {
    asm volatile(
        "mma.sync.aligned.m16n8k16.row.col.f32.f16.f16.f32 "
        "{%0,%1,%2,%3}, {%4,%5,%6,%7}, {%8,%9}, {%0,%1,%2,%3};"
        : "+f"(c[0]), "+f"(c[1]), "+f"(c[2]), "+f"(c[3])
        : "r"(a0), "r"(a1), "r"(a2), "r"(a3), "r"(b0), "r"(b1));
}

#define LDSM_X4(r0, r1, r2, r3, addr) \
    asm volatile("ldmatrix.sync.aligned.m8n8.x4.shared.b16 {%0,%1,%2,%3}, [%4];" \
                 : "=r"(r0), "=r"(r1), "=r"(r2), "=r"(r3) : "r"(addr))

#define CP_ASYNC16(dst, src, sz) \
    asm volatile("cp.async.cg.shared.global [%0], [%1], 16, %2;" \
                 :: "r"(dst), "l"(src), "r"(sz) : "memory")

#define CP_COMMIT() asm volatile("cp.async.commit_group;" ::: "memory")

// XOR-swizzled offset of 16B chunk c in row r (row stride 64B data, no pad)
__device__ __forceinline__ uint32_t swz(int row, int chunk) {
    return (uint32_t)(row * 64 + ((chunk ^ ((row >> 1) & 3)) << 4));
}

// ---------------- fp32 -> fp16 hi/lo split (activations) ---------------------
__global__ void split_k(const float* __restrict__ s, f16* __restrict__ hi,
                        f16* __restrict__ lo, int n) {
    int i = (blockIdx.x * blockDim.x + threadIdx.x) * 4;
    if (i >= n) return;
    float4 v = *(const float4*)(s + i);
    uint32_t h0, l0, h1, l1;
    split2h(v.x, v.y, h0, l0);
    split2h(v.z, v.w, h1, l1);
    *(uint2*)(hi + i) = make_uint2(h0, h1);
    *(uint2*)(lo + i) = make_uint2(l0, l1);
}

// fp32 -> fp16 convert of all four weight matrices in one launch
__global__ void wcvt_k(const float* __restrict__ s0, f16* __restrict__ d0, int n0,
                       const float* __restrict__ s1, f16* __restrict__ d1, int n1,
                       const float* __restrict__ s2, f16* __restrict__ d2, int n2,
                       const float* __restrict__ s3, f16* __restrict__ d3, int n3) {
    int i = (blockIdx.x * blockDim.x + threadIdx.x) * 4;
    const float* s; f16* d;
    if (i < n0)                    { s = s0 + i;                  d = d0 + i; }
    else if (i < n0 + n1)          { s = s1 + (i - n0);           d = d1 + (i - n0); }
    else if (i < n0 + n1 + n2)     { s = s2 + (i - n0 - n1);      d = d2 + (i - n0 - n1); }
    else if (i < n0 + n1 + n2 + n3){ s = s3 + (i - n0 - n1 - n2); d = d3 + (i - n0 - n1 - n2); }
    else return;
    float4 v = *(const float4*)s;
    __half2 a = __floats2half2_rn(v.x, v.y);
    __half2 b = __floats2half2_rn(v.z, v.w);
    *(uint2*)d = make_uint2(*reinterpret_cast<uint32_t*>(&a),
                            *reinterpret_cast<uint32_t*>(&b));
}

// ---------------- CSR build --------------------------------------------------
__global__ void zero_cnt_k() {
    int i = blockIdx.x * blockDim.x + threadIdx.x;
    if (i < NN) g_cnt[i] = 0;
}

__global__ void count_k(const int* __restrict__ dst) {
    int e = blockIdx.x * blockDim.x + threadIdx.x;
    if (e < EE) atomicAdd(&g_cnt[dst[e]], 1);
}

__global__ void scan_k() {
    __shared__ int s[1024];
    __shared__ int carry;
    int tid = threadIdx.x;
    if (tid == 0) carry = 0;
    __syncthreads();
    for (int base = 0; base < NN; base += 1024) {
        int i = base + tid;
        int v = (i < NN) ? g_cnt[i] : 0;
        s[tid] = v;
        __syncthreads();
        #pragma unroll
        for (int off = 1; off < 1024; off <<= 1) {
            int t = 0;
            if (tid >= off) t = s[tid - off];
            __syncthreads();
            if (tid >= off) s[tid] += t;
            __syncthreads();
        }
        int incl  = s[tid];
        int cbase = carry;
        __syncthreads();
        if (i < NN) {
            int ex = cbase + incl - v;
            g_off[i]  = ex;
            g_fill[i] = ex;
        }
        __syncthreads();
        if (tid == 0) carry = cbase + s[1023];
        __syncthreads();
    }
    if (tid == 0) g_off[NN] = carry;
}

__global__ void scatter_k(const int* __restrict__ src, const int* __restrict__ dst,
                          const float* __restrict__ w) {
    int e = blockIdx.x * blockDim.x + threadIdx.x;
    if (e < EE) {
        int d = dst[e];
        int p = atomicAdd(&g_fill[d], 1);
        g_csr_src[p] = src[e];
        g_csr_w[p]   = w[e];
    }
}

// ---------------- adj_mul gather, 4-way unrolled (MLP>=4) --------------------
__global__ void gather_k(const float* __restrict__ h,
                         f16* __restrict__ ahh, f16* __restrict__ ahl) {
    int node = blockIdx.x * 4 + threadIdx.y;
    if (node >= NN) return;
    int beg = g_off[node], end = g_off[node + 1];
    const float4* __restrict__ H = (const float4*)h;
    int t = threadIdx.x;  // 0..63
    float ax = 0.f, ay = 0.f, az = 0.f, aw = 0.f;

    int k = beg;
    for (; k + 4 <= end; k += 4) {
        int   s0 = g_csr_src[k],     s1 = g_csr_src[k + 1];
        int   s2 = g_csr_src[k + 2], s3 = g_csr_src[k + 3];
        float w0 = g_csr_w[k],       w1 = g_csr_w[k + 1];
        float w2 = g_csr_w[k + 2],   w3 = g_csr_w[k + 3];
        float4 v0 = H[(size_t)s0 * 64 + t];
        float4 v1 = H[(size_t)s1 * 64 + t];
        float4 v2 = H[(size_t)s2 * 64 + t];
        float4 v3 = H[(size_t)s3 * 64 + t];
        ax = fmaf(v0.x, w0, fmaf(v1.x, w1, fmaf(v2.x, w2, fmaf(v3.x, w3, ax))));
        ay = fmaf(v0.y, w0, fmaf(v1.y, w1, fmaf(v2.y, w2, fmaf(v3.y, w3, ay))));
        az = fmaf(v0.z, w0, fmaf(v1.z, w1, fmaf(v2.z, w2, fmaf(v3.z, w3, az))));
        aw = fmaf(v0.w, w0, fmaf(v1.w, w1, fmaf(v2.w, w2, fmaf(v3.w, w3, aw))));
    }
    for (; k < end; ++k) {
        int s = g_csr_src[k];
        float w = g_csr_w[k];
        float4 v = H[(size_t)s * 64 + t];
        ax = fmaf(v.x, w, ax); ay = fmaf(v.y, w, ay);
        az = fmaf(v.z, w, az); aw = fmaf(v.w, w, aw);
    }
    uint32_t h0, l0, h1, l1;
    split2h(ax, ay, h0, l0);
    split2h(az, aw, h1, l1);
    ((uint2*)ahh)[(size_t)node * 64 + t] = make_uint2(h0, h1);
    ((uint2*)ahl)[(size_t)node * 64 + t] = make_uint2(l0, l1);
}

// ---------------- fp16x2 tensor-core GEMM: 144xBN tile, 1 CTA/SM -------------
// C = epi( [A1|A2] @ Wh^T ), A = exact fp16 hi+lo split, W = fp16(W).
// 2 products per fragment: Ah*Bh + Al*Bh  (error ~ A*(W - fp16(W)) ~ 2^-11).
// 384 threads, 12 warps (3x4), warp tile 48 x (BN/4). 4-buffer cp.async ring.
template<int BN, bool FUSE, bool SPLIT>
__global__ __launch_bounds__(384)
void mma_gemm_k(const f16* __restrict__ a1h, const f16* __restrict__ a1l,
                const f16* __restrict__ a2h, const f16* __restrict__ a2l,
                int Ktot,
                const f16* __restrict__ wh,
                const float* __restrict__ bias, const float* __restrict__ res,
                float* __restrict__ C, f16* __restrict__ Chi, f16* __restrict__ Clo,
                int M, int Ncols)
{
    constexpr int NT   = BN / 32;            // n-fragments per warp (8 or 4)
    constexpr int BBYT = BN * 64;            // bytes for B hi tile
    constexpr int STGB = 2 * ABYT + BBYT;    // AH | AL | BH
    constexpr int NCHK = 1152 + 4 * BN;      // 16B chunks per stage
    constexpr int ITER = (NCHK + 383) / 384;

    extern __shared__ __align__(16) char smem[];
    const uint32_t sb = smem_u32(smem);
    const int tid  = threadIdx.x;
    const int lane = tid & 31, wid = tid >> 5;
    const int wm = wid >> 2, wn = wid & 3;     // 3 x 4 warp grid
    const int r = lane >> 2, q = lane & 3;
    const int ib = blockIdx.x * BM, jb = blockIdx.y * BN;
    const int S = Ktot / 32;

    const int aRow = wm * 48 + (lane & 15);
    const int bRow = wn * (BN / 4) + (lane & 7) + ((lane >> 4) << 3);
    const int aChk = (lane >> 4);
    const int bChk = ((lane >> 3) & 1);

    float acc[3][NT][4];
    #pragma unroll
    for (int a = 0; a < 3; ++a)
        #pragma unroll
        for (int b = 0; b < NT; ++b)
            #pragma unroll
            for (int c = 0; c < 4; ++c) acc[a][b][c] = 0.f;

    // async fill of stage s into ring buffer s % NSTG; always commits a group.
    auto fill = [&](int s) {
        if (s < S) {
            const int k0 = s * 32;
            const uint32_t stb = sb + (s % NSTG) * STGB;
            #pragma unroll
            for (int i = 0; i < ITER; ++i) {
                int g = i * 384 + tid;
                if (g < NCHK) {
                    if (g < 1152) {
                        int mat = (g >= 576);
                        int idx = g - mat * 576;
                        int row = idx >> 2, c = idx & 3;
                        uint32_t dst = stb + mat * ABYT + swz(row, c);
                        const f16* a = (k0 < 256) ? (mat ? a1l : a1h)
                                                  : (mat ? a2l : a2h);
                        int gr = ib + row, sz = 16;
                        if (gr >= M) { gr = 0; sz = 0; }
                        CP_ASYNC16(dst, a + (size_t)gr * 256 + (k0 & 255) + c * 8, sz);
                    } else {
                        int idx = g - 1152;
                        int row = idx >> 2, c = idx & 3;
                        uint32_t dst = stb + 2 * ABYT + swz(row, c);
                        CP_ASYNC16(dst, wh + (size_t)(jb + row) * Ktot + k0 + c * 8, 16);
                    }
                }
            }
        }
        CP_COMMIT();
    };

    fill(0); fill(1); fill(2);          // 3 groups outstanding

    for (int s = 0; s < S; ++s) {
        asm volatile("cp.async.wait_group 2;" ::: "memory");  // fill(s) done
        __syncthreads();
        fill(s + 3);                    // ring (s+3)%4 = stage s-1's buffer

        const uint32_t stb = sb + (s % NSTG) * STGB;
        const uint32_t ahB = stb;
        const uint32_t alB = stb + ABYT;
        const uint32_t bhB = stb + 2 * ABYT;

        #pragma unroll
        for (int ks = 0; ks < 2; ++ks) {
            const int aChunk = ks * 2 + aChk;
            const int bChunk = ks * 2 + bChk;

            // B hi fragments resident: 2*NT regs
            uint32_t BH[NT][2];
            #pragma unroll
            for (int p = 0; p < NT / 2; ++p) {
                uint32_t bd = bhB + swz(bRow + p * 16, bChunk);
                LDSM_X4(BH[2*p][0], BH[2*p][1], BH[2*p+1][0], BH[2*p+1][1], bd);
            }

            // stream A one mt-row at a time: 4 regs, hi then lo
            #pragma unroll
            for (int mt = 0; mt < 3; ++mt) {
                uint32_t A0, A1, A2, A3;
                LDSM_X4(A0, A1, A2, A3, ahB + swz(aRow + mt * 16, aChunk));
                #pragma unroll
                for (int nt = 0; nt < NT; ++nt)
                    mma_f16(acc[mt][nt], A0, A1, A2, A3, BH[nt][0], BH[nt][1]);
                LDSM_X4(A0, A1, A2, A3, alB + swz(aRow + mt * 16, aChunk));
                #pragma unroll
                for (int nt = 0; nt < NT; ++nt)
                    mma_f16(acc[mt][nt], A0, A1, A2, A3, BH[nt][0], BH[nt][1]);
            }
        }
    }

    // ---------------- epilogue ----------------
    #pragma unroll
    for (int mt = 0; mt < 3; ++mt) {
        #pragma unroll
        for (int nt = 0; nt < NT; ++nt) {
            int row0 = ib + wm * 48 + mt * 16 + r;
            int col  = jb + wn * (BN / 4) + nt * 8 + 2 * q;
            float2 b2 = make_float2(0.f, 0.f);
            if (FUSE) b2 = *(const float2*)&bias[col];
            #pragma unroll
            for (int hf = 0; hf < 2; ++hf) {
                int row = row0 + 8 * hf;
                if (row >= M) continue;
                float o0 = acc[mt][nt][2 * hf + 0];
                float o1 = acc[mt][nt][2 * hf + 1];
                if (FUSE) {
                    float2 rv = *(const float2*)&res[(size_t)row * Ncols + col];
                    o0 = rv.x + fmaxf(o0 + b2.x, 0.f);
                    o1 = rv.y + fmaxf(o1 + b2.y, 0.f);
                }
                *(float2*)&C[(size_t)row * Ncols + col] = make_float2(o0, o1);
                if (SPLIT) {
                    uint32_t hi, lo;
                    split2h(o0, o1, hi, lo);
                    *(uint32_t*)(Chi + (size_t)row * Ncols + col) = hi;
                    *(uint32_t*)(Clo + (size_t)row * Ncols + col) = lo;
                }
            }
        }
    }
}

// ---------------- row L2-normalize (128 cols): one warp per row --------------
__global__ void norm_k(float* __restrict__ out) {
    int row = blockIdx.x * 8 + threadIdx.y;  // blockDim (32,8)
    if (row >= NN) return;
    float4* p = (float4*)out + (size_t)row * 32 + threadIdx.x;
    float4 v = *p;
    float s = v.x * v.x + v.y * v.y + v.z * v.z + v.w * v.w;
    #pragma unroll
    for (int off = 16; off > 0; off >>= 1)
        s += __shfl_xor_sync(0xFFFFFFFFu, s, off);
    float r = rsqrtf(s);
    v.x *= r; v.y *= r; v.z *= r; v.w *= r;
    *p = v;
}

// ---------------- launch -----------------------------------------------------
extern "C" void kernel_launch(void* const* d_in, const int* in_sizes, int n_in,
                              void* d_out, int out_size) {
    const float* x     = (const float*)d_in[0];
    const int*   esrc  = (const int*)  d_in[1];
    const int*   edst  = (const int*)  d_in[2];
    const float* ew    = (const float*)d_in[3];
    const float* W_emb = (const float*)d_in[4];
    const float* W_gc1 = (const float*)d_in[5];
    const float* b_gc1 = (const float*)d_in[6];
    const float* W_gc2 = (const float*)d_in[7];
    const float* b_gc2 = (const float*)d_in[8];
    const float* W_fc  = (const float*)d_in[9];
    float* out = (float*)d_out;

    float *h, *h2;
    f16 *xh, *xl, *hh, *hl, *h2h, *h2l, *ahh, *ahl;
    f16 *we, *w1, *w2, *wf;
    cudaGetSymbolAddress((void**)&h,   g_h);
    cudaGetSymbolAddress((void**)&h2,  g_h2);
    cudaGetSymbolAddress((void**)&xh,  g_xh);  cudaGetSymbolAddress((void**)&xl,  g_xl);
    cudaGetSymbolAddress((void**)&hh,  g_hh);  cudaGetSymbolAddress((void**)&hl,  g_hl);
    cudaGetSymbolAddress((void**)&h2h, g_h2h); cudaGetSymbolAddress((void**)&h2l, g_h2l);
    cudaGetSymbolAddress((void**)&ahh, g_ahh); cudaGetSymbolAddress((void**)&ahl, g_ahl);
    cudaGetSymbolAddress((void**)&we,  g_we);
    cudaGetSymbolAddress((void**)&w1,  g_w1);
    cudaGetSymbolAddress((void**)&w2,  g_w2);
    cudaGetSymbolAddress((void**)&wf,  g_wf);

    const int SMEM256 = NSTG * (2 * ABYT + 256 * 64);  // 139264
    const int SMEM128 = NSTG * (2 * ABYT + 128 * 64);  // 106496
    cudaFuncSetAttribute(mma_gemm_k<256, true,  true >, cudaFuncAttributeMaxDynamicSharedMemorySize, SMEM256);
    cudaFuncSetAttribute(mma_gemm_k<256, false, true >, cudaFuncAttributeMaxDynamicSharedMemorySize, SMEM256);
    cudaFuncSetAttribute(mma_gemm_k<128, false, false>, cudaFuncAttributeMaxDynamicSharedMemorySize, SMEM128);

    const int MT = (NN + BM - 1) / BM;  // 139 -> one wave at 1 CTA/SM
    dim3 gHid(MT, 1);
    dim3 gOut(MT, 1);
    dim3 gblk(5000), gthr(64, 4);

    const int NW = HIDF * INF + 2 * (HIDF * 2 * HIDF) + OUTF * HIDF;

    // index-3 launch = emb GEMM (ncu capture slot)
    split_k<<<(NN * INF / 4 + 255) / 256, 256>>>(x, xh, xl, NN * INF);                 // 0
    wcvt_k<<<(NW / 4 + 255) / 256, 256>>>(                                             // 1
        W_emb, we, HIDF * INF,
        W_gc1, w1, HIDF * 2 * HIDF,
        W_gc2, w2, HIDF * 2 * HIDF,
        W_fc,  wf, OUTF * HIDF);
    zero_cnt_k<<<(NN + 255) / 256, 256>>>();                                           // 2
    mma_gemm_k<256, false, true><<<gHid, 384, SMEM256>>>(                              // 3 (ncu)
        xh, xl, nullptr, nullptr, INF, we,
        nullptr, nullptr, h, hh, hl, NN, HIDF);
    count_k  <<<(EE + 255) / 256, 256>>>(edst);                                        // 4
    scan_k   <<<1, 1024>>>();                                                          // 5
    scatter_k<<<(EE + 255) / 256, 256>>>(esrc, edst, ew);                              // 6

    // Ah = A @ h ; h2 = h + relu([h|Ah] @ W_gc1^T + b1)
    gather_k<<<gblk, gthr>>>(h, ahh, ahl);                                             // 7
    mma_gemm_k<256, true, true><<<gHid, 384, SMEM256>>>(                               // 8
        hh, hl, ahh, ahl, 2 * HIDF, w1,
        b_gc1, h, h2, h2h, h2l, NN, HIDF);
    // Ah = A @ h2 ; h = h2 + relu([h2|Ah] @ W_gc2^T + b2)
    gather_k<<<gblk, gthr>>>(h2, ahh, ahl);                                            // 9
    mma_gemm_k<256, true, true><<<gHid, 384, SMEM256>>>(                               // 10
        h2h, h2l, ahh, ahl, 2 * HIDF, w2,
        b_gc2, h2, h, hh, hl, NN, HIDF);
    // out = h @ W_fc^T ; rows L2-normalized
    mma_gemm_k<128, false, false><<<gOut, 384, SMEM128>>>(                             // 11
        hh, hl, nullptr, nullptr, HIDF, wf,
        nullptr, nullptr, out, nullptr, nullptr, NN, OUTF);
    norm_k<<<(NN + 7) / 8, dim3(32, 8)>>>(out);                                        // 12
}

// round 13
// speedup vs baseline: 3.5492x; 1.1753x over previous
#include <cuda_runtime.h>
#include <cuda_fp16.h>
#include <cstdint>

#define NN   20000
#define EE   320000
#define INF  256
#define HIDF 256
#define OUTF 128
#define BM   144                 // M tile (9 x 16)
#define ABYT 9216                // 144 rows x 64B per A matrix
#define NSTG 4                   // cp.async ring depth

typedef __half f16;

// ---------------- scratch (device globals; no allocation allowed) ------------
__device__ float g_h [NN * HIDF];
__device__ float g_h2[NN * HIDF];
__device__ f16   g_xh [NN * HIDF], g_xl [NN * HIDF];
__device__ f16   g_hh [NN * HIDF], g_hl [NN * HIDF];
__device__ f16   g_h2h[NN * HIDF], g_h2l[NN * HIDF];
__device__ f16   g_ahh[NN * HIDF], g_ahl[NN * HIDF];
__device__ f16   g_we[HIDF * INF];
__device__ f16   g_w1[HIDF * 2 * HIDF];
__device__ f16   g_w2[HIDF * 2 * HIDF];
__device__ f16   g_wf[OUTF * HIDF];
__device__ int   g_cnt[NN];
__device__ int   g_off[NN + 1];
__device__ int   g_fill[NN];
__device__ int   g_csr_src[EE];
__device__ float g_csr_w[EE];

// ---------------- helpers ----------------------------------------------------
__device__ __forceinline__ uint32_t smem_u32(const void* p) {
    uint32_t a;
    asm("{ .reg .u64 t; cvta.to.shared.u64 t, %1; cvt.u32.u64 %0, t; }"
        : "=r"(a) : "l"(p));
    return a;
}

// fp16 hi/lo split of two fp32 values, packed as half2 words
__device__ __forceinline__ void split2h(float x, float y, uint32_t& hi, uint32_t& lo) {
    f16 hx = __float2half_rn(x);
    f16 hy = __float2half_rn(y);
    float rx = x - __half2float(hx);
    float ry = y - __half2float(hy);
    __half2 H = __halves2half2(hx, hy);
    __half2 L = __floats2half2_rn(rx, ry);
    hi = *reinterpret_cast<uint32_t*>(&H);
    lo = *reinterpret_cast<uint32_t*>(&L);
}

__device__ __forceinline__ void mma_f16(float c[4],
                                        uint32_t a0, uint32_t a1, uint32_t a2, uint32_t a3,
                                        uint32_t b0, uint32_t b1) {
    asm volatile(
        "mma.sync.aligned.m16n8k16.row.col.f32.f16.f16.f32 "
        "{%0,%1,%2,%3}, {%4,%5,%6,%7}, {%8,%9}, {%0,%1,%2,%3};"
        : "+f"(c[0]), "+f"(c[1]), "+f"(c[2]), "+f"(c[3])
        : "r"(a0), "r"(a1), "r"(a2), "r"(a3), "r"(b0), "r"(b1));
}

#define LDSM_X4(r0, r1, r2, r3, addr) \
    asm volatile("ldmatrix.sync.aligned.m8n8.x4.shared.b16 {%0,%1,%2,%3}, [%4];" \
                 : "=r"(r0), "=r"(r1), "=r"(r2), "=r"(r3) : "r"(addr))

#define CP_ASYNC16(dst, src, sz) \
    asm volatile("cp.async.cg.shared.global [%0], [%1], 16, %2;" \
                 :: "r"(dst), "l"(src), "r"(sz) : "memory")

#define CP_COMMIT() asm volatile("cp.async.commit_group;" ::: "memory")

// XOR-swizzled offset of 16B chunk c in row r (row stride 64B data, no pad)
__device__ __forceinline__ uint32_t swz(int row, int chunk) {
    return (uint32_t)(row * 64 + ((chunk ^ ((row >> 1) & 3)) << 4));
}

// ---------------- fp32 -> fp16 hi/lo split (activations) ---------------------
__global__ void split_k(const float* __restrict__ s, f16* __restrict__ hi,
                        f16* __restrict__ lo, int n) {
    int i = (blockIdx.x * blockDim.x + threadIdx.x) * 4;
    if (i >= n) return;
    float4 v = *(const float4*)(s + i);
    uint32_t h0, l0, h1, l1;
    split2h(v.x, v.y, h0, l0);
    split2h(v.z, v.w, h1, l1);
    *(uint2*)(hi + i) = make_uint2(h0, h1);
    *(uint2*)(lo + i) = make_uint2(l0, l1);
}

// fp32 -> fp16 convert of all four weight matrices in one launch
__global__ void wcvt_k(const float* __restrict__ s0, f16* __restrict__ d0, int n0,
                       const float* __restrict__ s1, f16* __restrict__ d1, int n1,
                       const float* __restrict__ s2, f16* __restrict__ d2, int n2,
                       const float* __restrict__ s3, f16* __restrict__ d3, int n3) {
    int i = (blockIdx.x * blockDim.x + threadIdx.x) * 4;
    const float* s; f16* d;
    if (i < n0)                    { s = s0 + i;                  d = d0 + i; }
    else if (i < n0 + n1)          { s = s1 + (i - n0);           d = d1 + (i - n0); }
    else if (i < n0 + n1 + n2)     { s = s2 + (i - n0 - n1);      d = d2 + (i - n0 - n1); }
    else if (i < n0 + n1 + n2 + n3){ s = s3 + (i - n0 - n1 - n2); d = d3 + (i - n0 - n1 - n2); }
    else return;
    float4 v = *(const float4*)s;
    __half2 a = __floats2half2_rn(v.x, v.y);
    __half2 b = __floats2half2_rn(v.z, v.w);
    *(uint2*)d = make_uint2(*reinterpret_cast<uint32_t*>(&a),
                            *reinterpret_cast<uint32_t*>(&b));
}

// ---------------- CSR build --------------------------------------------------
__global__ void zero_cnt_k() {
    int i = blockIdx.x * blockDim.x + threadIdx.x;
    if (i < NN) g_cnt[i] = 0;
}

__global__ void count_k(const int* __restrict__ dst) {
    int e = blockIdx.x * blockDim.x + threadIdx.x;
    if (e < EE) atomicAdd(&g_cnt[dst[e]], 1);
}

// shuffle-based scan: 4 barriers per 1024-chunk (was ~21)
__global__ void scan_k() {
    __shared__ int wsum[32];
    __shared__ int carry;
    int tid = threadIdx.x, lane = tid & 31, w = tid >> 5;
    if (tid == 0) carry = 0;
    __syncthreads();
    for (int base = 0; base < NN; base += 1024) {
        int i = base + tid;
        int v = (i < NN) ? g_cnt[i] : 0;
        int incl = v;
        #pragma unroll
        for (int o = 1; o < 32; o <<= 1) {
            int t = __shfl_up_sync(0xFFFFFFFFu, incl, o);
            if (lane >= o) incl += t;
        }
        if (lane == 31) wsum[w] = incl;
        __syncthreads();
        if (w == 0) {
            int s = wsum[lane];
            #pragma unroll
            for (int o = 1; o < 32; o <<= 1) {
                int t = __shfl_up_sync(0xFFFFFFFFu, s, o);
                if (lane >= o) s += t;
            }
            wsum[lane] = s;
        }
        __syncthreads();
        int woff = (w > 0) ? wsum[w - 1] : 0;
        int ex = carry + woff + incl - v;
        if (i < NN) { g_off[i] = ex; g_fill[i] = ex; }
        __syncthreads();
        if (tid == 0) carry += wsum[31];
        __syncthreads();
    }
    if (tid == 0) g_off[NN] = carry;
}

__global__ void scatter_k(const int* __restrict__ src, const int* __restrict__ dst,
                          const float* __restrict__ w) {
    int e = blockIdx.x * blockDim.x + threadIdx.x;
    if (e < EE) {
        int d = dst[e];
        int p = atomicAdd(&g_fill[d], 1);
        g_csr_src[p] = src[e];
        g_csr_w[p]   = w[e];
    }
}

// ---------------- adj_mul gather, 8-way unrolled (MLP>=8) --------------------
__global__ void gather_k(const float* __restrict__ h,
                         f16* __restrict__ ahh, f16* __restrict__ ahl) {
    int node = blockIdx.x * 4 + threadIdx.y;
    if (node >= NN) return;
    int beg = g_off[node], end = g_off[node + 1];
    const float4* __restrict__ H = (const float4*)h;
    int t = threadIdx.x;  // 0..63
    float ax = 0.f, ay = 0.f, az = 0.f, aw = 0.f;

    int k = beg;
    for (; k + 8 <= end; k += 8) {
        int s[8]; float w[8];
        #pragma unroll
        for (int j = 0; j < 8; ++j) { s[j] = g_csr_src[k + j]; w[j] = g_csr_w[k + j]; }
        float4 v[8];
        #pragma unroll
        for (int j = 0; j < 8; ++j) v[j] = H[(size_t)s[j] * 64 + t];
        #pragma unroll
        for (int j = 0; j < 8; ++j) {
            ax = fmaf(v[j].x, w[j], ax);
            ay = fmaf(v[j].y, w[j], ay);
            az = fmaf(v[j].z, w[j], az);
            aw = fmaf(v[j].w, w[j], aw);
        }
    }
    if (k + 4 <= end) {
        int s[4]; float w[4];
        #pragma unroll
        for (int j = 0; j < 4; ++j) { s[j] = g_csr_src[k + j]; w[j] = g_csr_w[k + j]; }
        float4 v[4];
        #pragma unroll
        for (int j = 0; j < 4; ++j) v[j] = H[(size_t)s[j] * 64 + t];
        #pragma unroll
        for (int j = 0; j < 4; ++j) {
            ax = fmaf(v[j].x, w[j], ax);
            ay = fmaf(v[j].y, w[j], ay);
            az = fmaf(v[j].z, w[j], az);
            aw = fmaf(v[j].w, w[j], aw);
        }
        k += 4;
    }
    for (; k < end; ++k) {
        int s = g_csr_src[k];
        float w = g_csr_w[k];
        float4 v = H[(size_t)s * 64 + t];
        ax = fmaf(v.x, w, ax); ay = fmaf(v.y, w, ay);
        az = fmaf(v.z, w, az); aw = fmaf(v.w, w, aw);
    }
    uint32_t h0, l0, h1, l1;
    split2h(ax, ay, h0, l0);
    split2h(az, aw, h1, l1);
    ((uint2*)ahh)[(size_t)node * 64 + t] = make_uint2(h0, h1);
    ((uint2*)ahl)[(size_t)node * 64 + t] = make_uint2(l0, l1);
}

// ---------------- fp16x2 tensor-core GEMM: 144xBN tile, 1 CTA/SM -------------
// C = epi( [A1|A2] @ Wh^T ), A = exact fp16 hi+lo split, W = fp16(W).
template<int BN, bool FUSE, bool SPLIT>
__global__ __launch_bounds__(384)
void mma_gemm_k(const f16* __restrict__ a1h, const f16* __restrict__ a1l,
                const f16* __restrict__ a2h, const f16* __restrict__ a2l,
                int Ktot,
                const f16* __restrict__ wh,
                const float* __restrict__ bias, const float* __restrict__ res,
                float* __restrict__ C, f16* __restrict__ Chi, f16* __restrict__ Clo,
                int M, int Ncols)
{
    constexpr int NT   = BN / 32;
    constexpr int BBYT = BN * 64;
    constexpr int STGB = 2 * ABYT + BBYT;
    constexpr int NCHK = 1152 + 4 * BN;
    constexpr int ITER = (NCHK + 383) / 384;

    extern __shared__ __align__(16) char smem[];
    const uint32_t sb = smem_u32(smem);
    const int tid  = threadIdx.x;
    const int lane = tid & 31, wid = tid >> 5;
    const int wm = wid >> 2, wn = wid & 3;
    const int r = lane >> 2, q = lane & 3;
    const int ib = blockIdx.x * BM, jb = blockIdx.y * BN;
    const int S = Ktot / 32;

    const int aRow = wm * 48 + (lane & 15);
    const int bRow = wn * (BN / 4) + (lane & 7) + ((lane >> 4) << 3);
    const int aChk = (lane >> 4);
    const int bChk = ((lane >> 3) & 1);

    float acc[3][NT][4];
    #pragma unroll
    for (int a = 0; a < 3; ++a)
        #pragma unroll
        for (int b = 0; b < NT; ++b)
            #pragma unroll
            for (int c = 0; c < 4; ++c) acc[a][b][c] = 0.f;

    auto fill = [&](int s) {
        if (s < S) {
            const int k0 = s * 32;
            const uint32_t stb = sb + (s % NSTG) * STGB;
            #pragma unroll
            for (int i = 0; i < ITER; ++i) {
                int g = i * 384 + tid;
                if (g < NCHK) {
                    if (g < 1152) {
                        int mat = (g >= 576);
                        int idx = g - mat * 576;
                        int row = idx >> 2, c = idx & 3;
                        uint32_t dst = stb + mat * ABYT + swz(row, c);
                        const f16* a = (k0 < 256) ? (mat ? a1l : a1h)
                                                  : (mat ? a2l : a2h);
                        int gr = ib + row, sz = 16;
                        if (gr >= M) { gr = 0; sz = 0; }
                        CP_ASYNC16(dst, a + (size_t)gr * 256 + (k0 & 255) + c * 8, sz);
                    } else {
                        int idx = g - 1152;
                        int row = idx >> 2, c = idx & 3;
                        uint32_t dst = stb + 2 * ABYT + swz(row, c);
                        CP_ASYNC16(dst, wh + (size_t)(jb + row) * Ktot + k0 + c * 8, 16);
                    }
                }
            }
        }
        CP_COMMIT();
    };

    fill(0); fill(1); fill(2);

    for (int s = 0; s < S; ++s) {
        asm volatile("cp.async.wait_group 2;" ::: "memory");
        __syncthreads();
        fill(s + 3);

        const uint32_t stb = sb + (s % NSTG) * STGB;
        const uint32_t ahB = stb;
        const uint32_t alB = stb + ABYT;
        const uint32_t bhB = stb + 2 * ABYT;

        #pragma unroll
        for (int ks = 0; ks < 2; ++ks) {
            const int aChunk = ks * 2 + aChk;
            const int bChunk = ks * 2 + bChk;

            uint32_t BH[NT][2];
            #pragma unroll
            for (int p = 0; p < NT / 2; ++p) {
                uint32_t bd = bhB + swz(bRow + p * 16, bChunk);
                LDSM_X4(BH[2*p][0], BH[2*p][1], BH[2*p+1][0], BH[2*p+1][1], bd);
            }

            #pragma unroll
            for (int mt = 0; mt < 3; ++mt) {
                uint32_t A0, A1, A2, A3;
                LDSM_X4(A0, A1, A2, A3, ahB + swz(aRow + mt * 16, aChunk));
                #pragma unroll
                for (int nt = 0; nt < NT; ++nt)
                    mma_f16(acc[mt][nt], A0, A1, A2, A3, BH[nt][0], BH[nt][1]);
                LDSM_X4(A0, A1, A2, A3, alB + swz(aRow + mt * 16, aChunk));
                #pragma unroll
                for (int nt = 0; nt < NT; ++nt)
                    mma_f16(acc[mt][nt], A0, A1, A2, A3, BH[nt][0], BH[nt][1]);
            }
        }
    }

    // ---------------- epilogue ----------------
    #pragma unroll
    for (int mt = 0; mt < 3; ++mt) {
        #pragma unroll
        for (int nt = 0; nt < NT; ++nt) {
            int row0 = ib + wm * 48 + mt * 16 + r;
            int col  = jb + wn * (BN / 4) + nt * 8 + 2 * q;
            float2 b2 = make_float2(0.f, 0.f);
            if (FUSE) b2 = *(const float2*)&bias[col];
            #pragma unroll
            for (int hf = 0; hf < 2; ++hf) {
                int row = row0 + 8 * hf;
                if (row >= M) continue;
                float o0 = acc[mt][nt][2 * hf + 0];
                float o1 = acc[mt][nt][2 * hf + 1];
                if (FUSE) {
                    float2 rv = *(const float2*)&res[(size_t)row * Ncols + col];
                    o0 = rv.x + fmaxf(o0 + b2.x, 0.f);
                    o1 = rv.y + fmaxf(o1 + b2.y, 0.f);
                }
                *(float2*)&C[(size_t)row * Ncols + col] = make_float2(o0, o1);
                if (SPLIT) {
                    uint32_t hi, lo;
                    split2h(o0, o1, hi, lo);
                    *(uint32_t*)(Chi + (size_t)row * Ncols + col) = hi;
                    *(uint32_t*)(Clo + (size_t)row * Ncols + col) = lo;
                }
            }
        }
    }
}

// ---------------- row L2-normalize (128 cols): one warp per row --------------
__global__ void norm_k(float* __restrict__ out) {
    int row = blockIdx.x * 8 + threadIdx.y;  // blockDim (32,8)
    if (row >= NN) return;
    float4* p = (float4*)out + (size_t)row * 32 + threadIdx.x;
    float4 v = *p;
    float s = v.x * v.x + v.y * v.y + v.z * v.z + v.w * v.w;
    #pragma unroll
    for (int off = 16; off > 0; off >>= 1)
        s += __shfl_xor_sync(0xFFFFFFFFu, s, off);
    float r = rsqrtf(s);
    v.x *= r; v.y *= r; v.z *= r; v.w *= r;
    *p = v;
}

// ---------------- launch -----------------------------------------------------
extern "C" void kernel_launch(void* const* d_in, const int* in_sizes, int n_in,
                              void* d_out, int out_size) {
    const float* x     = (const float*)d_in[0];
    const int*   esrc  = (const int*)  d_in[1];
    const int*   edst  = (const int*)  d_in[2];
    const float* ew    = (const float*)d_in[3];
    const float* W_emb = (const float*)d_in[4];
    const float* W_gc1 = (const float*)d_in[5];
    const float* b_gc1 = (const float*)d_in[6];
    const float* W_gc2 = (const float*)d_in[7];
    const float* b_gc2 = (const float*)d_in[8];
    const float* W_fc  = (const float*)d_in[9];
    float* out = (float*)d_out;

    float *h, *h2;
    f16 *xh, *xl, *hh, *hl, *h2h, *h2l, *ahh, *ahl;
    f16 *we, *w1, *w2, *wf;
    cudaGetSymbolAddress((void**)&h,   g_h);
    cudaGetSymbolAddress((void**)&h2,  g_h2);
    cudaGetSymbolAddress((void**)&xh,  g_xh);  cudaGetSymbolAddress((void**)&xl,  g_xl);
    cudaGetSymbolAddress((void**)&hh,  g_hh);  cudaGetSymbolAddress((void**)&hl,  g_hl);
    cudaGetSymbolAddress((void**)&h2h, g_h2h); cudaGetSymbolAddress((void**)&h2l, g_h2l);
    cudaGetSymbolAddress((void**)&ahh, g_ahh); cudaGetSymbolAddress((void**)&ahl, g_ahl);
    cudaGetSymbolAddress((void**)&we,  g_we);
    cudaGetSymbolAddress((void**)&w1,  g_w1);
    cudaGetSymbolAddress((void**)&w2,  g_w2);
    cudaGetSymbolAddress((void**)&wf,  g_wf);

    const int SMEM256 = NSTG * (2 * ABYT + 256 * 64);  // 139264
    const int SMEM128 = NSTG * (2 * ABYT + 128 * 64);  // 106496
    cudaFuncSetAttribute(mma_gemm_k<256, true,  true >, cudaFuncAttributeMaxDynamicSharedMemorySize, SMEM256);
    cudaFuncSetAttribute(mma_gemm_k<256, false, true >, cudaFuncAttributeMaxDynamicSharedMemorySize, SMEM256);
    cudaFuncSetAttribute(mma_gemm_k<128, false, false>, cudaFuncAttributeMaxDynamicSharedMemorySize, SMEM128);

    // side stream + fork/join events: created once, on the (non-capture)
    // correctness call; reused identically on the capture call.
    static cudaStream_t s2 = nullptr;
    static cudaEvent_t evF = nullptr, evJ = nullptr;
    if (!s2) {
        cudaStreamCreateWithFlags(&s2, cudaStreamNonBlocking);
        cudaEventCreateWithFlags(&evF, cudaEventDisableTiming);
        cudaEventCreateWithFlags(&evJ, cudaEventDisableTiming);
    }

    const int MT = (NN + BM - 1) / BM;  // 139 -> one wave at 1 CTA/SM
    dim3 gHid(MT, 1);
    dim3 gOut(MT, 1);
    dim3 gblk(5000), gthr(64, 4);

    const int NW = HIDF * INF + 2 * (HIDF * 2 * HIDF) + OUTF * HIDF;

    // fork: CSR build on s2, split/wcvt/emb-GEMM on main stream (overlap)
    cudaEventRecord(evF, 0);
    cudaStreamWaitEvent(s2, evF, 0);

    split_k<<<(NN * INF / 4 + 255) / 256, 256>>>(x, xh, xl, NN * INF);                 // 0 main
    wcvt_k<<<(NW / 4 + 255) / 256, 256>>>(                                             // 1 main
        W_emb, we, HIDF * INF,
        W_gc1, w1, HIDF * 2 * HIDF,
        W_gc2, w2, HIDF * 2 * HIDF,
        W_fc,  wf, OUTF * HIDF);
    zero_cnt_k<<<(NN + 255) / 256, 256, 0, s2>>>();                                    // 2 s2
    mma_gemm_k<256, false, true><<<gHid, 384, SMEM256>>>(                              // 3 main (ncu)
        xh, xl, nullptr, nullptr, INF, we,
        nullptr, nullptr, h, hh, hl, NN, HIDF);
    count_k  <<<(EE + 255) / 256, 256, 0, s2>>>(edst);                                 // 4 s2
    scan_k   <<<1, 1024, 0, s2>>>();                                                   // 5 s2
    scatter_k<<<(EE + 255) / 256, 256, 0, s2>>>(esrc, edst, ew);                       // 6 s2

    // join: gather needs both h (main) and CSR (s2)
    cudaEventRecord(evJ, s2);
    cudaStreamWaitEvent(0, evJ, 0);

    // Ah = A @ h ; h2 = h + relu([h|Ah] @ W_gc1^T + b1)
    gather_k<<<gblk, gthr>>>(h, ahh, ahl);                                             // 7
    mma_gemm_k<256, true, true><<<gHid, 384, SMEM256>>>(                               // 8
        hh, hl, ahh, ahl, 2 * HIDF, w1,
        b_gc1, h, h2, h2h, h2l, NN, HIDF);
    // Ah = A @ h2 ; h = h2 + relu([h2|Ah] @ W_gc2^T + b2)
    gather_k<<<gblk, gthr>>>(h2, ahh, ahl);                                            // 9
    mma_gemm_k<256, true, true><<<gHid, 384, SMEM256>>>(                               // 10
        h2h, h2l, ahh, ahl, 2 * HIDF, w2,
        b_gc2, h2, h, hh, hl, NN, HIDF);
    // out = h @ W_fc^T ; rows L2-normalized
    mma_gemm_k<128, false, false><<<gOut, 384, SMEM128>>>(                             // 11
        hh, hl, nullptr, nullptr, HIDF, wf,
        nullptr, nullptr, out, nullptr, nullptr, NN, OUTF);
    norm_k<<<(NN + 7) / 8, dim3(32, 8)>>>(out);                                        // 12
}

// round 16
// speedup vs baseline: 3.7180x; 1.0476x over previous
#include <cuda_runtime.h>
#include <cuda_fp16.h>
#include <cstdint>

#define NN   20000
#define EE   320000
#define INF  256
#define HIDF 256
#define OUTF 128
#define BM   144                 // M tile (9 x 16)
#define ABYT 9216                // 144 rows x 64B per A matrix
#define NSTG 4                   // cp.async ring depth

typedef __half f16;

// ---------------- scratch (device globals; no allocation allowed) ------------
__device__ float g_h [NN * HIDF];
__device__ float g_h2[NN * HIDF];
__device__ f16   g_xh [NN * HIDF], g_xl [NN * HIDF];
__device__ f16   g_hh [NN * HIDF], g_hl [NN * HIDF];
__device__ f16   g_h2h[NN * HIDF], g_h2l[NN * HIDF];
__device__ f16   g_ahh[NN * HIDF], g_ahl[NN * HIDF];
__device__ f16   g_we[HIDF * INF];
__device__ f16   g_w1[HIDF * 2 * HIDF];
__device__ f16   g_w2[HIDF * 2 * HIDF];
__device__ f16   g_wf[OUTF * HIDF];
__device__ int   g_cnt[NN];
__device__ int   g_off[NN + 1];
__device__ int   g_fill[NN];
__device__ int   g_csr_src[EE];
__device__ float g_csr_w[EE];

// ---------------- helpers ----------------------------------------------------
__device__ __forceinline__ uint32_t smem_u32(const void* p) {
    uint32_t a;
    asm("{ .reg .u64 t; cvta.to.shared.u64 t, %1; cvt.u32.u64 %0, t; }"
        : "=r"(a) : "l"(p));
    return a;
}

// fp16 hi/lo split of two fp32 values, packed as half2 words
__device__ __forceinline__ void split2h(float x, float y, uint32_t& hi, uint32_t& lo) {
    f16 hx = __float2half_rn(x);
    f16 hy = __float2half_rn(y);
    float rx = x - __half2float(hx);
    float ry = y - __half2float(hy);
    __half2 H = __halves2half2(hx, hy);
    __half2 L = __floats2half2_rn(rx, ry);
    hi = *reinterpret_cast<uint32_t*>(&H);
    lo = *reinterpret_cast<uint32_t*>(&L);
}

__device__ __forceinline__ void mma_f16(float c[4],
                                        uint32_t a0, uint32_t a1, uint32_t a2, uint32_t a3,
                                        uint32_t b0, uint32_t b1) {
    asm volatile(
        "mma.sync.aligned.m16n8k16.row.col.f32.f16.f16.f32 "
        "{%0,%1,%2,%3}, {%4,%5,%6,%7}, {%8,%9}, {%0,%1,%2,%3};"
        : "+f"(c[0]), "+f"(c[1]), "+f"(c[2]), "+f"(c[3])
        : "r"(a0), "r"(a1), "r"(a2), "r"(a3), "r"(b0), "r"(b1));
}

#define LDSM_X4(r0, r1, r2, r3, addr) \
    asm volatile("ldmatrix.sync.aligned.m8n8.x4.shared.b16 {%0,%1,%2,%3}, [%4];" \
                 : "=r"(r0), "=r"(r1), "=r"(r2), "=r"(r3) : "r"(addr))

#define CP_ASYNC16(dst, src, sz) \
    asm volatile("cp.async.cg.shared.global [%0], [%1], 16, %2;" \
                 :: "r"(dst), "l"(src), "r"(sz) : "memory")

#define CP_COMMIT() asm volatile("cp.async.commit_group;" ::: "memory")

// XOR-swizzled offset of 16B chunk c in row r (row stride 64B data, no pad)
__device__ __forceinline__ uint32_t swz(int row, int chunk) {
    return (uint32_t)(row * 64 + ((chunk ^ ((row >> 1) & 3)) << 4));
}

// ---------------- fp32 -> fp16 hi/lo split (activations) ---------------------
__global__ void split_k(const float* __restrict__ s, f16* __restrict__ hi,
                        f16* __restrict__ lo, int n) {
    int i = (blockIdx.x * blockDim.x + threadIdx.x) * 4;
    if (i >= n) return;
    float4 v = *(const float4*)(s + i);
    uint32_t h0, l0, h1, l1;
    split2h(v.x, v.y, h0, l0);
    split2h(v.z, v.w, h1, l1);
    *(uint2*)(hi + i) = make_uint2(h0, h1);
    *(uint2*)(lo + i) = make_uint2(l0, l1);
}

// fp32 -> fp16 convert of all four weight matrices in one launch
__global__ void wcvt_k(const float* __restrict__ s0, f16* __restrict__ d0, int n0,
                       const float* __restrict__ s1, f16* __restrict__ d1, int n1,
                       const float* __restrict__ s2, f16* __restrict__ d2, int n2,
                       const float* __restrict__ s3, f16* __restrict__ d3, int n3) {
    int i = (blockIdx.x * blockDim.x + threadIdx.x) * 4;
    const float* s; f16* d;
    if (i < n0)                    { s = s0 + i;                  d = d0 + i; }
    else if (i < n0 + n1)          { s = s1 + (i - n0);           d = d1 + (i - n0); }
    else if (i < n0 + n1 + n2)     { s = s2 + (i - n0 - n1);      d = d2 + (i - n0 - n1); }
    else if (i < n0 + n1 + n2 + n3){ s = s3 + (i - n0 - n1 - n2); d = d3 + (i - n0 - n1 - n2); }
    else return;
    float4 v = *(const float4*)s;
    __half2 a = __floats2half2_rn(v.x, v.y);
    __half2 b = __floats2half2_rn(v.z, v.w);
    *(uint2*)d = make_uint2(*reinterpret_cast<uint32_t*>(&a),
                            *reinterpret_cast<uint32_t*>(&b));
}

// ---------------- CSR build --------------------------------------------------
__global__ void zero_cnt_k() {
    int i = blockIdx.x * blockDim.x + threadIdx.x;
    if (i < NN) g_cnt[i] = 0;
}

__global__ void count_k(const int* __restrict__ dst) {
    int e = blockIdx.x * blockDim.x + threadIdx.x;
    if (e < EE) atomicAdd(&g_cnt[dst[e]], 1);
}

// shuffle-based scan: 4 barriers per 1024-chunk
__global__ void scan_k() {
    __shared__ int wsum[32];
    __shared__ int carry;
    int tid = threadIdx.x, lane = tid & 31, w = tid >> 5;
    if (tid == 0) carry = 0;
    __syncthreads();
    for (int base = 0; base < NN; base += 1024) {
        int i = base + tid;
        int v = (i < NN) ? g_cnt[i] : 0;
        int incl = v;
        #pragma unroll
        for (int o = 1; o < 32; o <<= 1) {
            int t = __shfl_up_sync(0xFFFFFFFFu, incl, o);
            if (lane >= o) incl += t;
        }
        if (lane == 31) wsum[w] = incl;
        __syncthreads();
        if (w == 0) {
            int s = wsum[lane];
            #pragma unroll
            for (int o = 1; o < 32; o <<= 1) {
                int t = __shfl_up_sync(0xFFFFFFFFu, s, o);
                if (lane >= o) s += t;
            }
            wsum[lane] = s;
        }
        __syncthreads();
        int woff = (w > 0) ? wsum[w - 1] : 0;
        int ex = carry + woff + incl - v;
        if (i < NN) { g_off[i] = ex; g_fill[i] = ex; }
        __syncthreads();
        if (tid == 0) carry += wsum[31];
        __syncthreads();
    }
    if (tid == 0) g_off[NN] = carry;
}

__global__ void scatter_k(const int* __restrict__ src, const int* __restrict__ dst,
                          const float* __restrict__ w) {
    int e = blockIdx.x * blockDim.x + threadIdx.x;
    if (e < EE) {
        int d = dst[e];
        int p = atomicAdd(&g_fill[d], 1);
        g_csr_src[p] = src[e];
        g_csr_w[p]   = w[e];
    }
}

// ---------------- adj_mul gather: fp16 h reads, fp32 accumulate --------------
// reads hin (fp16 hi of h): 512B/row vs 1KB -> at the L2 BW roofline this
// halves gather time. 8-way edge unroll for MLP.
__global__ void gather_k(const f16* __restrict__ hin,
                         f16* __restrict__ ahh, f16* __restrict__ ahl) {
    int node = blockIdx.x * 4 + threadIdx.y;
    if (node >= NN) return;
    int beg = g_off[node], end = g_off[node + 1];
    const uint2* __restrict__ H = (const uint2*)hin;   // 4 halves per lane
    int t = threadIdx.x;  // 0..63
    float ax = 0.f, ay = 0.f, az = 0.f, aw = 0.f;

    int k = beg;
    for (; k + 8 <= end; k += 8) {
        int s[8]; float w[8];
        #pragma unroll
        for (int j = 0; j < 8; ++j) { s[j] = g_csr_src[k + j]; w[j] = g_csr_w[k + j]; }
        uint2 u[8];
        #pragma unroll
        for (int j = 0; j < 8; ++j) u[j] = H[(size_t)s[j] * 64 + t];
        #pragma unroll
        for (int j = 0; j < 8; ++j) {
            float2 f0 = __half22float2(*reinterpret_cast<__half2*>(&u[j].x));
            float2 f1 = __half22float2(*reinterpret_cast<__half2*>(&u[j].y));
            ax = fmaf(f0.x, w[j], ax);
            ay = fmaf(f0.y, w[j], ay);
            az = fmaf(f1.x, w[j], az);
            aw = fmaf(f1.y, w[j], aw);
        }
    }
    if (k + 4 <= end) {
        int s[4]; float w[4];
        #pragma unroll
        for (int j = 0; j < 4; ++j) { s[j] = g_csr_src[k + j]; w[j] = g_csr_w[k + j]; }
        uint2 u[4];
        #pragma unroll
        for (int j = 0; j < 4; ++j) u[j] = H[(size_t)s[j] * 64 + t];
        #pragma unroll
        for (int j = 0; j < 4; ++j) {
            float2 f0 = __half22float2(*reinterpret_cast<__half2*>(&u[j].x));
            float2 f1 = __half22float2(*reinterpret_cast<__half2*>(&u[j].y));
            ax = fmaf(f0.x, w[j], ax);
            ay = fmaf(f0.y, w[j], ay);
            az = fmaf(f1.x, w[j], az);
            aw = fmaf(f1.y, w[j], aw);
        }
        k += 4;
    }
    for (; k < end; ++k) {
        int s = g_csr_src[k];
        float w = g_csr_w[k];
        uint2 u = H[(size_t)s * 64 + t];
        float2 f0 = __half22float2(*reinterpret_cast<__half2*>(&u.x));
        float2 f1 = __half22float2(*reinterpret_cast<__half2*>(&u.y));
        ax = fmaf(f0.x, w, ax); ay = fmaf(f0.y, w, ay);
        az = fmaf(f1.x, w, az); aw = fmaf(f1.y, w, aw);
    }
    uint32_t h0, l0, h1, l1;
    split2h(ax, ay, h0, l0);
    split2h(az, aw, h1, l1);
    ((uint2*)ahh)[(size_t)node * 64 + t] = make_uint2(h0, h1);
    ((uint2*)ahl)[(size_t)node * 64 + t] = make_uint2(l0, l1);
}

// ---------------- fp16x2 tensor-core GEMM: 144xBN tile, 1 CTA/SM -------------
// C = epi( [A1|A2] @ Wh^T ), A = exact fp16 hi+lo split, W = fp16(W).
template<int BN, bool FUSE, bool SPLIT>
__global__ __launch_bounds__(384)
void mma_gemm_k(const f16* __restrict__ a1h, const f16* __restrict__ a1l,
                const f16* __restrict__ a2h, const f16* __restrict__ a2l,
                int Ktot,
                const f16* __restrict__ wh,
                const float* __restrict__ bias, const float* __restrict__ res,
                float* __restrict__ C, f16* __restrict__ Chi, f16* __restrict__ Clo,
                int M, int Ncols)
{
    constexpr int NT   = BN / 32;
    constexpr int BBYT = BN * 64;
    constexpr int STGB = 2 * ABYT + BBYT;
    constexpr int NCHK = 1152 + 4 * BN;
    constexpr int ITER = (NCHK + 383) / 384;

    extern __shared__ __align__(16) char smem[];
    const uint32_t sb = smem_u32(smem);
    const int tid  = threadIdx.x;
    const int lane = tid & 31, wid = tid >> 5;
    const int wm = wid >> 2, wn = wid & 3;
    const int r = lane >> 2, q = lane & 3;
    const int ib = blockIdx.x * BM, jb = blockIdx.y * BN;
    const int S = Ktot / 32;

    const int aRow = wm * 48 + (lane & 15);
    const int bRow = wn * (BN / 4) + (lane & 7) + ((lane >> 4) << 3);
    const int aChk = (lane >> 4);
    const int bChk = ((lane >> 3) & 1);

    float acc[3][NT][4];
    #pragma unroll
    for (int a = 0; a < 3; ++a)
        #pragma unroll
        for (int b = 0; b < NT; ++b)
            #pragma unroll
            for (int c = 0; c < 4; ++c) acc[a][b][c] = 0.f;

    auto fill = [&](int s) {
        if (s < S) {
            const int k0 = s * 32;
            const uint32_t stb = sb + (s % NSTG) * STGB;
            #pragma unroll
            for (int i = 0; i < ITER; ++i) {
                int g = i * 384 + tid;
                if (g < NCHK) {
                    if (g < 1152) {
                        int mat = (g >= 576);
                        int idx = g - mat * 576;
                        int row = idx >> 2, c = idx & 3;
                        uint32_t dst = stb + mat * ABYT + swz(row, c);
                        const f16* a = (k0 < 256) ? (mat ? a1l : a1h)
                                                  : (mat ? a2l : a2h);
                        int gr = ib + row, sz = 16;
                        if (gr >= M) { gr = 0; sz = 0; }
                        CP_ASYNC16(dst, a + (size_t)gr * 256 + (k0 & 255) + c * 8, sz);
                    } else {
                        int idx = g - 1152;
                        int row = idx >> 2, c = idx & 3;
                        uint32_t dst = stb + 2 * ABYT + swz(row, c);
                        CP_ASYNC16(dst, wh + (size_t)(jb + row) * Ktot + k0 + c * 8, 16);
                    }
                }
            }
        }
        CP_COMMIT();
    };

    fill(0); fill(1); fill(2);

    for (int s = 0; s < S; ++s) {
        asm volatile("cp.async.wait_group 2;" ::: "memory");
        __syncthreads();
        fill(s + 3);

        const uint32_t stb = sb + (s % NSTG) * STGB;
        const uint32_t ahB = stb;
        const uint32_t alB = stb + ABYT;
        const uint32_t bhB = stb + 2 * ABYT;

        #pragma unroll
        for (int ks = 0; ks < 2; ++ks) {
            const int aChunk = ks * 2 + aChk;
            const int bChunk = ks * 2 + bChk;

            uint32_t BH[NT][2];
            #pragma unroll
            for (int p = 0; p < NT / 2; ++p) {
                uint32_t bd = bhB + swz(bRow + p * 16, bChunk);
                LDSM_X4(BH[2*p][0], BH[2*p][1], BH[2*p+1][0], BH[2*p+1][1], bd);
            }

            #pragma unroll
            for (int mt = 0; mt < 3; ++mt) {
                uint32_t A0, A1, A2, A3;
                LDSM_X4(A0, A1, A2, A3, ahB + swz(aRow + mt * 16, aChunk));
                #pragma unroll
                for (int nt = 0; nt < NT; ++nt)
                    mma_f16(acc[mt][nt], A0, A1, A2, A3, BH[nt][0], BH[nt][1]);
                LDSM_X4(A0, A1, A2, A3, alB + swz(aRow + mt * 16, aChunk));
                #pragma unroll
                for (int nt = 0; nt < NT; ++nt)
                    mma_f16(acc[mt][nt], A0, A1, A2, A3, BH[nt][0], BH[nt][1]);
            }
        }
    }

    // ---------------- epilogue ----------------
    #pragma unroll
    for (int mt = 0; mt < 3; ++mt) {
        #pragma unroll
        for (int nt = 0; nt < NT; ++nt) {
            int row0 = ib + wm * 48 + mt * 16 + r;
            int col  = jb + wn * (BN / 4) + nt * 8 + 2 * q;
            float2 b2 = make_float2(0.f, 0.f);
            if (FUSE) b2 = *(const float2*)&bias[col];
            #pragma unroll
            for (int hf = 0; hf < 2; ++hf) {
                int row = row0 + 8 * hf;
                if (row >= M) continue;
                float o0 = acc[mt][nt][2 * hf + 0];
                float o1 = acc[mt][nt][2 * hf + 1];
                if (FUSE) {
                    float2 rv = *(const float2*)&res[(size_t)row * Ncols + col];
                    o0 = rv.x + fmaxf(o0 + b2.x, 0.f);
                    o1 = rv.y + fmaxf(o1 + b2.y, 0.f);
                }
                *(float2*)&C[(size_t)row * Ncols + col] = make_float2(o0, o1);
                if (SPLIT) {
                    uint32_t hi, lo;
                    split2h(o0, o1, hi, lo);
                    *(uint32_t*)(Chi + (size_t)row * Ncols + col) = hi;
                    *(uint32_t*)(Clo + (size_t)row * Ncols + col) = lo;
                }
            }
        }
    }
}

// ---------------- row L2-normalize (128 cols): one warp per row --------------
__global__ void norm_k(float* __restrict__ out) {
    int row = blockIdx.x * 8 + threadIdx.y;  // blockDim (32,8)
    if (row >= NN) return;
    float4* p = (float4*)out + (size_t)row * 32 + threadIdx.x;
    float4 v = *p;
    float s = v.x * v.x + v.y * v.y + v.z * v.z + v.w * v.w;
    #pragma unroll
    for (int off = 16; off > 0; off >>= 1)
        s += __shfl_xor_sync(0xFFFFFFFFu, s, off);
    float r = rsqrtf(s);
    v.x *= r; v.y *= r; v.z *= r; v.w *= r;
    *p = v;
}

// ---------------- launch -----------------------------------------------------
extern "C" void kernel_launch(void* const* d_in, const int* in_sizes, int n_in,
                              void* d_out, int out_size) {
    const float* x     = (const float*)d_in[0];
    const int*   esrc  = (const int*)  d_in[1];
    const int*   edst  = (const int*)  d_in[2];
    const float* ew    = (const float*)d_in[3];
    const float* W_emb = (const float*)d_in[4];
    const float* W_gc1 = (const float*)d_in[5];
    const float* b_gc1 = (const float*)d_in[6];
    const float* W_gc2 = (const float*)d_in[7];
    const float* b_gc2 = (const float*)d_in[8];
    const float* W_fc  = (const float*)d_in[9];
    float* out = (float*)d_out;

    float *h, *h2;
    f16 *xh, *xl, *hh, *hl, *h2h, *h2l, *ahh, *ahl;
    f16 *we, *w1, *w2, *wf;
    cudaGetSymbolAddress((void**)&h,   g_h);
    cudaGetSymbolAddress((void**)&h2,  g_h2);
    cudaGetSymbolAddress((void**)&xh,  g_xh);  cudaGetSymbolAddress((void**)&xl,  g_xl);
    cudaGetSymbolAddress((void**)&hh,  g_hh);  cudaGetSymbolAddress((void**)&hl,  g_hl);
    cudaGetSymbolAddress((void**)&h2h, g_h2h); cudaGetSymbolAddress((void**)&h2l, g_h2l);
    cudaGetSymbolAddress((void**)&ahh, g_ahh); cudaGetSymbolAddress((void**)&ahl, g_ahl);
    cudaGetSymbolAddress((void**)&we,  g_we);
    cudaGetSymbolAddress((void**)&w1,  g_w1);
    cudaGetSymbolAddress((void**)&w2,  g_w2);
    cudaGetSymbolAddress((void**)&wf,  g_wf);

    const int SMEM256 = NSTG * (2 * ABYT + 256 * 64);  // 139264
    const int SMEM128 = NSTG * (2 * ABYT + 128 * 64);  // 106496
    cudaFuncSetAttribute(mma_gemm_k<256, true,  true >, cudaFuncAttributeMaxDynamicSharedMemorySize, SMEM256);
    cudaFuncSetAttribute(mma_gemm_k<256, false, true >, cudaFuncAttributeMaxDynamicSharedMemorySize, SMEM256);
    cudaFuncSetAttribute(mma_gemm_k<128, false, false>, cudaFuncAttributeMaxDynamicSharedMemorySize, SMEM128);

    // side stream + fork/join events: created once, on the (non-capture)
    // correctness call; reused identically on the capture call.
    static cudaStream_t s2 = nullptr;
    static cudaEvent_t evF = nullptr, evJ = nullptr;
    if (!s2) {
        cudaStreamCreateWithFlags(&s2, cudaStreamNonBlocking);
        cudaEventCreateWithFlags(&evF, cudaEventDisableTiming);
        cudaEventCreateWithFlags(&evJ, cudaEventDisableTiming);
    }

    const int MT = (NN + BM - 1) / BM;  // 139 -> one wave at 1 CTA/SM
    dim3 gHid(MT, 1);
    dim3 gOut(MT, 1);
    dim3 gblk(5000), gthr(64, 4);

    const int NW = HIDF * INF + 2 * (HIDF * 2 * HIDF) + OUTF * HIDF;

    // fork: CSR build on s2, split/wcvt/emb-GEMM on main stream (overlap)
    cudaEventRecord(evF, 0);
    cudaStreamWaitEvent(s2, evF, 0);

    split_k<<<(NN * INF / 4 + 255) / 256, 256>>>(x, xh, xl, NN * INF);                 // 0 main
    wcvt_k<<<(NW / 4 + 255) / 256, 256>>>(                                             // 1 main
        W_emb, we, HIDF * INF,
        W_gc1, w1, HIDF * 2 * HIDF,
        W_gc2, w2, HIDF * 2 * HIDF,
        W_fc,  wf, OUTF * HIDF);
    zero_cnt_k<<<(NN + 255) / 256, 256, 0, s2>>>();                                    // 2 s2
    mma_gemm_k<256, false, true><<<gHid, 384, SMEM256>>>(                              // 3 main (ncu)
        xh, xl, nullptr, nullptr, INF, we,
        nullptr, nullptr, h, hh, hl, NN, HIDF);
    count_k  <<<(EE + 255) / 256, 256, 0, s2>>>(edst);                                 // 4 s2
    scan_k   <<<1, 1024, 0, s2>>>();                                                   // 5 s2
    scatter_k<<<(EE + 255) / 256, 256, 0, s2>>>(esrc, edst, ew);                       // 6 s2

    // join: gather needs both hh (main) and CSR (s2)
    cudaEventRecord(evJ, s2);
    cudaStreamWaitEvent(0, evJ, 0);

    // Ah = A @ h ; h2 = h + relu([h|Ah] @ W_gc1^T + b1)
    gather_k<<<gblk, gthr>>>(hh, ahh, ahl);                                            // 7
    mma_gemm_k<256, true, true><<<gHid, 384, SMEM256>>>(                               // 8
        hh, hl, ahh, ahl, 2 * HIDF, w1,
        b_gc1, h, h2, h2h, h2l, NN, HIDF);
    // Ah = A @ h2 ; h = h2 + relu([h2|Ah] @ W_gc2^T + b2)
    gather_k<<<gblk, gthr>>>(h2h, ahh, ahl);                                           // 9
    mma_gemm_k<256, true, true><<<gHid, 384, SMEM256>>>(                               // 10
        h2h, h2l, ahh, ahl, 2 * HIDF, w2,
        b_gc2, h2, h, hh, hl, NN, HIDF);
    // out = h @ W_fc^T ; rows L2-normalized
    mma_gemm_k<128, false, false><<<gOut, 384, SMEM128>>>(                             // 11
        hh, hl, nullptr, nullptr, HIDF, wf,
        nullptr, nullptr, out, nullptr, nullptr, NN, OUTF);
    norm_k<<<(NN + 7) / 8, dim3(32, 8)>>>(out);                                        // 12
}

// round 17
// speedup vs baseline: 3.9744x; 1.0690x over previous
#include <cuda_runtime.h>
#include <cuda_fp16.h>
#include <cstdint>

#define NN   20000
#define EE   320000
#define INF  256
#define HIDF 256
#define OUTF 128
#define BM   144                 // M tile (9 x 16)
#define ABYT 9216                // 144 rows x 64B per A matrix
#define NSTG 4                   // cp.async ring depth

typedef __half f16;

// ---------------- scratch (device globals; no allocation allowed) ------------
__device__ f16   g_xh [NN * HIDF], g_xl [NN * HIDF];
__device__ f16   g_hh [NN * HIDF], g_hl [NN * HIDF];
__device__ f16   g_h2h[NN * HIDF], g_h2l[NN * HIDF];
__device__ f16   g_ahh[NN * HIDF];
__device__ f16   g_we[HIDF * INF];
__device__ f16   g_w1[HIDF * 2 * HIDF];
__device__ f16   g_w2[HIDF * 2 * HIDF];
__device__ f16   g_wf[OUTF * HIDF];
__device__ int   g_cnt[NN];
__device__ int   g_off[NN + 1];
__device__ int   g_fill[NN];
__device__ int   g_csr_src[EE];
__device__ float g_csr_w[EE];

// ---------------- helpers ----------------------------------------------------
__device__ __forceinline__ uint32_t smem_u32(const void* p) {
    uint32_t a;
    asm("{ .reg .u64 t; cvta.to.shared.u64 t, %1; cvt.u32.u64 %0, t; }"
        : "=r"(a) : "l"(p));
    return a;
}

// fp16 hi/lo split of two fp32 values, packed as half2 words
__device__ __forceinline__ void split2h(float x, float y, uint32_t& hi, uint32_t& lo) {
    f16 hx = __float2half_rn(x);
    f16 hy = __float2half_rn(y);
    float rx = x - __half2float(hx);
    float ry = y - __half2float(hy);
    __half2 H = __halves2half2(hx, hy);
    __half2 L = __floats2half2_rn(rx, ry);
    hi = *reinterpret_cast<uint32_t*>(&H);
    lo = *reinterpret_cast<uint32_t*>(&L);
}

__device__ __forceinline__ void mma_f16(float c[4],
                                        uint32_t a0, uint32_t a1, uint32_t a2, uint32_t a3,
                                        uint32_t b0, uint32_t b1) {
    asm volatile(
        "mma.sync.aligned.m16n8k16.row.col.f32.f16.f16.f32 "
        "{%0,%1,%2,%3}, {%4,%5,%6,%7}, {%8,%9}, {%0,%1,%2,%3};"
        : "+f"(c[0]), "+f"(c[1]), "+f"(c[2]), "+f"(c[3])
        : "r"(a0), "r"(a1), "r"(a2), "r"(a3), "r"(b0), "r"(b1));
}

#define LDSM_X4(r0, r1, r2, r3, addr) \
    asm volatile("ldmatrix.sync.aligned.m8n8.x4.shared.b16 {%0,%1,%2,%3}, [%4];" \
                 : "=r"(r0), "=r"(r1), "=r"(r2), "=r"(r3) : "r"(addr))

#define CP_ASYNC16(dst, src, sz) \
    asm volatile("cp.async.cg.shared.global [%0], [%1], 16, %2;" \
                 :: "r"(dst), "l"(src), "r"(sz) : "memory")

#define CP_COMMIT() asm volatile("cp.async.commit_group;" ::: "memory")

// XOR-swizzled offset of 16B chunk c in row r (row stride 64B data, no pad)
__device__ __forceinline__ uint32_t swz(int row, int chunk) {
    return (uint32_t)(row * 64 + ((chunk ^ ((row >> 1) & 3)) << 4));
}

// ---------------- fp32 -> fp16 hi/lo split (activations) ---------------------
__global__ void split_k(const float* __restrict__ s, f16* __restrict__ hi,
                        f16* __restrict__ lo, int n) {
    int i = (blockIdx.x * blockDim.x + threadIdx.x) * 4;
    if (i >= n) return;
    float4 v = *(const float4*)(s + i);
    uint32_t h0, l0, h1, l1;
    split2h(v.x, v.y, h0, l0);
    split2h(v.z, v.w, h1, l1);
    *(uint2*)(hi + i) = make_uint2(h0, h1);
    *(uint2*)(lo + i) = make_uint2(l0, l1);
}

// fp32 -> fp16 convert of all four weight matrices in one launch
__global__ void wcvt_k(const float* __restrict__ s0, f16* __restrict__ d0, int n0,
                       const float* __restrict__ s1, f16* __restrict__ d1, int n1,
                       const float* __restrict__ s2, f16* __restrict__ d2, int n2,
                       const float* __restrict__ s3, f16* __restrict__ d3, int n3) {
    int i = (blockIdx.x * blockDim.x + threadIdx.x) * 4;
    const float* s; f16* d;
    if (i < n0)                    { s = s0 + i;                  d = d0 + i; }
    else if (i < n0 + n1)          { s = s1 + (i - n0);           d = d1 + (i - n0); }
    else if (i < n0 + n1 + n2)     { s = s2 + (i - n0 - n1);      d = d2 + (i - n0 - n1); }
    else if (i < n0 + n1 + n2 + n3){ s = s3 + (i - n0 - n1 - n2); d = d3 + (i - n0 - n1 - n2); }
    else return;
    float4 v = *(const float4*)s;
    __half2 a = __floats2half2_rn(v.x, v.y);
    __half2 b = __floats2half2_rn(v.z, v.w);
    *(uint2*)d = make_uint2(*reinterpret_cast<uint32_t*>(&a),
                            *reinterpret_cast<uint32_t*>(&b));
}

// ---------------- CSR build --------------------------------------------------
__global__ void zero_cnt_k() {
    int i = blockIdx.x * blockDim.x + threadIdx.x;
    if (i < NN) g_cnt[i] = 0;
}

__global__ void count_k(const int* __restrict__ dst) {
    int e = blockIdx.x * blockDim.x + threadIdx.x;
    if (e < EE) atomicAdd(&g_cnt[dst[e]], 1);
}

// shuffle-based scan: 4 barriers per 1024-chunk
__global__ void scan_k() {
    __shared__ int wsum[32];
    __shared__ int carry;
    int tid = threadIdx.x, lane = tid & 31, w = tid >> 5;
    if (tid == 0) carry = 0;
    __syncthreads();
    for (int base = 0; base < NN; base += 1024) {
        int i = base + tid;
        int v = (i < NN) ? g_cnt[i] : 0;
        int incl = v;
        #pragma unroll
        for (int o = 1; o < 32; o <<= 1) {
            int t = __shfl_up_sync(0xFFFFFFFFu, incl, o);
            if (lane >= o) incl += t;
        }
        if (lane == 31) wsum[w] = incl;
        __syncthreads();
        if (w == 0) {
            int s = wsum[lane];
            #pragma unroll
            for (int o = 1; o < 32; o <<= 1) {
                int t = __shfl_up_sync(0xFFFFFFFFu, s, o);
                if (lane >= o) s += t;
            }
            wsum[lane] = s;
        }
        __syncthreads();
        int woff = (w > 0) ? wsum[w - 1] : 0;
        int ex = carry + woff + incl - v;
        if (i < NN) { g_off[i] = ex; g_fill[i] = ex; }
        __syncthreads();
        if (tid == 0) carry += wsum[31];
        __syncthreads();
    }
    if (tid == 0) g_off[NN] = carry;
}

__global__ void scatter_k(const int* __restrict__ src, const int* __restrict__ dst,
                          const float* __restrict__ w) {
    int e = blockIdx.x * blockDim.x + threadIdx.x;
    if (e < EE) {
        int d = dst[e];
        int p = atomicAdd(&g_fill[d], 1);
        g_csr_src[p] = src[e];
        g_csr_w[p]   = w[e];
    }
}

// ---------------- adj_mul gather: fp16 h reads, fp32 acc, fp16-hi output -----
__global__ void gather_k(const f16* __restrict__ hin, f16* __restrict__ ahh) {
    int node = blockIdx.x * 4 + threadIdx.y;
    if (node >= NN) return;
    int beg = g_off[node], end = g_off[node + 1];
    const uint2* __restrict__ H = (const uint2*)hin;   // 4 halves per lane
    int t = threadIdx.x;  // 0..63
    float ax = 0.f, ay = 0.f, az = 0.f, aw = 0.f;

    int k = beg;
    for (; k + 8 <= end; k += 8) {
        int s[8]; float w[8];
        #pragma unroll
        for (int j = 0; j < 8; ++j) { s[j] = g_csr_src[k + j]; w[j] = g_csr_w[k + j]; }
        uint2 u[8];
        #pragma unroll
        for (int j = 0; j < 8; ++j) u[j] = H[(size_t)s[j] * 64 + t];
        #pragma unroll
        for (int j = 0; j < 8; ++j) {
            float2 f0 = __half22float2(*reinterpret_cast<__half2*>(&u[j].x));
            float2 f1 = __half22float2(*reinterpret_cast<__half2*>(&u[j].y));
            ax = fmaf(f0.x, w[j], ax);
            ay = fmaf(f0.y, w[j], ay);
            az = fmaf(f1.x, w[j], az);
            aw = fmaf(f1.y, w[j], aw);
        }
    }
    if (k + 4 <= end) {
        int s[4]; float w[4];
        #pragma unroll
        for (int j = 0; j < 4; ++j) { s[j] = g_csr_src[k + j]; w[j] = g_csr_w[k + j]; }
        uint2 u[4];
        #pragma unroll
        for (int j = 0; j < 4; ++j) u[j] = H[(size_t)s[j] * 64 + t];
        #pragma unroll
        for (int j = 0; j < 4; ++j) {
            float2 f0 = __half22float2(*reinterpret_cast<__half2*>(&u[j].x));
            float2 f1 = __half22float2(*reinterpret_cast<__half2*>(&u[j].y));
            ax = fmaf(f0.x, w[j], ax);
            ay = fmaf(f0.y, w[j], ay);
            az = fmaf(f1.x, w[j], az);
            aw = fmaf(f1.y, w[j], aw);
        }
        k += 4;
    }
    for (; k < end; ++k) {
        int s = g_csr_src[k];
        float w = g_csr_w[k];
        uint2 u = H[(size_t)s * 64 + t];
        float2 f0 = __half22float2(*reinterpret_cast<__half2*>(&u.x));
        float2 f1 = __half22float2(*reinterpret_cast<__half2*>(&u.y));
        ax = fmaf(f0.x, w, ax); ay = fmaf(f0.y, w, ay);
        az = fmaf(f1.x, w, az); aw = fmaf(f1.y, w, aw);
    }
    __half2 o0 = __floats2half2_rn(ax, ay);
    __half2 o1 = __floats2half2_rn(az, aw);
    ((uint2*)ahh)[(size_t)node * 64 + t] =
        make_uint2(*reinterpret_cast<uint32_t*>(&o0), *reinterpret_cast<uint32_t*>(&o1));
}

// ---------------- fp16 tensor-core GEMM: 144xBN tile, 1 CTA/SM ---------------
// C = epi( [A1|A2] @ Wh^T ). A1 = exact fp16 hi+lo split (2 products);
// A2 (k >= 256) = fp16 hi only (1 product) when A2LO == false.
// FUSE: out = (rh+rl) + relu(acc + bias). SPLIT: write fp16 hi/lo.
// OUT32: write fp32 C.
template<int BN, bool FUSE, bool SPLIT, bool OUT32, bool A2LO>
__global__ __launch_bounds__(384)
void mma_gemm_k(const f16* __restrict__ a1h, const f16* __restrict__ a1l,
                const f16* __restrict__ a2h, const f16* __restrict__ a2l,
                int Ktot,
                const f16* __restrict__ wh,
                const float* __restrict__ bias,
                const f16* __restrict__ rh, const f16* __restrict__ rl,
                float* __restrict__ C, f16* __restrict__ Chi, f16* __restrict__ Clo,
                int M, int Ncols)
{
    constexpr int NT   = BN / 32;
    constexpr int BBYT = BN * 64;
    constexpr int STGB = 2 * ABYT + BBYT;
    constexpr int NCHK = 1152 + 4 * BN;
    constexpr int ITER = (NCHK + 383) / 384;

    extern __shared__ __align__(16) char smem[];
    const uint32_t sb = smem_u32(smem);
    const int tid  = threadIdx.x;
    const int lane = tid & 31, wid = tid >> 5;
    const int wm = wid >> 2, wn = wid & 3;
    const int r = lane >> 2, q = lane & 3;
    const int ib = blockIdx.x * BM, jb = blockIdx.y * BN;
    const int S = Ktot / 32;

    const int aRow = wm * 48 + (lane & 15);
    const int bRow = wn * (BN / 4) + (lane & 7) + ((lane >> 4) << 3);
    const int aChk = (lane >> 4);
    const int bChk = ((lane >> 3) & 1);

    float acc[3][NT][4];
    #pragma unroll
    for (int a = 0; a < 3; ++a)
        #pragma unroll
        for (int b = 0; b < NT; ++b)
            #pragma unroll
            for (int c = 0; c < 4; ++c) acc[a][b][c] = 0.f;

    auto fill = [&](int s) {
        if (s < S) {
            const int k0 = s * 32;
            const uint32_t stb = sb + (s % NSTG) * STGB;
            const bool wantLo = (k0 < 256) || A2LO;
            #pragma unroll
            for (int i = 0; i < ITER; ++i) {
                int g = i * 384 + tid;
                if (g < NCHK) {
                    if (g < 1152) {
                        int mat = (g >= 576);
                        if (mat && !wantLo) continue;      // A2 lo unused
                        int idx = g - mat * 576;
                        int row = idx >> 2, c = idx & 3;
                        uint32_t dst = stb + mat * ABYT + swz(row, c);
                        const f16* a = (k0 < 256) ? (mat ? a1l : a1h)
                                                  : (mat ? a2l : a2h);
                        int gr = ib + row, sz = 16;
                        if (gr >= M) { gr = 0; sz = 0; }
                        CP_ASYNC16(dst, a + (size_t)gr * 256 + (k0 & 255) + c * 8, sz);
                    } else {
                        int idx = g - 1152;
                        int row = idx >> 2, c = idx & 3;
                        uint32_t dst = stb + 2 * ABYT + swz(row, c);
                        CP_ASYNC16(dst, wh + (size_t)(jb + row) * Ktot + k0 + c * 8, 16);
                    }
                }
            }
        }
        CP_COMMIT();
    };

    fill(0); fill(1); fill(2);

    for (int s = 0; s < S; ++s) {
        asm volatile("cp.async.wait_group 2;" ::: "memory");
        __syncthreads();
        fill(s + 3);

        const int k0 = s * 32;
        const bool useLo = (k0 < 256) || A2LO;
        const uint32_t stb = sb + (s % NSTG) * STGB;
        const uint32_t ahB = stb;
        const uint32_t alB = stb + ABYT;
        const uint32_t bhB = stb + 2 * ABYT;

        #pragma unroll
        for (int ks = 0; ks < 2; ++ks) {
            const int aChunk = ks * 2 + aChk;
            const int bChunk = ks * 2 + bChk;

            uint32_t BH[NT][2];
            #pragma unroll
            for (int p = 0; p < NT / 2; ++p) {
                uint32_t bd = bhB + swz(bRow + p * 16, bChunk);
                LDSM_X4(BH[2*p][0], BH[2*p][1], BH[2*p+1][0], BH[2*p+1][1], bd);
            }

            #pragma unroll
            for (int mt = 0; mt < 3; ++mt) {
                uint32_t A0, A1, A2, A3;
                LDSM_X4(A0, A1, A2, A3, ahB + swz(aRow + mt * 16, aChunk));
                #pragma unroll
                for (int nt = 0; nt < NT; ++nt)
                    mma_f16(acc[mt][nt], A0, A1, A2, A3, BH[nt][0], BH[nt][1]);
                if (useLo) {
                    LDSM_X4(A0, A1, A2, A3, alB + swz(aRow + mt * 16, aChunk));
                    #pragma unroll
                    for (int nt = 0; nt < NT; ++nt)
                        mma_f16(acc[mt][nt], A0, A1, A2, A3, BH[nt][0], BH[nt][1]);
                }
            }
        }
    }

    // ---------------- epilogue ----------------
    #pragma unroll
    for (int mt = 0; mt < 3; ++mt) {
        #pragma unroll
        for (int nt = 0; nt < NT; ++nt) {
            int row0 = ib + wm * 48 + mt * 16 + r;
            int col  = jb + wn * (BN / 4) + nt * 8 + 2 * q;
            float2 b2 = make_float2(0.f, 0.f);
            if (FUSE) b2 = *(const float2*)&bias[col];
            #pragma unroll
            for (int hf = 0; hf < 2; ++hf) {
                int row = row0 + 8 * hf;
                if (row >= M) continue;
                float o0 = acc[mt][nt][2 * hf + 0];
                float o1 = acc[mt][nt][2 * hf + 1];
                if (FUSE) {
                    uint32_t uh = *(const uint32_t*)(rh + (size_t)row * Ncols + col);
                    uint32_t ul = *(const uint32_t*)(rl + (size_t)row * Ncols + col);
                    float2 fh = __half22float2(*reinterpret_cast<__half2*>(&uh));
                    float2 fl = __half22float2(*reinterpret_cast<__half2*>(&ul));
                    o0 = (fh.x + fl.x) + fmaxf(o0 + b2.x, 0.f);
                    o1 = (fh.y + fl.y) + fmaxf(o1 + b2.y, 0.f);
                }
                if (OUT32)
                    *(float2*)&C[(size_t)row * Ncols + col] = make_float2(o0, o1);
                if (SPLIT) {
                    uint32_t hi, lo;
                    split2h(o0, o1, hi, lo);
                    *(uint32_t*)(Chi + (size_t)row * Ncols + col) = hi;
                    *(uint32_t*)(Clo + (size_t)row * Ncols + col) = lo;
                }
            }
        }
    }
}

// ---------------- row L2-normalize (128 cols): one warp per row --------------
__global__ void norm_k(float* __restrict__ out) {
    int row = blockIdx.x * 8 + threadIdx.y;  // blockDim (32,8)
    if (row >= NN) return;
    float4* p = (float4*)out + (size_t)row * 32 + threadIdx.x;
    float4 v = *p;
    float s = v.x * v.x + v.y * v.y + v.z * v.z + v.w * v.w;
    #pragma unroll
    for (int off = 16; off > 0; off >>= 1)
        s += __shfl_xor_sync(0xFFFFFFFFu, s, off);
    float r = rsqrtf(s);
    v.x *= r; v.y *= r; v.z *= r; v.w *= r;
    *p = v;
}

// ---------------- launch -----------------------------------------------------
extern "C" void kernel_launch(void* const* d_in, const int* in_sizes, int n_in,
                              void* d_out, int out_size) {
    const float* x     = (const float*)d_in[0];
    const int*   esrc  = (const int*)  d_in[1];
    const int*   edst  = (const int*)  d_in[2];
    const float* ew    = (const float*)d_in[3];
    const float* W_emb = (const float*)d_in[4];
    const float* W_gc1 = (const float*)d_in[5];
    const float* b_gc1 = (const float*)d_in[6];
    const float* W_gc2 = (const float*)d_in[7];
    const float* b_gc2 = (const float*)d_in[8];
    const float* W_fc  = (const float*)d_in[9];
    float* out = (float*)d_out;

    f16 *xh, *xl, *hh, *hl, *h2h, *h2l, *ahh;
    f16 *we, *w1, *w2, *wf;
    cudaGetSymbolAddress((void**)&xh,  g_xh);  cudaGetSymbolAddress((void**)&xl,  g_xl);
    cudaGetSymbolAddress((void**)&hh,  g_hh);  cudaGetSymbolAddress((void**)&hl,  g_hl);
    cudaGetSymbolAddress((void**)&h2h, g_h2h); cudaGetSymbolAddress((void**)&h2l, g_h2l);
    cudaGetSymbolAddress((void**)&ahh, g_ahh);
    cudaGetSymbolAddress((void**)&we,  g_we);
    cudaGetSymbolAddress((void**)&w1,  g_w1);
    cudaGetSymbolAddress((void**)&w2,  g_w2);
    cudaGetSymbolAddress((void**)&wf,  g_wf);

    const int SMEM256 = NSTG * (2 * ABYT + 256 * 64);  // 139264
    const int SMEM128 = NSTG * (2 * ABYT + 128 * 64);  // 106496
    cudaFuncSetAttribute(mma_gemm_k<256, true,  true,  false, false>, cudaFuncAttributeMaxDynamicSharedMemorySize, SMEM256);
    cudaFuncSetAttribute(mma_gemm_k<256, false, true,  false, true >, cudaFuncAttributeMaxDynamicSharedMemorySize, SMEM256);
    cudaFuncSetAttribute(mma_gemm_k<128, false, false, true,  true >, cudaFuncAttributeMaxDynamicSharedMemorySize, SMEM128);

    // side stream + fork/join events: created once, on the (non-capture)
    // correctness call; reused identically on the capture call.
    static cudaStream_t s2 = nullptr;
    static cudaEvent_t evF = nullptr, evJ = nullptr;
    if (!s2) {
        cudaStreamCreateWithFlags(&s2, cudaStreamNonBlocking);
        cudaEventCreateWithFlags(&evF, cudaEventDisableTiming);
        cudaEventCreateWithFlags(&evJ, cudaEventDisableTiming);
    }

    const int MT = (NN + BM - 1) / BM;  // 139 -> one wave at 1 CTA/SM
    dim3 gHid(MT, 1);
    dim3 gOut(MT, 1);
    dim3 gblk(5000), gthr(64, 4);

    const int NW = HIDF * INF + 2 * (HIDF * 2 * HIDF) + OUTF * HIDF;

    // fork: CSR build on s2, split/wcvt/emb-GEMM on main stream (overlap)
    cudaEventRecord(evF, 0);
    cudaStreamWaitEvent(s2, evF, 0);

    split_k<<<(NN * INF / 4 + 255) / 256, 256>>>(x, xh, xl, NN * INF);                 // 0 main
    wcvt_k<<<(NW / 4 + 255) / 256, 256>>>(                                             // 1 main
        W_emb, we, HIDF * INF,
        W_gc1, w1, HIDF * 2 * HIDF,
        W_gc2, w2, HIDF * 2 * HIDF,
        W_fc,  wf, OUTF * HIDF);
    zero_cnt_k<<<(NN + 255) / 256, 256, 0, s2>>>();                                    // 2 s2
    mma_gemm_k<256, false, true, false, true><<<gHid, 384, SMEM256>>>(                 // 3 main (ncu)
        xh, xl, nullptr, nullptr, INF, we,
        nullptr, nullptr, nullptr, nullptr, hh, hl, NN, HIDF);
    count_k  <<<(EE + 255) / 256, 256, 0, s2>>>(edst);                                 // 4 s2
    scan_k   <<<1, 1024, 0, s2>>>();                                                   // 5 s2
    scatter_k<<<(EE + 255) / 256, 256, 0, s2>>>(esrc, edst, ew);                       // 6 s2

    // join: gather needs both hh (main) and CSR (s2)
    cudaEventRecord(evJ, s2);
    cudaStreamWaitEvent(0, evJ, 0);

    // Ah = A @ h ; h2 = h + relu([h|Ah] @ W_gc1^T + b1)
    gather_k<<<gblk, gthr>>>(hh, ahh);                                                 // 7
    mma_gemm_k<256, true, true, false, false><<<gHid, 384, SMEM256>>>(                 // 8
        hh, hl, ahh, nullptr, 2 * HIDF, w1,
        b_gc1, hh, hl, nullptr, h2h, h2l, NN, HIDF);
    // Ah = A @ h2 ; h = h2 + relu([h2|Ah] @ W_gc2^T + b2)
    gather_k<<<gblk, gthr>>>(h2h, ahh);                                                // 9
    mma_gemm_k<256, true, true, false, false><<<gHid, 384, SMEM256>>>(                 // 10
        h2h, h2l, ahh, nullptr, 2 * HIDF, w2,
        b_gc2, h2h, h2l, nullptr, hh, hl, NN, HIDF);
    // out = h @ W_fc^T ; rows L2-normalized
    mma_gemm_k<128, false, false, true, true><<<gOut, 384, SMEM128>>>(                 // 11
        hh, hl, nullptr, nullptr, HIDF, wf,
        nullptr, nullptr, nullptr, out, nullptr, nullptr, NN, OUTF);
    norm_k<<<(NN + 7) / 8, dim3(32, 8)>>>(out);                                        // 12
}